// round 1
// baseline (speedup 1.0000x reference)
#include <cuda_runtime.h>
#include <math.h>

#define TPB        256
#define TILE_M     128
#define HDIM       128
#define PAD        132   // row stride (floats) for transposed activation/weight buffers
#define NJ         7

// SMEM layout (floats):
//   bufA[128*132] , bufB[128*132] : activations transposed h[k][m] (double-buffered)
//   WTs [128*132]                 : current layer weights transposed W[k][o]
//                                   (also reused as WTf[k*16+o] for the final layer)
//   Tcum[128*17]                  : cumulative 4x4 transform per sample (pad 17)
//   ybuf[128*21]                  : staged y output [m][i*7+j]
//   bias_s[128]
#define SMEM_FLOATS (3*128*132 + 128*17 + 128*21 + 128)

__device__ __forceinline__ void gemm_layer(const float* __restrict__ hA,
                                           const float* __restrict__ WT,
                                           const float* __restrict__ bias_s,
                                           float* __restrict__ hB,
                                           int K, int tx, int ty)
{
    // C[m][o] = relu( sum_k hA[k][m] * WT[k][o] + bias[o] ), stored transposed: hB[o][m]
    float acc[8][8];   // [jj over o][ii over m]
    #pragma unroll
    for (int jj = 0; jj < 8; ++jj) {
        float b = bias_s[ty*8 + jj];
        #pragma unroll
        for (int ii = 0; ii < 8; ++ii) acc[jj][ii] = b;
    }

    for (int k = 0; k < K; ++k) {
        const float4 a0 = *(const float4*)&hA[k*PAD + tx*8];
        const float4 a1 = *(const float4*)&hA[k*PAD + tx*8 + 4];
        const float4 b0 = *(const float4*)&WT[k*PAD + ty*8];
        const float4 b1 = *(const float4*)&WT[k*PAD + ty*8 + 4];
        float a[8] = {a0.x,a0.y,a0.z,a0.w,a1.x,a1.y,a1.z,a1.w};
        float b[8] = {b0.x,b0.y,b0.z,b0.w,b1.x,b1.y,b1.z,b1.w};
        #pragma unroll
        for (int jj = 0; jj < 8; ++jj)
            #pragma unroll
            for (int ii = 0; ii < 8; ++ii)
                acc[jj][ii] = fmaf(a[ii], b[jj], acc[jj][ii]);
    }

    #pragma unroll
    for (int jj = 0; jj < 8; ++jj) {
        int o = ty*8 + jj;
        float4 v0, v1;
        v0.x = fmaxf(acc[jj][0], 0.f); v0.y = fmaxf(acc[jj][1], 0.f);
        v0.z = fmaxf(acc[jj][2], 0.f); v0.w = fmaxf(acc[jj][3], 0.f);
        v1.x = fmaxf(acc[jj][4], 0.f); v1.y = fmaxf(acc[jj][5], 0.f);
        v1.z = fmaxf(acc[jj][6], 0.f); v1.w = fmaxf(acc[jj][7], 0.f);
        *(float4*)&hB[o*PAD + tx*8]     = v0;
        *(float4*)&hB[o*PAD + tx*8 + 4] = v1;
    }
}

__global__ void __launch_bounds__(TPB, 1)
fkine_kernel(const float* __restrict__ q,
             const float* __restrict__ W0,
             const float* __restrict__ b0,
             const float* __restrict__ Wh,
             const float* __restrict__ bh,
             const float* __restrict__ Wf,
             const float* __restrict__ bf,
             float* __restrict__ out_y,
             float* __restrict__ out_t)
{
    extern __shared__ float smem[];
    float* bufA   = smem;
    float* bufB   = bufA + 128*PAD;
    float* WTs    = bufB + 128*PAD;
    float* Tcum   = WTs  + 128*PAD;   // stride 17
    float* ybuf   = Tcum + 128*17;    // stride 21
    float* bias_s = ybuf + 128*21;

    const int tid = threadIdx.x;
    const int tx  = tid & 15;
    const int ty  = tid >> 4;
    const int g0  = blockIdx.x * TILE_M;

    // init cumulative transforms to identity
    for (int idx = tid; idx < 128*16; idx += TPB) {
        int m = idx >> 4, e = idx & 15;
        Tcum[m*17 + e] = ((e >> 2) == (e & 3)) ? 1.f : 0.f;
    }

    float* hA = bufA;
    float* hB = bufB;

    for (int j = 0; j < NJ; ++j) {
        __syncthreads();   // protect hA rows 0..2, WTs, hB from prior-iter readers

        // ---- features: qf = [theta, cos, sin], stored as layer-0 activations hA[k][m]
        if (tid < TILE_M) {
            float th = q[(size_t)(g0 + tid)*NJ + j];
            hA[0*PAD + tid] = th;
            hA[1*PAD + tid] = cosf(th);
            hA[2*PAD + tid] = sinf(th);
        }
        // ---- W0[j] (H x 3, [out][in]) -> WTs[k][o]
        {
            const float* w0 = W0 + (size_t)j*HDIM*3;
            for (int idx = tid; idx < HDIM*3; idx += TPB) {
                int o = idx / 3, k = idx - o*3;
                WTs[k*PAD + o] = w0[idx];
            }
            if (tid < HDIM) bias_s[tid] = b0[j*HDIM + tid];
        }
        __syncthreads();
        gemm_layer(hA, WTs, bias_s, hB, 3, tx, ty);
        __syncthreads();
        { float* t = hA; hA = hB; hB = t; }

        // ---- two hidden layers 128 -> 128
        for (int l = 0; l < 2; ++l) {
            const float* wh = Wh + (size_t)(j*2 + l)*HDIM*HDIM;
            for (int idx = tid; idx < HDIM*HDIM; idx += TPB) {
                int o = idx >> 7, k = idx & 127;
                WTs[k*PAD + o] = wh[idx];
            }
            if (tid < HDIM) bias_s[tid] = bh[(j*2 + l)*HDIM + tid];
            __syncthreads();
            gemm_layer(hA, WTs, bias_s, hB, HDIM, tx, ty);
            __syncthreads();
            { float* t = hA; hA = hB; hB = t; }
        }

        // ---- final layer 128 -> 12 (no relu); WTs reused as WTf[k*16 + o]
        {
            const float* wf = Wf + (size_t)j*12*HDIM;
            for (int idx = tid; idx < 12*HDIM; idx += TPB) {
                int o = idx >> 7, k = idx & 127;
                WTs[k*16 + o] = wf[idx];
            }
        }
        __syncthreads();
        {
            int m  = tid & 127;
            int ob = (tid >> 7) * 6;    // half 0 -> outputs 0..5, half 1 -> 6..11
            float acc[6];
            #pragma unroll
            for (int i = 0; i < 6; ++i) acc[i] = bf[j*12 + ob + i];
            for (int k = 0; k < HDIM; ++k) {
                float a = hA[k*PAD + m];
                #pragma unroll
                for (int i = 0; i < 6; ++i)
                    acc[i] = fmaf(a, WTs[k*16 + ob + i], acc[i]);
            }
            #pragma unroll
            for (int i = 0; i < 6; ++i) hB[m*16 + ob + i] = acc[i];  // hB = scratch top buffer
        }
        __syncthreads();

        // ---- chain epilogue: T_new = T_local @ T_prev
        if (tid < TILE_M) {
            int m = tid;
            float Tl[12], Tp[16], Tn[16];
            #pragma unroll
            for (int i = 0; i < 12; ++i) Tl[i] = hB[m*16 + i];
            #pragma unroll
            for (int i = 0; i < 16; ++i) Tp[i] = Tcum[m*17 + i];
            #pragma unroll
            for (int i = 0; i < 3; ++i)
                #pragma unroll
                for (int c = 0; c < 4; ++c)
                    Tn[i*4+c] = Tl[i*4+0]*Tp[0+c] + Tl[i*4+1]*Tp[4+c]
                              + Tl[i*4+2]*Tp[8+c] + Tl[i*4+3]*Tp[12+c];
            #pragma unroll
            for (int c = 0; c < 4; ++c) Tn[12+c] = Tp[12+c];  // bottom row of Tl is (0,0,0,1)

            // t output: local transform incl. bottom row, [N][7][4][4]
            float4* tp = (float4*)(out_t + (size_t)(g0 + m)*112 + j*16);
            tp[0] = make_float4(Tl[0], Tl[1], Tl[2],  Tl[3]);
            tp[1] = make_float4(Tl[4], Tl[5], Tl[6],  Tl[7]);
            tp[2] = make_float4(Tl[8], Tl[9], Tl[10], Tl[11]);
            tp[3] = make_float4(0.f, 0.f, 0.f, 1.f);

            // y = T_new[:3, 3], layout [N][3][7]
            ybuf[m*21 +      j] = Tn[3];
            ybuf[m*21 +  7 + j] = Tn[7];
            ybuf[m*21 + 14 + j] = Tn[11];

            #pragma unroll
            for (int i = 0; i < 16; ++i) Tcum[m*17 + i] = Tn[i];
        }
    }

    __syncthreads();
    // coalesced y write: this CTA owns contiguous slice [g0*21, (g0+128)*21)
    for (int idx = tid; idx < TILE_M*21; idx += TPB)
        out_y[(size_t)g0*21 + idx] = ybuf[idx];
}

extern "C" void kernel_launch(void* const* d_in, const int* in_sizes, int n_in,
                              void* d_out, int out_size)
{
    const float* q  = (const float*)d_in[0];
    const float* W0 = (const float*)d_in[1];
    const float* b0 = (const float*)d_in[2];
    const float* Wh = (const float*)d_in[3];
    const float* bh = (const float*)d_in[4];
    const float* Wf = (const float*)d_in[5];
    const float* bf = (const float*)d_in[6];

    const int N = in_sizes[0] / NJ;           // q is [N, 7]
    float* out_y = (float*)d_out;             // [N, 3, 7]
    float* out_t = out_y + (size_t)N*21;      // [N, 7, 4, 4]

    const size_t smem_bytes = SMEM_FLOATS * sizeof(float);
    cudaFuncSetAttribute(fkine_kernel,
                         cudaFuncAttributeMaxDynamicSharedMemorySize,
                         (int)smem_bytes);

    fkine_kernel<<<N / TILE_M, TPB, smem_bytes>>>(q, W0, b0, Wh, bh, Wf, bf,
                                                  out_y, out_t);
}

// round 2
// speedup vs baseline: 1.0165x; 1.0165x over previous
#include <cuda_runtime.h>
#include <math.h>

#define TPB        256
#define TILE_M     128
#define HDIM       128
#define PAD        132   // row stride (floats) for transposed activation/weight buffers
#define NJ         7

// SMEM layout (floats):
//   bufA[128*132] , bufB[128*132] : activations transposed h[k][m] (double-buffered)
//   WTs [128*132]                 : current layer weights transposed W[k][o]
//   Tcum[128*17], ybuf[128*21], bias_s[128]
#define SMEM_FLOATS (3*128*132 + 128*17 + 128*21 + 128)

typedef unsigned long long u64;

__device__ __forceinline__ u64 pack_dup(float x) {
    u64 r;
    asm("mov.b64 %0, {%1, %1};" : "=l"(r) : "f"(x));
    return r;
}
__device__ __forceinline__ u64 pack2(float lo, float hi) {
    u64 r;
    asm("mov.b64 %0, {%1, %2};" : "=l"(r) : "f"(lo), "f"(hi));
    return r;
}
__device__ __forceinline__ u64 fma2(u64 a, u64 b, u64 c) {
    u64 d;
    asm("fma.rn.f32x2 %0, %1, %2, %3;" : "=l"(d) : "l"(a), "l"(b), "l"(c));
    return d;
}
__device__ __forceinline__ float2 unpack2(u64 v) {
    float2 f;
    asm("mov.b64 {%0, %1}, %2;" : "=f"(f.x), "=f"(f.y) : "l"(v));
    return f;
}

__device__ __forceinline__ void gemm_layer(const float* __restrict__ hA,
                                           const float* __restrict__ WT,
                                           const float* __restrict__ bias_s,
                                           float* __restrict__ hB,
                                           int K, int tx, int ty)
{
    // C[m][o] = relu( sum_k hA[k][m] * WT[k][o] + bias[o] ), stored transposed hB[o][m].
    // Packed f32x2: accumulator pairs along m (contiguous in the transposed layout).
    u64 acc[8][4];   // [jj over o][pair over m]
    #pragma unroll
    for (int jj = 0; jj < 8; ++jj) {
        u64 b = pack_dup(bias_s[ty*8 + jj]);
        #pragma unroll
        for (int p = 0; p < 4; ++p) acc[jj][p] = b;
    }

    for (int k = 0; k < K; ++k) {
        const ulonglong2* ap = (const ulonglong2*)&hA[k*PAD + tx*8];
        ulonglong2 A0 = ap[0];
        ulonglong2 A1 = ap[1];
        u64 a[4] = {A0.x, A0.y, A1.x, A1.y};

        const float4 b0 = *(const float4*)&WT[k*PAD + ty*8];
        const float4 b1 = *(const float4*)&WT[k*PAD + ty*8 + 4];
        u64 bb[8];
        bb[0] = pack_dup(b0.x); bb[1] = pack_dup(b0.y);
        bb[2] = pack_dup(b0.z); bb[3] = pack_dup(b0.w);
        bb[4] = pack_dup(b1.x); bb[5] = pack_dup(b1.y);
        bb[6] = pack_dup(b1.z); bb[7] = pack_dup(b1.w);

        #pragma unroll
        for (int jj = 0; jj < 8; ++jj)
            #pragma unroll
            for (int p = 0; p < 4; ++p)
                acc[jj][p] = fma2(a[p], bb[jj], acc[jj][p]);
    }

    #pragma unroll
    for (int jj = 0; jj < 8; ++jj) {
        int o = ty*8 + jj;
        float2 v0 = unpack2(acc[jj][0]);
        float2 v1 = unpack2(acc[jj][1]);
        float2 v2 = unpack2(acc[jj][2]);
        float2 v3 = unpack2(acc[jj][3]);
        float4 w0, w1;
        w0.x = fmaxf(v0.x, 0.f); w0.y = fmaxf(v0.y, 0.f);
        w0.z = fmaxf(v1.x, 0.f); w0.w = fmaxf(v1.y, 0.f);
        w1.x = fmaxf(v2.x, 0.f); w1.y = fmaxf(v2.y, 0.f);
        w1.z = fmaxf(v3.x, 0.f); w1.w = fmaxf(v3.y, 0.f);
        *(float4*)&hB[o*PAD + tx*8]     = w0;
        *(float4*)&hB[o*PAD + tx*8 + 4] = w1;
    }
}

__global__ void __launch_bounds__(TPB, 1)
fkine_kernel(const float* __restrict__ q,
             const float* __restrict__ W0,
             const float* __restrict__ b0,
             const float* __restrict__ Wh,
             const float* __restrict__ bh,
             const float* __restrict__ Wf,
             const float* __restrict__ bf,
             float* __restrict__ out_y,
             float* __restrict__ out_t)
{
    extern __shared__ float smem[];
    float* bufA   = smem;
    float* bufB   = bufA + 128*PAD;
    float* WTs    = bufB + 128*PAD;
    float* Tcum   = WTs  + 128*PAD;   // stride 17
    float* ybuf   = Tcum + 128*17;    // stride 21
    float* bias_s = ybuf + 128*21;

    const int tid = threadIdx.x;
    const int tx  = tid & 15;
    const int ty  = tid >> 4;
    const int g0  = blockIdx.x * TILE_M;

    // init cumulative transforms to identity
    for (int idx = tid; idx < 128*16; idx += TPB) {
        int m = idx >> 4, e = idx & 15;
        Tcum[m*17 + e] = ((e >> 2) == (e & 3)) ? 1.f : 0.f;
    }

    float* hA = bufA;
    float* hB = bufB;

    for (int j = 0; j < NJ; ++j) {
        __syncthreads();   // protect hA rows 0..2, WTs, hB from prior-iter readers

        // ---- features: qf = [theta, cos, sin] as layer-0 activations hA[k][m]
        if (tid < TILE_M) {
            float th = q[(size_t)(g0 + tid)*NJ + j];
            hA[0*PAD + tid] = th;
            hA[1*PAD + tid] = cosf(th);
            hA[2*PAD + tid] = sinf(th);
        }
        // ---- W0[j] (H x 3, [out][in]) -> WTs[k][o]
        {
            const float* w0 = W0 + (size_t)j*HDIM*3;
            for (int idx = tid; idx < HDIM*3; idx += TPB) {
                int o = idx / 3, k = idx - o*3;
                WTs[k*PAD + o] = w0[idx];
            }
            if (tid < HDIM) bias_s[tid] = b0[j*HDIM + tid];
        }
        __syncthreads();
        gemm_layer(hA, WTs, bias_s, hB, 3, tx, ty);
        __syncthreads();
        { float* t = hA; hA = hB; hB = t; }

        // ---- two hidden layers 128 -> 128
        for (int l = 0; l < 2; ++l) {
            const float* wh = Wh + (size_t)(j*2 + l)*HDIM*HDIM;
            for (int idx = tid; idx < HDIM*HDIM; idx += TPB) {
                int o = idx >> 7, k = idx & 127;
                WTs[k*PAD + o] = wh[idx];
            }
            if (tid < HDIM) bias_s[tid] = bh[(j*2 + l)*HDIM + tid];
            __syncthreads();
            gemm_layer(hA, WTs, bias_s, hB, HDIM, tx, ty);
            __syncthreads();
            { float* t = hA; hA = hB; hB = t; }
        }

        // ---- final layer 128 -> 12 (no relu); WTs reused as WTf[k*16 + o]
        {
            const float* wf = Wf + (size_t)j*12*HDIM;
            for (int idx = tid; idx < 12*HDIM; idx += TPB) {
                int o = idx >> 7, k = idx & 127;
                WTs[k*16 + o] = wf[idx];
            }
        }
        __syncthreads();
        {
            int m  = tid & 127;
            int ob = (tid >> 7) * 6;    // half 0 -> outputs 0..5, half 1 -> 6..11
            u64 acc2[3];
            #pragma unroll
            for (int i = 0; i < 3; ++i)
                acc2[i] = pack2(bf[j*12 + ob + 2*i], bf[j*12 + ob + 2*i + 1]);
            for (int k = 0; k < HDIM; ++k) {
                u64 ad = pack_dup(hA[k*PAD + m]);
                const u64* wp = (const u64*)&WTs[k*16 + ob];   // 8B-aligned (ob in {0,6})
                #pragma unroll
                for (int i = 0; i < 3; ++i)
                    acc2[i] = fma2(ad, wp[i], acc2[i]);
            }
            #pragma unroll
            for (int i = 0; i < 3; ++i) {
                float2 v = unpack2(acc2[i]);
                hB[m*16 + ob + 2*i]     = v.x;
                hB[m*16 + ob + 2*i + 1] = v.y;
            }
        }
        __syncthreads();

        // ---- chain epilogue: T_new = T_local @ T_prev
        if (tid < TILE_M) {
            int m = tid;
            float Tl[12], Tp[16], Tn[16];
            #pragma unroll
            for (int i = 0; i < 12; ++i) Tl[i] = hB[m*16 + i];
            #pragma unroll
            for (int i = 0; i < 16; ++i) Tp[i] = Tcum[m*17 + i];
            #pragma unroll
            for (int i = 0; i < 3; ++i)
                #pragma unroll
                for (int c = 0; c < 4; ++c)
                    Tn[i*4+c] = Tl[i*4+0]*Tp[0+c] + Tl[i*4+1]*Tp[4+c]
                              + Tl[i*4+2]*Tp[8+c] + Tl[i*4+3]*Tp[12+c];
            #pragma unroll
            for (int c = 0; c < 4; ++c) Tn[12+c] = Tp[12+c];

            float4* tp = (float4*)(out_t + (size_t)(g0 + m)*112 + j*16);
            tp[0] = make_float4(Tl[0], Tl[1], Tl[2],  Tl[3]);
            tp[1] = make_float4(Tl[4], Tl[5], Tl[6],  Tl[7]);
            tp[2] = make_float4(Tl[8], Tl[9], Tl[10], Tl[11]);
            tp[3] = make_float4(0.f, 0.f, 0.f, 1.f);

            ybuf[m*21 +      j] = Tn[3];
            ybuf[m*21 +  7 + j] = Tn[7];
            ybuf[m*21 + 14 + j] = Tn[11];

            #pragma unroll
            for (int i = 0; i < 16; ++i) Tcum[m*17 + i] = Tn[i];
        }
    }

    __syncthreads();
    for (int idx = tid; idx < TILE_M*21; idx += TPB)
        out_y[(size_t)g0*21 + idx] = ybuf[idx];
}

extern "C" void kernel_launch(void* const* d_in, const int* in_sizes, int n_in,
                              void* d_out, int out_size)
{
    const float* q  = (const float*)d_in[0];
    const float* W0 = (const float*)d_in[1];
    const float* b0 = (const float*)d_in[2];
    const float* Wh = (const float*)d_in[3];
    const float* bh = (const float*)d_in[4];
    const float* Wf = (const float*)d_in[5];
    const float* bf = (const float*)d_in[6];

    const int N = in_sizes[0] / NJ;           // q is [N, 7]
    float* out_y = (float*)d_out;             // [N, 3, 7]
    float* out_t = out_y + (size_t)N*21;      // [N, 7, 4, 4]

    const size_t smem_bytes = SMEM_FLOATS * sizeof(float);
    cudaFuncSetAttribute(fkine_kernel,
                         cudaFuncAttributeMaxDynamicSharedMemorySize,
                         (int)smem_bytes);

    fkine_kernel<<<N / TILE_M, TPB, smem_bytes>>>(q, W0, b0, Wh, bh, Wf, bf,
                                                  out_y, out_t);
}

// round 4
// speedup vs baseline: 2.0338x; 2.0008x over previous
#include <cuda_runtime.h>
#include <cstdint>
#include <math.h>

typedef uint32_t u32;

#define TPB    256
#define NJ     7
#define RSB    272          // bytes per bf16 tile row (136 bf16, conflict-free ldmatrix)

// ---- smem byte offsets ----
#define SM_A_HI   0
#define SM_A_LO   34816          // 128*272
#define SM_W_HI   69632
#define SM_W_LO   104448
#define SM_BIAS   139264         // 128 f32
#define SM_TOP    139776         // 128 x 18 f32
#define SM_TCUM   148992         // 128 x 17 f32
#define SM_YBUF   157696         // 128 x 21 f32
#define SM_TOTAL  168448

static __device__ __forceinline__ u32 smem_u32(const void* p) {
    u32 a;
    asm("{ .reg .u64 t; cvta.to.shared.u64 t, %1; cvt.u32.u64 %0, t; }" : "=r"(a) : "l"(p));
    return a;
}
// pack two floats -> bf16x2 (lo half = x0, hi half = x1)
static __device__ __forceinline__ u32 packbf(float x0, float x1) {
    u32 r;
    asm("cvt.rn.bf16x2.f32 %0, %1, %2;" : "=r"(r) : "f"(x1), "f"(x0));
    return r;
}
static __device__ __forceinline__ uint4 ldmx4(u32 addr) {
    uint4 r;
    asm volatile("ldmatrix.sync.aligned.m8n8.x4.shared.b16 {%0,%1,%2,%3}, [%4];"
                 : "=r"(r.x), "=r"(r.y), "=r"(r.z), "=r"(r.w) : "r"(addr));
    return r;
}
static __device__ __forceinline__ void mma_bf(float d[4], const uint4& a, u32 b0, u32 b1) {
    asm volatile("mma.sync.aligned.m16n8k16.row.col.f32.bf16.bf16.f32 "
                 "{%0,%1,%2,%3},{%4,%5,%6,%7},{%8,%9},{%0,%1,%2,%3};"
                 : "+f"(d[0]), "+f"(d[1]), "+f"(d[2]), "+f"(d[3])
                 : "r"(a.x), "r"(a.y), "r"(a.z), "r"(a.w), "r"(b0), "r"(b1));
}
// split pair of f32 into hi/lo bf16x2 words
static __device__ __forceinline__ void split2(float v0, float v1, u32& hi, u32& lo) {
    hi = packbf(v0, v1);
    float r0 = v0 - __uint_as_float(hi << 16);
    float r1 = v1 - __uint_as_float(hi & 0xffff0000u);
    lo = packbf(r0, r1);
}

// 256-thread loader: W fp32 [128][128] -> W_HI/W_LO bf16 tiles
static __device__ __forceinline__ void load_W(const float* __restrict__ W, char* sm, int tid) {
    const float4* Wv = (const float4*)W;
    #pragma unroll 4
    for (int i = 0; i < 16; ++i) {
        int g = tid + (i << 8);
        float4 w = Wv[g];
        int n = g >> 5, k0 = (g & 31) << 2;
        u32 h0, l0, h1, l1;
        split2(w.x, w.y, h0, l0);
        split2(w.z, w.w, h1, l1);
        u32 off = n * RSB + (k0 << 1);
        *(uint2*)(sm + SM_W_HI + off) = make_uint2(h0, h1);
        *(uint2*)(sm + SM_W_LO + off) = make_uint2(l0, l1);
    }
}

// 256-thread loader: Wf fp32 [12][128] -> rows 0..11 of W tiles, rows 12..15 zero
static __device__ __forceinline__ void load_Wf(const float* __restrict__ Wf, char* sm, int tid) {
    const float4* Wv = (const float4*)Wf;
    for (int g = tid; g < 384; g += TPB) {
        float4 w = Wv[g];
        int n = g >> 5, k0 = (g & 31) << 2;
        u32 h0, l0, h1, l1;
        split2(w.x, w.y, h0, l0);
        split2(w.z, w.w, h1, l1);
        u32 off = n * RSB + (k0 << 1);
        *(uint2*)(sm + SM_W_HI + off) = make_uint2(h0, h1);
        *(uint2*)(sm + SM_W_LO + off) = make_uint2(l0, l1);
    }
    for (int idx = tid; idx < 272; idx += TPB) {      // 4 rows x 68 u32
        int row = 12 + idx / 68, c = idx % 68;
        u32 off = row * RSB + c * 4;
        *(u32*)(sm + SM_W_HI + off) = 0;
        *(u32*)(sm + SM_W_LO + off) = 0;
    }
}

// hidden layer: D = relu(A @ W^T + bias); warps 4m x 2n; writes new A hi/lo
static __device__ void mma_hidden(u32 smb, char* sm, const float* bias_s, int lane, int wid) {
    const int m_base = (wid >> 1) * 32;
    const int n_base = (wid & 1) * 64;
    float acc[2][8][4];
    #pragma unroll
    for (int nt = 0; nt < 8; ++nt) {
        int c = n_base + nt * 8 + 2 * (lane & 3);
        float b0 = bias_s[c], b1 = bias_s[c + 1];
        #pragma unroll
        for (int mt = 0; mt < 2; ++mt) {
            acc[mt][nt][0] = b0; acc[mt][nt][1] = b1;
            acc[mt][nt][2] = b0; acc[mt][nt][3] = b1;
        }
    }
    const int arow = lane & 15, acol = (lane >> 4) << 3;
    const int brow = (lane & 7) + ((lane & 16) >> 1);
    const int bcol = lane & 8;

    #pragma unroll
    for (int k = 0; k < 8; ++k) {
        int k0 = k * 16;
        uint4 ahi[2], alo[2];
        #pragma unroll
        for (int mt = 0; mt < 2; ++mt) {
            u32 a = smb + SM_A_HI + (u32)(m_base + mt * 16 + arow) * RSB + (u32)(k0 + acol) * 2;
            ahi[mt] = ldmx4(a);
            alo[mt] = ldmx4(a + (SM_A_LO - SM_A_HI));
        }
        #pragma unroll
        for (int np = 0; np < 4; ++np) {
            int n0 = n_base + np * 16;
            u32 b = smb + SM_W_HI + (u32)(n0 + brow) * RSB + (u32)(k0 + bcol) * 2;
            uint4 bh = ldmx4(b);
            uint4 bl = ldmx4(b + (SM_W_LO - SM_W_HI));
            #pragma unroll
            for (int mt = 0; mt < 2; ++mt) {
                mma_bf(acc[mt][np*2+0], ahi[mt], bh.x, bh.y);
                mma_bf(acc[mt][np*2+0], ahi[mt], bl.x, bl.y);
                mma_bf(acc[mt][np*2+0], alo[mt], bh.x, bh.y);
                mma_bf(acc[mt][np*2+1], ahi[mt], bh.z, bh.w);
                mma_bf(acc[mt][np*2+1], ahi[mt], bl.z, bl.w);
                mma_bf(acc[mt][np*2+1], alo[mt], bh.z, bh.w);
            }
        }
    }
    __syncthreads();   // all warps finished reading A before overwrite
    #pragma unroll
    for (int mt = 0; mt < 2; ++mt) {
        #pragma unroll
        for (int nt = 0; nt < 8; ++nt) {
            int r = m_base + mt * 16 + (lane >> 2);
            int c = n_base + nt * 8 + 2 * (lane & 3);
            u32 hi, lo;
            float v0 = fmaxf(acc[mt][nt][0], 0.f), v1 = fmaxf(acc[mt][nt][1], 0.f);
            split2(v0, v1, hi, lo);
            *(u32*)(sm + SM_A_HI + r * RSB + c * 2) = hi;
            *(u32*)(sm + SM_A_LO + r * RSB + c * 2) = lo;
            float v2 = fmaxf(acc[mt][nt][2], 0.f), v3 = fmaxf(acc[mt][nt][3], 0.f);
            split2(v2, v3, hi, lo);
            *(u32*)(sm + SM_A_HI + (r + 8) * RSB + c * 2) = hi;
            *(u32*)(sm + SM_A_LO + (r + 8) * RSB + c * 2) = lo;
        }
    }
}

// final layer: D[128][16] = A @ Wf^T  (bias added later); each warp m16 stripe
static __device__ void mma_final(u32 smb, char* sm, int lane, int wid) {
    const int m_base = wid * 16;
    float acc[2][4] = {};
    const int arow = lane & 15, acol = (lane >> 4) << 3;
    const int brow = (lane & 7) + ((lane & 16) >> 1);
    const int bcol = lane & 8;
    #pragma unroll
    for (int k = 0; k < 8; ++k) {
        int k0 = k * 16;
        u32 a = smb + SM_A_HI + (u32)(m_base + arow) * RSB + (u32)(k0 + acol) * 2;
        uint4 ahi = ldmx4(a);
        uint4 alo = ldmx4(a + (SM_A_LO - SM_A_HI));
        u32 b = smb + SM_W_HI + (u32)brow * RSB + (u32)(k0 + bcol) * 2;
        uint4 bh = ldmx4(b);
        uint4 bl = ldmx4(b + (SM_W_LO - SM_W_HI));
        mma_bf(acc[0], ahi, bh.x, bh.y);
        mma_bf(acc[0], ahi, bl.x, bl.y);
        mma_bf(acc[0], alo, bh.x, bh.y);
        mma_bf(acc[1], ahi, bh.z, bh.w);
        mma_bf(acc[1], ahi, bl.z, bl.w);
        mma_bf(acc[1], alo, bh.z, bh.w);
    }
    float* topb = (float*)(sm + SM_TOP);
    #pragma unroll
    for (int nt = 0; nt < 2; ++nt) {
        int r = m_base + (lane >> 2);
        int c = nt * 8 + 2 * (lane & 3);
        *(float2*)&topb[r * 18 + c]       = make_float2(acc[nt][0], acc[nt][1]);
        *(float2*)&topb[(r + 8) * 18 + c] = make_float2(acc[nt][2], acc[nt][3]);
    }
}

__global__ void __launch_bounds__(TPB, 1)
fkine_mma_kernel(const float* __restrict__ q,
                 const float* __restrict__ W0,
                 const float* __restrict__ b0,
                 const float* __restrict__ Wh,
                 const float* __restrict__ bh,
                 const float* __restrict__ Wf,
                 const float* __restrict__ bf,
                 float* __restrict__ out_y,
                 float* __restrict__ out_t)
{
    extern __shared__ char sm[];
    const u32 smb = smem_u32(sm);
    const int tid = threadIdx.x, lane = tid & 31, wid = tid >> 5;
    const int g0 = blockIdx.x * 128;
    float* bias_s = (float*)(sm + SM_BIAS);
    float* topb   = (float*)(sm + SM_TOP);
    float* Tcum   = (float*)(sm + SM_TCUM);
    float* ybuf   = (float*)(sm + SM_YBUF);

    for (int idx = tid; idx < 128 * 16; idx += TPB) {
        int m = idx >> 4, e = idx & 15;
        Tcum[m * 17 + e] = ((e >> 2) == (e & 3)) ? 1.f : 0.f;
    }
    load_W(Wh, sm, tid);
    if (tid < 128) bias_s[tid] = bh[tid];
    __syncthreads();

    for (int j = 0; j < NJ; ++j) {
        // ---- layer 0 (K=3, scalar fp32) -> A hi/lo
        {
            int m = tid >> 1, hb = (tid & 1) * 64;
            float th = q[(size_t)(g0 + m) * NJ + j];
            float ct = cosf(th), st = sinf(th);
            const float* w0  = W0 + (size_t)j * 384;
            const float* b0j = b0 + (size_t)j * 128;
            for (int o = hb; o < hb + 64; o += 2) {
                float h0 = fmaxf(fmaf(w0[o*3+0], th, fmaf(w0[o*3+1], ct, fmaf(w0[o*3+2], st, b0j[o]))),   0.f);
                float h1 = fmaxf(fmaf(w0[o*3+3], th, fmaf(w0[o*3+4], ct, fmaf(w0[o*3+5], st, b0j[o+1]))), 0.f);
                u32 hi, lo;
                split2(h0, h1, hi, lo);
                *(u32*)(sm + SM_A_HI + m * RSB + o * 2) = hi;
                *(u32*)(sm + SM_A_LO + m * RSB + o * 2) = lo;
            }
        }
        __syncthreads();

        // ---- hidden layer 1
        mma_hidden(smb, sm, bias_s, lane, wid);
        load_W(Wh + ((size_t)j * 2 + 1) * 16384, sm, tid);
        if (tid < 128) bias_s[tid] = bh[(j * 2 + 1) * 128 + tid];
        __syncthreads();

        // ---- hidden layer 2
        mma_hidden(smb, sm, bias_s, lane, wid);
        load_Wf(Wf + (size_t)j * 1536, sm, tid);
        __syncthreads();

        // ---- final layer -> topb
        mma_final(smb, sm, lane, wid);
        __syncthreads();

        // prefetch next joint's first hidden weights
        if (j < NJ - 1) {
            load_W(Wh + (size_t)(j + 1) * 2 * 16384, sm, tid);
            if (tid < 128) bias_s[tid] = bh[(j + 1) * 2 * 128 + tid];
        }

        // ---- chain epilogue
        if (tid < 128) {
            int m = tid;
            float Tl[12], Tp[16], Tn[16];
            #pragma unroll
            for (int i = 0; i < 12; ++i)
                Tl[i] = topb[m * 18 + i] + __ldg(&bf[j * 12 + i]);
            #pragma unroll
            for (int i = 0; i < 16; ++i) Tp[i] = Tcum[m * 17 + i];
            #pragma unroll
            for (int i = 0; i < 3; ++i)
                #pragma unroll
                for (int c = 0; c < 4; ++c)
                    Tn[i*4+c] = Tl[i*4+0]*Tp[0+c] + Tl[i*4+1]*Tp[4+c]
                              + Tl[i*4+2]*Tp[8+c] + Tl[i*4+3]*Tp[12+c];
            #pragma unroll
            for (int c = 0; c < 4; ++c) Tn[12+c] = Tp[12+c];

            float4* tp = (float4*)(out_t + (size_t)(g0 + m) * 112 + j * 16);
            tp[0] = make_float4(Tl[0], Tl[1], Tl[2],  Tl[3]);
            tp[1] = make_float4(Tl[4], Tl[5], Tl[6],  Tl[7]);
            tp[2] = make_float4(Tl[8], Tl[9], Tl[10], Tl[11]);
            tp[3] = make_float4(0.f, 0.f, 0.f, 1.f);

            ybuf[m * 21 +      j] = Tn[3];
            ybuf[m * 21 +  7 + j] = Tn[7];
            ybuf[m * 21 + 14 + j] = Tn[11];

            #pragma unroll
            for (int i = 0; i < 16; ++i) Tcum[m * 17 + i] = Tn[i];
        }
        __syncthreads();
    }

    for (int idx = tid; idx < 128 * 21; idx += TPB)
        out_y[(size_t)g0 * 21 + idx] = ybuf[idx];
}

extern "C" void kernel_launch(void* const* d_in, const int* in_sizes, int n_in,
                              void* d_out, int out_size)
{
    const float* q  = (const float*)d_in[0];
    const float* W0 = (const float*)d_in[1];
    const float* b0 = (const float*)d_in[2];
    const float* Wh = (const float*)d_in[3];
    const float* bh = (const float*)d_in[4];
    const float* Wf = (const float*)d_in[5];
    const float* bf = (const float*)d_in[6];

    const int N = in_sizes[0] / NJ;           // q is [N, 7]
    float* out_y = (float*)d_out;             // [N, 3, 7]
    float* out_t = out_y + (size_t)N * 21;    // [N, 7, 4, 4]

    cudaFuncSetAttribute(fkine_mma_kernel,
                         cudaFuncAttributeMaxDynamicSharedMemorySize, SM_TOTAL);

    fkine_mma_kernel<<<N / 128, TPB, SM_TOTAL>>>(q, W0, b0, Wh, bh, Wf, bf,
                                                 out_y, out_t);
}

// round 5
// speedup vs baseline: 2.4748x; 1.2168x over previous
#include <cuda_runtime.h>
#include <cuda_bf16.h>
#include <cstdint>
#include <math.h>

typedef uint32_t u32;

#define TPB    256
#define NJ     7
#define RSB    272          // bytes per bf16 tile row (136 bf16)

// ---- smem byte offsets ----
#define SM_A_HI   0
#define SM_A_LO   34816
#define SM_WX     69632          // W1 hi+lo (hi at +0, lo at +34816)
#define SM_WY     139264         // W2 hi+lo
#define SM_WF     208896         // Wf hi+lo (hi at +0, lo at +4352)
#define SM_TCUM   217600         // 128 x 17 f32
#define SM_TOTAL  226304
#define BIGLO     34816
#define WFLO      4352
#define TOPOFF    144            // TOP overlay: SM_A_LO + r*RSB + TOPOFF (18 floats)

// ---- preconverted weight images in global ----
#define BIGSZ   69632            // one hidden layer hi+lo image
#define WFSZ    8704
#define JSTRIDE (2*BIGSZ + WFSZ) // 147968: [W1hi W1lo W2hi W2lo Wfhi Wflo]
__device__ __align__(16) char g_wbuf[NJ * JSTRIDE];

static __device__ __forceinline__ u32 smem_u32(const void* p) {
    u32 a;
    asm("{ .reg .u64 t; cvta.to.shared.u64 t, %1; cvt.u32.u64 %0, t; }" : "=r"(a) : "l"(p));
    return a;
}
static __device__ __forceinline__ u32 packbf(float x0, float x1) {
    u32 r;
    asm("cvt.rn.bf16x2.f32 %0, %1, %2;" : "=r"(r) : "f"(x1), "f"(x0));
    return r;
}
static __device__ __forceinline__ uint4 ldmx4(u32 addr) {
    uint4 r;
    asm volatile("ldmatrix.sync.aligned.m8n8.x4.shared.b16 {%0,%1,%2,%3}, [%4];"
                 : "=r"(r.x), "=r"(r.y), "=r"(r.z), "=r"(r.w) : "r"(addr));
    return r;
}
static __device__ __forceinline__ void mma_bf(float d[4], const uint4& a, u32 b0, u32 b1) {
    asm volatile("mma.sync.aligned.m16n8k16.row.col.f32.bf16.bf16.f32 "
                 "{%0,%1,%2,%3},{%4,%5,%6,%7},{%8,%9},{%0,%1,%2,%3};"
                 : "+f"(d[0]), "+f"(d[1]), "+f"(d[2]), "+f"(d[3])
                 : "r"(a.x), "r"(a.y), "r"(a.z), "r"(a.w), "r"(b0), "r"(b1));
}
static __device__ __forceinline__ void split2(float v0, float v1, u32& hi, u32& lo) {
    hi = packbf(v0, v1);
    float r0 = v0 - __uint_as_float(hi << 16);
    float r1 = v1 - __uint_as_float(hi & 0xffff0000u);
    lo = packbf(r0, r1);
}
// async copy 'bytes' (mult of 16) from global to smem, one commit group
static __device__ __forceinline__ void cpy_async(u32 dst, const char* src, int bytes, int tid) {
    for (int off = tid * 16; off < bytes; off += TPB * 16)
        asm volatile("cp.async.cg.shared.global [%0], [%1], 16;"
                     :: "r"(dst + off), "l"(src + off));
    asm volatile("cp.async.commit_group;" ::: "memory");
}
#define CP_WAIT(n) asm volatile("cp.async.wait_group %0;" :: "n"(n) : "memory")

// ============ weight preconversion kernel (runs once per launch) ============
__global__ void conv_weights_kernel(const float* __restrict__ Wh,
                                    const float* __restrict__ Wf)
{
    const int stride = gridDim.x * blockDim.x;
    const int t0 = blockIdx.x * blockDim.x + threadIdx.x;
    // hidden layers: 14 x [128 x 128]
    for (int i = t0; i < 14 * 16384; i += stride) {
        int layer = i >> 14;
        int j = layer >> 1, l = layer & 1;
        int r = (i >> 7) & 127, k = i & 127;
        float v = Wh[i];
        __nv_bfloat16 h = __float2bfloat16(v);
        __nv_bfloat16 lo = __float2bfloat16(v - __bfloat162float(h));
        char* base = g_wbuf + j * JSTRIDE + l * BIGSZ;
        ((__nv_bfloat16*)base)[r * 136 + k] = h;
        ((__nv_bfloat16*)(base + BIGLO))[r * 136 + k] = lo;
    }
    // final layers: 7 x [12 x 128] into 16-row images
    for (int i = t0; i < 7 * 1536; i += stride) {
        int j = i / 1536;
        int rem = i - j * 1536;
        int r = rem >> 7, k = rem & 127;
        float v = Wf[i];
        __nv_bfloat16 h = __float2bfloat16(v);
        __nv_bfloat16 lo = __float2bfloat16(v - __bfloat162float(h));
        char* base = g_wbuf + j * JSTRIDE + 2 * BIGSZ;
        ((__nv_bfloat16*)base)[r * 136 + k] = h;
        ((__nv_bfloat16*)(base + WFLO))[r * 136 + k] = lo;
    }
    // zero rows 12..15 of final images (incl. pad cols)
    for (int i = t0; i < 7 * 4 * 136; i += stride) {
        int j = i / 544;
        int rem = i - j * 544;
        int r = 12 + rem / 136, k = rem % 136;
        char* base = g_wbuf + j * JSTRIDE + 2 * BIGSZ;
        ((__nv_bfloat16*)base)[r * 136 + k] = __float2bfloat16(0.f);
        ((__nv_bfloat16*)(base + WFLO))[r * 136 + k] = __float2bfloat16(0.f);
    }
}

// ============ main kernel ============

// hidden layer: A <- relu(A @ W^T + bias); warps 4m x 2n
static __device__ void mma_hidden(u32 smb, char* sm, const float* __restrict__ bias,
                                  u32 wbase, int lane, int wid)
{
    const int m_base = (wid >> 1) * 32;
    const int n_base = (wid & 1) * 64;
    float acc[2][8][4];
    #pragma unroll
    for (int mt = 0; mt < 2; ++mt)
        #pragma unroll
        for (int nt = 0; nt < 8; ++nt)
            #pragma unroll
            for (int e = 0; e < 4; ++e) acc[mt][nt][e] = 0.f;

    const int arow = lane & 15, acol = (lane >> 4) << 3;
    const int brow = (lane & 7) + ((lane & 16) >> 1);
    const int bcol = lane & 8;

    #pragma unroll
    for (int k = 0; k < 8; ++k) {
        int k0 = k * 16;
        uint4 ahi[2], alo[2];
        #pragma unroll
        for (int mt = 0; mt < 2; ++mt) {
            u32 a = smb + SM_A_HI + (u32)(m_base + mt * 16 + arow) * RSB + (u32)(k0 + acol) * 2;
            ahi[mt] = ldmx4(a);
            alo[mt] = ldmx4(a + (SM_A_LO - SM_A_HI));
        }
        #pragma unroll
        for (int np = 0; np < 4; ++np) {
            int n0 = n_base + np * 16;
            u32 b = smb + wbase + (u32)(n0 + brow) * RSB + (u32)(k0 + bcol) * 2;
            uint4 bh = ldmx4(b);
            uint4 bl = ldmx4(b + BIGLO);
            #pragma unroll
            for (int mt = 0; mt < 2; ++mt) {
                mma_bf(acc[mt][np*2+0], ahi[mt], bh.x, bh.y);
                mma_bf(acc[mt][np*2+0], ahi[mt], bl.x, bl.y);
                mma_bf(acc[mt][np*2+0], alo[mt], bh.x, bh.y);
                mma_bf(acc[mt][np*2+1], ahi[mt], bh.z, bh.w);
                mma_bf(acc[mt][np*2+1], ahi[mt], bl.z, bl.w);
                mma_bf(acc[mt][np*2+1], alo[mt], bh.z, bh.w);
            }
        }
    }
    __syncthreads();   // all warps done reading A before overwrite
    #pragma unroll
    for (int mt = 0; mt < 2; ++mt) {
        #pragma unroll
        for (int nt = 0; nt < 8; ++nt) {
            int r = m_base + mt * 16 + (lane >> 2);
            int c = n_base + nt * 8 + 2 * (lane & 3);
            float b0v = __ldg(&bias[c]), b1v = __ldg(&bias[c + 1]);
            u32 hi, lo;
            float v0 = fmaxf(acc[mt][nt][0] + b0v, 0.f);
            float v1 = fmaxf(acc[mt][nt][1] + b1v, 0.f);
            split2(v0, v1, hi, lo);
            *(u32*)(sm + SM_A_HI + r * RSB + c * 2) = hi;
            *(u32*)(sm + SM_A_LO + r * RSB + c * 2) = lo;
            float v2 = fmaxf(acc[mt][nt][2] + b0v, 0.f);
            float v3 = fmaxf(acc[mt][nt][3] + b1v, 0.f);
            split2(v2, v3, hi, lo);
            *(u32*)(sm + SM_A_HI + (r + 8) * RSB + c * 2) = hi;
            *(u32*)(sm + SM_A_LO + (r + 8) * RSB + c * 2) = lo;
        }
    }
}

// final layer: TOP[128][16] = A @ Wf^T ; TOP overlaid on A_LO high columns
static __device__ void mma_final(u32 smb, char* sm, int lane, int wid)
{
    const int m_base = wid * 16;
    float acc[2][4] = {};
    const int arow = lane & 15, acol = (lane >> 4) << 3;
    const int brow = (lane & 7) + ((lane & 16) >> 1);
    const int bcol = lane & 8;
    #pragma unroll
    for (int k = 0; k < 8; ++k) {
        int k0 = k * 16;
        u32 a = smb + SM_A_HI + (u32)(m_base + arow) * RSB + (u32)(k0 + acol) * 2;
        uint4 ahi = ldmx4(a);
        uint4 alo = ldmx4(a + (SM_A_LO - SM_A_HI));
        u32 b = smb + SM_WF + (u32)brow * RSB + (u32)(k0 + bcol) * 2;
        uint4 bh = ldmx4(b);
        uint4 bl = ldmx4(b + WFLO);
        mma_bf(acc[0], ahi, bh.x, bh.y);
        mma_bf(acc[0], ahi, bl.x, bl.y);
        mma_bf(acc[0], alo, bh.x, bh.y);
        mma_bf(acc[1], ahi, bh.z, bh.w);
        mma_bf(acc[1], ahi, bl.z, bl.w);
        mma_bf(acc[1], alo, bh.z, bh.w);
    }
    __syncthreads();   // all reads of A (incl. overlay region) done before TOP stores
    #pragma unroll
    for (int nt = 0; nt < 2; ++nt) {
        int r = m_base + (lane >> 2);
        int c = nt * 8 + 2 * (lane & 3);
        *(float2*)(sm + SM_A_LO + r * RSB + TOPOFF + c * 4)       = make_float2(acc[nt][0], acc[nt][1]);
        *(float2*)(sm + SM_A_LO + (r + 8) * RSB + TOPOFF + c * 4) = make_float2(acc[nt][2], acc[nt][3]);
    }
}

__global__ void __launch_bounds__(TPB, 1)
fkine_mma_kernel(const float* __restrict__ q,
                 const float* __restrict__ W0,
                 const float* __restrict__ b0,
                 const float* __restrict__ bh,
                 const float* __restrict__ bf,
                 float* __restrict__ out_y,
                 float* __restrict__ out_t)
{
    extern __shared__ char sm[];
    const u32 smb = smem_u32(sm);
    const int tid = threadIdx.x, lane = tid & 31, wid = tid >> 5;
    const int g0 = blockIdx.x * 128;
    float* Tcum = (float*)(sm + SM_TCUM);

    for (int idx = tid; idx < 128 * 16; idx += TPB) {
        int m = idx >> 4, e = idx & 15;
        Tcum[m * 17 + e] = ((e >> 2) == (e & 3)) ? 1.f : 0.f;
    }
    // prologue copies: W1(0) -> WX, W2(0) -> WY  (groups in fixed order)
    cpy_async(smb + SM_WX, g_wbuf, BIGSZ, tid);
    cpy_async(smb + SM_WY, g_wbuf + BIGSZ, BIGSZ, tid);
    __syncthreads();

    for (int j = 0; j < NJ; ++j) {
        const char* gj = g_wbuf + (size_t)j * JSTRIDE;

        // ---- P0: layer 0 (K=3, scalar fp32) -> full A hi/lo; issue G1 = Wf(j)
        {
            int m = tid >> 1, hb = (tid & 1) * 64;
            float th = q[(size_t)(g0 + m) * NJ + j];
            float ct = cosf(th), st = sinf(th);
            const float* w0  = W0 + (size_t)j * 384;
            const float* b0j = b0 + (size_t)j * 128;
            for (int o = hb; o < hb + 64; o += 2) {
                float h0 = fmaxf(fmaf(w0[o*3+0], th, fmaf(w0[o*3+1], ct, fmaf(w0[o*3+2], st, b0j[o]))),   0.f);
                float h1 = fmaxf(fmaf(w0[o*3+3], th, fmaf(w0[o*3+4], ct, fmaf(w0[o*3+5], st, b0j[o+1]))), 0.f);
                u32 hi, lo;
                split2(h0, h1, hi, lo);
                *(u32*)(sm + SM_A_HI + m * RSB + o * 2) = hi;
                *(u32*)(sm + SM_A_LO + m * RSB + o * 2) = lo;
            }
        }
        cpy_async(smb + SM_WF, gj + 2 * BIGSZ, WFSZ, tid);     // G1(j)

        // ---- B1: need WX = W1(j) (allow 2 pending: W2-copy + Wf-copy)
        CP_WAIT(2);
        __syncthreads();
        // ---- P1: hidden layer 1
        mma_hidden(smb, sm, bh + (size_t)(j * 2) * 128, SM_WX, lane, wid);

        // ---- B2: need WY = W2(j) (allow 1 pending: Wf-copy)
        CP_WAIT(1);
        __syncthreads();
        // ---- P2: issue G2 = W1(j+1) -> WX, then hidden layer 2
        if (j < NJ - 1)
            cpy_async(smb + SM_WX, gj + JSTRIDE, BIGSZ, tid);
        mma_hidden(smb, sm, bh + (size_t)(j * 2 + 1) * 128, SM_WY, lane, wid);

        // ---- B3: need WF = Wf(j) (allow 1 pending: G2)
        CP_WAIT(1);
        __syncthreads();
        // ---- P3: issue G3 = W2(j+1) -> WY, then final layer
        if (j < NJ - 1)
            cpy_async(smb + SM_WY, gj + JSTRIDE + BIGSZ, BIGSZ, tid);
        mma_final(smb, sm, lane, wid);
        __syncthreads();

        // ---- P4: chain epilogue (one thread per sample)
        if (tid < 128) {
            int m = tid;
            float Tl[12], Tp[16], Tn[16];
            #pragma unroll
            for (int i = 0; i < 12; ++i)
                Tl[i] = *(float*)(sm + SM_A_LO + m * RSB + TOPOFF + i * 4) + __ldg(&bf[j * 12 + i]);
            #pragma unroll
            for (int i = 0; i < 16; ++i) Tp[i] = Tcum[m * 17 + i];
            #pragma unroll
            for (int i = 0; i < 3; ++i)
                #pragma unroll
                for (int c = 0; c < 4; ++c)
                    Tn[i*4+c] = Tl[i*4+0]*Tp[0+c] + Tl[i*4+1]*Tp[4+c]
                              + Tl[i*4+2]*Tp[8+c] + Tl[i*4+3]*Tp[12+c];
            #pragma unroll
            for (int c = 0; c < 4; ++c) Tn[12+c] = Tp[12+c];

            float4* tp = (float4*)(out_t + (size_t)(g0 + m) * 112 + j * 16);
            tp[0] = make_float4(Tl[0], Tl[1], Tl[2],  Tl[3]);
            tp[1] = make_float4(Tl[4], Tl[5], Tl[6],  Tl[7]);
            tp[2] = make_float4(Tl[8], Tl[9], Tl[10], Tl[11]);
            tp[3] = make_float4(0.f, 0.f, 0.f, 1.f);

            size_t yb = (size_t)(g0 + m) * 21 + j;
            out_y[yb]      = Tn[3];
            out_y[yb + 7]  = Tn[7];
            out_y[yb + 14] = Tn[11];

            #pragma unroll
            for (int i = 0; i < 16; ++i) Tcum[m * 17 + i] = Tn[i];
        }
        __syncthreads();
    }
}

extern "C" void kernel_launch(void* const* d_in, const int* in_sizes, int n_in,
                              void* d_out, int out_size)
{
    const float* q  = (const float*)d_in[0];
    const float* W0 = (const float*)d_in[1];
    const float* b0 = (const float*)d_in[2];
    const float* Wh = (const float*)d_in[3];
    const float* bh = (const float*)d_in[4];
    const float* Wf = (const float*)d_in[5];
    const float* bf = (const float*)d_in[6];

    const int N = in_sizes[0] / NJ;           // q is [N, 7]
    float* out_y = (float*)d_out;             // [N, 3, 7]
    float* out_t = out_y + (size_t)N * 21;    // [N, 7, 4, 4]

    conv_weights_kernel<<<128, 256>>>(Wh, Wf);

    cudaFuncSetAttribute(fkine_mma_kernel,
                         cudaFuncAttributeMaxDynamicSharedMemorySize, SM_TOTAL);
    fkine_mma_kernel<<<N / 128, TPB, SM_TOTAL>>>(q, W0, b0, bh, bf, out_y, out_t);
}

// round 6
// speedup vs baseline: 2.5816x; 1.0431x over previous
#include <cuda_runtime.h>
#include <cuda_bf16.h>
#include <cstdint>
#include <math.h>

typedef uint32_t u32;

#define TPB    256
#define NJ     7
#define RSB    272          // bytes per bf16 tile row (136 bf16)

// ---- smem byte offsets ----
#define SM_A_HI   0
#define SM_A_LO   34816
#define SM_WX     69632          // W1 hi+lo (hi at +0, lo at +34816)
#define SM_WY     139264         // W2 hi+lo
#define SM_WF     208896         // Wf hi+lo (hi at +0, lo at +4352)
#define SM_TCUM   217600         // 128 x 17 f32
#define SM_MBAR   226304         // 3 mbarriers (8B each)
#define SM_TOTAL  226368
#define BIGLO     34816
#define WFLO      4352
#define TOPOFF    144            // TOP overlay: SM_A_LO + r*RSB + TOPOFF

// ---- preconverted weight images in global ----
#define BIGSZ   69632            // one hidden layer hi+lo image
#define WFSZ    8704
#define JSTRIDE (2*BIGSZ + WFSZ) // [W1hi W1lo W2hi W2lo Wfhi Wflo]
__device__ __align__(16) char g_wbuf[NJ * JSTRIDE];

static __device__ __forceinline__ u32 smem_u32(const void* p) {
    u32 a;
    asm("{ .reg .u64 t; cvta.to.shared.u64 t, %1; cvt.u32.u64 %0, t; }" : "=r"(a) : "l"(p));
    return a;
}
static __device__ __forceinline__ u32 packbf(float x0, float x1) {
    u32 r;
    asm("cvt.rn.bf16x2.f32 %0, %1, %2;" : "=r"(r) : "f"(x1), "f"(x0));
    return r;
}
static __device__ __forceinline__ uint4 ldmx4(u32 addr) {
    uint4 r;
    asm volatile("ldmatrix.sync.aligned.m8n8.x4.shared.b16 {%0,%1,%2,%3}, [%4];"
                 : "=r"(r.x), "=r"(r.y), "=r"(r.z), "=r"(r.w) : "r"(addr));
    return r;
}
static __device__ __forceinline__ void mma_bf(float d[4], const uint4& a, u32 b0, u32 b1) {
    asm volatile("mma.sync.aligned.m16n8k16.row.col.f32.bf16.bf16.f32 "
                 "{%0,%1,%2,%3},{%4,%5,%6,%7},{%8,%9},{%0,%1,%2,%3};"
                 : "+f"(d[0]), "+f"(d[1]), "+f"(d[2]), "+f"(d[3])
                 : "r"(a.x), "r"(a.y), "r"(a.z), "r"(a.w), "r"(b0), "r"(b1));
}
static __device__ __forceinline__ void split2(float v0, float v1, u32& hi, u32& lo) {
    hi = packbf(v0, v1);
    float r0 = v0 - __uint_as_float(hi << 16);
    float r1 = v1 - __uint_as_float(hi & 0xffff0000u);
    lo = packbf(r0, r1);
}

// ---- TMA bulk copy + mbarrier machinery ----
#define MBAR_INIT(mb, c)  asm volatile("mbarrier.init.shared.b64 [%0], %1;" :: "r"((u32)(mb)), "r"((u32)(c)) : "memory")
#define MBAR_EXPECT(mb, bytes) \
    asm volatile("mbarrier.arrive.expect_tx.shared.b64 _, [%0], %1;" :: "r"((u32)(mb)), "r"((u32)(bytes)) : "memory")
#define TMA_BULK(dst, src, bytes, mb) \
    asm volatile("cp.async.bulk.shared::cta.global.mbarrier::complete_tx::bytes [%0], [%1], %2, [%3];" \
                 :: "r"((u32)(dst)), "l"(src), "r"((u32)(bytes)), "r"((u32)(mb)) : "memory")
#define FENCE_ASYNC() asm volatile("fence.proxy.async.shared::cta;" ::: "memory")

#define MBAR_WAIT(mb, ph) do { \
    u32 _mb = (u32)(mb); u32 _p = (u32)(ph); u32 _done; \
    asm volatile("{ .reg .pred p; mbarrier.try_wait.parity.acquire.cta.shared::cta.b64 p, [%1], %2; selp.b32 %0, 1, 0, p; }" \
        : "=r"(_done) : "r"(_mb), "r"(_p) : "memory"); \
    if (!_done) { \
        asm volatile("{ .reg .pred P1;\n\t" \
            "WL_%=:\n\t" \
            "mbarrier.try_wait.parity.acquire.cta.shared::cta.b64 P1, [%0], %1, 0x989680;\n\t" \
            "@P1 bra.uni WD_%=;\n\t" \
            "bra.uni WL_%=;\n\t" \
            "WD_%=: }" :: "r"(_mb), "r"(_p) : "memory"); \
    } } while (0)

// ============ weight preconversion kernel (runs once per launch) ============
__global__ void conv_weights_kernel(const float* __restrict__ Wh,
                                    const float* __restrict__ Wf)
{
    const int stride = gridDim.x * blockDim.x;
    const int t0 = blockIdx.x * blockDim.x + threadIdx.x;
    for (int i = t0; i < 14 * 16384; i += stride) {
        int layer = i >> 14;
        int j = layer >> 1, l = layer & 1;
        int r = (i >> 7) & 127, k = i & 127;
        float v = Wh[i];
        __nv_bfloat16 h = __float2bfloat16(v);
        __nv_bfloat16 lo = __float2bfloat16(v - __bfloat162float(h));
        char* base = g_wbuf + j * JSTRIDE + l * BIGSZ;
        ((__nv_bfloat16*)base)[r * 136 + k] = h;
        ((__nv_bfloat16*)(base + BIGLO))[r * 136 + k] = lo;
    }
    for (int i = t0; i < 7 * 1536; i += stride) {
        int j = i / 1536;
        int rem = i - j * 1536;
        int r = rem >> 7, k = rem & 127;
        float v = Wf[i];
        __nv_bfloat16 h = __float2bfloat16(v);
        __nv_bfloat16 lo = __float2bfloat16(v - __bfloat162float(h));
        char* base = g_wbuf + j * JSTRIDE + 2 * BIGSZ;
        ((__nv_bfloat16*)base)[r * 136 + k] = h;
        ((__nv_bfloat16*)(base + WFLO))[r * 136 + k] = lo;
    }
    for (int i = t0; i < 7 * 4 * 136; i += stride) {
        int j = i / 544;
        int rem = i - j * 544;
        int r = 12 + rem / 136, k = rem % 136;
        char* base = g_wbuf + j * JSTRIDE + 2 * BIGSZ;
        ((__nv_bfloat16*)base)[r * 136 + k] = __float2bfloat16(0.f);
        ((__nv_bfloat16*)(base + WFLO))[r * 136 + k] = __float2bfloat16(0.f);
    }
}

// ============ main kernel ============

// hidden layer: A <- relu(A @ W^T + bias); warps 4m x 2n
static __device__ void mma_hidden(u32 smb, char* sm, const float* __restrict__ bias,
                                  u32 wbase, int lane, int wid)
{
    const int m_base = (wid >> 1) * 32;
    const int n_base = (wid & 1) * 64;
    float acc[2][8][4];
    #pragma unroll
    for (int mt = 0; mt < 2; ++mt)
        #pragma unroll
        for (int nt = 0; nt < 8; ++nt)
            #pragma unroll
            for (int e = 0; e < 4; ++e) acc[mt][nt][e] = 0.f;

    const int arow = lane & 15, acol = (lane >> 4) << 3;
    const int brow = (lane & 7) + ((lane & 16) >> 1);
    const int bcol = lane & 8;

    #pragma unroll
    for (int k = 0; k < 8; ++k) {
        int k0 = k * 16;
        uint4 ahi[2], alo[2];
        #pragma unroll
        for (int mt = 0; mt < 2; ++mt) {
            u32 a = smb + SM_A_HI + (u32)(m_base + mt * 16 + arow) * RSB + (u32)(k0 + acol) * 2;
            ahi[mt] = ldmx4(a);
            alo[mt] = ldmx4(a + (SM_A_LO - SM_A_HI));
        }
        #pragma unroll
        for (int np = 0; np < 4; ++np) {
            int n0 = n_base + np * 16;
            u32 b = smb + wbase + (u32)(n0 + brow) * RSB + (u32)(k0 + bcol) * 2;
            uint4 bh = ldmx4(b);
            uint4 bl = ldmx4(b + BIGLO);
            #pragma unroll
            for (int mt = 0; mt < 2; ++mt) {
                mma_bf(acc[mt][np*2+0], ahi[mt], bh.x, bh.y);
                mma_bf(acc[mt][np*2+0], ahi[mt], bl.x, bl.y);
                mma_bf(acc[mt][np*2+0], alo[mt], bh.x, bh.y);
                mma_bf(acc[mt][np*2+1], ahi[mt], bh.z, bh.w);
                mma_bf(acc[mt][np*2+1], ahi[mt], bl.z, bl.w);
                mma_bf(acc[mt][np*2+1], alo[mt], bh.z, bh.w);
            }
        }
    }
    __syncthreads();   // all warps done reading A (and W) before overwrite
    #pragma unroll
    for (int mt = 0; mt < 2; ++mt) {
        #pragma unroll
        for (int nt = 0; nt < 8; ++nt) {
            int r = m_base + mt * 16 + (lane >> 2);
            int c = n_base + nt * 8 + 2 * (lane & 3);
            float b0v = __ldg(&bias[c]), b1v = __ldg(&bias[c + 1]);
            u32 hi, lo;
            float v0 = fmaxf(acc[mt][nt][0] + b0v, 0.f);
            float v1 = fmaxf(acc[mt][nt][1] + b1v, 0.f);
            split2(v0, v1, hi, lo);
            *(u32*)(sm + SM_A_HI + r * RSB + c * 2) = hi;
            *(u32*)(sm + SM_A_LO + r * RSB + c * 2) = lo;
            float v2 = fmaxf(acc[mt][nt][2] + b0v, 0.f);
            float v3 = fmaxf(acc[mt][nt][3] + b1v, 0.f);
            split2(v2, v3, hi, lo);
            *(u32*)(sm + SM_A_HI + (r + 8) * RSB + c * 2) = hi;
            *(u32*)(sm + SM_A_LO + (r + 8) * RSB + c * 2) = lo;
        }
    }
}

// final layer: TOP[128][16] = A @ Wf^T ; TOP overlaid on A_LO high columns
static __device__ void mma_final(u32 smb, char* sm, int lane, int wid)
{
    const int m_base = wid * 16;
    float acc[2][4] = {};
    const int arow = lane & 15, acol = (lane >> 4) << 3;
    const int brow = (lane & 7) + ((lane & 16) >> 1);
    const int bcol = lane & 8;
    #pragma unroll
    for (int k = 0; k < 8; ++k) {
        int k0 = k * 16;
        u32 a = smb + SM_A_HI + (u32)(m_base + arow) * RSB + (u32)(k0 + acol) * 2;
        uint4 ahi = ldmx4(a);
        uint4 alo = ldmx4(a + (SM_A_LO - SM_A_HI));
        u32 b = smb + SM_WF + (u32)brow * RSB + (u32)(k0 + bcol) * 2;
        uint4 bh = ldmx4(b);
        uint4 bl = ldmx4(b + WFLO);
        mma_bf(acc[0], ahi, bh.x, bh.y);
        mma_bf(acc[0], ahi, bl.x, bl.y);
        mma_bf(acc[0], alo, bh.x, bh.y);
        mma_bf(acc[1], ahi, bh.z, bh.w);
        mma_bf(acc[1], ahi, bl.z, bl.w);
        mma_bf(acc[1], alo, bh.z, bh.w);
    }
    __syncthreads();   // all reads of A (incl. overlay region) done before TOP stores
    #pragma unroll
    for (int nt = 0; nt < 2; ++nt) {
        int r = m_base + (lane >> 2);
        int c = nt * 8 + 2 * (lane & 3);
        *(float2*)(sm + SM_A_LO + r * RSB + TOPOFF + c * 4)       = make_float2(acc[nt][0], acc[nt][1]);
        *(float2*)(sm + SM_A_LO + (r + 8) * RSB + TOPOFF + c * 4) = make_float2(acc[nt][2], acc[nt][3]);
    }
}

__global__ void __launch_bounds__(TPB, 1)
fkine_mma_kernel(const float* __restrict__ q,
                 const float* __restrict__ W0,
                 const float* __restrict__ b0,
                 const float* __restrict__ bh,
                 const float* __restrict__ bf,
                 float* __restrict__ out_y,
                 float* __restrict__ out_t)
{
    extern __shared__ char sm[];
    const u32 smb = smem_u32(sm);
    const int tid = threadIdx.x, lane = tid & 31, wid = tid >> 5;
    const int g0 = blockIdx.x * 128;
    float* Tcum = (float*)(sm + SM_TCUM);
    const u32 mbX = smb + SM_MBAR, mbY = smb + SM_MBAR + 8, mbF = smb + SM_MBAR + 16;
    const char* gw = g_wbuf;

    // init barriers + prologue TMA copies (WX = W1(0), WY = W2(0))
    if (tid == 0) {
        MBAR_INIT(mbX, 1); MBAR_INIT(mbY, 1); MBAR_INIT(mbF, 1);
        FENCE_ASYNC();
        MBAR_EXPECT(mbX, BIGSZ); TMA_BULK(smb + SM_WX, gw, BIGSZ, mbX);
        MBAR_EXPECT(mbY, BIGSZ); TMA_BULK(smb + SM_WY, gw + BIGSZ, BIGSZ, mbY);
    }
    for (int idx = tid; idx < 128 * 16; idx += TPB) {
        int m = idx >> 4, e = idx & 15;
        Tcum[m * 17 + e] = ((e >> 2) == (e & 3)) ? 1.f : 0.f;
    }
    __syncthreads();

    int phX = 0, phY = 0, phF = 0;

    for (int j = 0; j < NJ; ++j) {
        const char* gj = gw + (size_t)j * JSTRIDE;

        // ---- P0: layer 0 (K=3, scalar fp32) -> A hi/lo; issue WF(j)
        if (tid == 0) {
            MBAR_EXPECT(mbF, WFSZ); TMA_BULK(smb + SM_WF, gj + 2 * BIGSZ, WFSZ, mbF);
        }
        {
            int m = tid >> 1, hb = (tid & 1) * 64;
            float th = q[(size_t)(g0 + m) * NJ + j];
            float ct = cosf(th), st = sinf(th);
            const float* w0  = W0 + (size_t)j * 384;
            const float* b0j = b0 + (size_t)j * 128;
            for (int o = hb; o < hb + 64; o += 2) {
                float h0 = fmaxf(fmaf(w0[o*3+0], th, fmaf(w0[o*3+1], ct, fmaf(w0[o*3+2], st, b0j[o]))),   0.f);
                float h1 = fmaxf(fmaf(w0[o*3+3], th, fmaf(w0[o*3+4], ct, fmaf(w0[o*3+5], st, b0j[o+1]))), 0.f);
                u32 hi, lo;
                split2(h0, h1, hi, lo);
                *(u32*)(sm + SM_A_HI + m * RSB + o * 2) = hi;
                *(u32*)(sm + SM_A_LO + m * RSB + o * 2) = lo;
            }
        }
        __syncthreads();           // A ready for all warps

        // ---- P1: hidden layer 1 (uses WX)
        MBAR_WAIT(mbX, phX); phX ^= 1;
        mma_hidden(smb, sm, bh + (size_t)(j * 2) * 128, SM_WX, lane, wid);
        __syncthreads();           // new A visible; WX reads complete

        // ---- P2: refill WX with W1(j+1); hidden layer 2 (uses WY)
        if (tid == 0 && j < NJ - 1) {
            MBAR_EXPECT(mbX, BIGSZ); TMA_BULK(smb + SM_WX, gj + JSTRIDE, BIGSZ, mbX);
        }
        MBAR_WAIT(mbY, phY); phY ^= 1;
        mma_hidden(smb, sm, bh + (size_t)(j * 2 + 1) * 128, SM_WY, lane, wid);
        __syncthreads();           // new A visible; WY reads complete

        // ---- P3: refill WY with W2(j+1); final layer (uses WF)
        if (tid == 0 && j < NJ - 1) {
            MBAR_EXPECT(mbY, BIGSZ); TMA_BULK(smb + SM_WY, gj + JSTRIDE + BIGSZ, BIGSZ, mbY);
        }
        MBAR_WAIT(mbF, phF); phF ^= 1;
        mma_final(smb, sm, lane, wid);
        __syncthreads();

        // ---- P4: chain epilogue (one thread per sample)
        if (tid < 128) {
            int m = tid;
            float Tl[12], Tp[16], Tn[16];
            #pragma unroll
            for (int i = 0; i < 12; ++i)
                Tl[i] = *(float*)(sm + SM_A_LO + m * RSB + TOPOFF + i * 4) + __ldg(&bf[j * 12 + i]);
            #pragma unroll
            for (int i = 0; i < 16; ++i) Tp[i] = Tcum[m * 17 + i];
            #pragma unroll
            for (int i = 0; i < 3; ++i)
                #pragma unroll
                for (int c = 0; c < 4; ++c)
                    Tn[i*4+c] = Tl[i*4+0]*Tp[0+c] + Tl[i*4+1]*Tp[4+c]
                              + Tl[i*4+2]*Tp[8+c] + Tl[i*4+3]*Tp[12+c];
            #pragma unroll
            for (int c = 0; c < 4; ++c) Tn[12+c] = Tp[12+c];

            float4* tp = (float4*)(out_t + (size_t)(g0 + m) * 112 + j * 16);
            tp[0] = make_float4(Tl[0], Tl[1], Tl[2],  Tl[3]);
            tp[1] = make_float4(Tl[4], Tl[5], Tl[6],  Tl[7]);
            tp[2] = make_float4(Tl[8], Tl[9], Tl[10], Tl[11]);
            tp[3] = make_float4(0.f, 0.f, 0.f, 1.f);

            size_t yb = (size_t)(g0 + m) * 21 + j;
            out_y[yb]      = Tn[3];
            out_y[yb + 7]  = Tn[7];
            out_y[yb + 14] = Tn[11];

            #pragma unroll
            for (int i = 0; i < 16; ++i) Tcum[m * 17 + i] = Tn[i];
        }
        __syncthreads();
    }
}

extern "C" void kernel_launch(void* const* d_in, const int* in_sizes, int n_in,
                              void* d_out, int out_size)
{
    const float* q  = (const float*)d_in[0];
    const float* W0 = (const float*)d_in[1];
    const float* b0 = (const float*)d_in[2];
    const float* Wh = (const float*)d_in[3];
    const float* bh = (const float*)d_in[4];
    const float* Wf = (const float*)d_in[5];
    const float* bf = (const float*)d_in[6];

    const int N = in_sizes[0] / NJ;           // q is [N, 7]
    float* out_y = (float*)d_out;             // [N, 3, 7]
    float* out_t = out_y + (size_t)N * 21;    // [N, 7, 4, 4]

    conv_weights_kernel<<<128, 256>>>(Wh, Wf);

    cudaFuncSetAttribute(fkine_mma_kernel,
                         cudaFuncAttributeMaxDynamicSharedMemorySize, SM_TOTAL);
    fkine_mma_kernel<<<N / 128, TPB, SM_TOTAL>>>(q, W0, b0, bh, bf, out_y, out_t);
}

// round 8
// speedup vs baseline: 2.6695x; 1.0341x over previous
#include <cuda_runtime.h>
#include <cuda_bf16.h>
#include <cstdint>
#include <math.h>

typedef uint32_t u32;

#define TPB    256
#define NJ     7
#define RSB    272          // bytes per bf16 tile row (136 bf16)
#define TILE_M 64

// ---- smem byte offsets ----
#define SM_A_HI   0
#define SM_A_LO   17408          // 64*272
#define SM_W      34816          // hidden W hi+lo (hi at +0, lo at +34816)
#define SM_WF     104448         // Wf hi+lo (hi at +0, lo at +4352)
#define SM_MBAR   113152         // 2 mbarriers
#define SM_TOTAL  113168
#define BIGLO     34816
#define WFLO      4352
#define TOPOFF    144            // TOP overlay: SM_A_LO + r*RSB + TOPOFF

// ---- preconverted weight images in global ----
#define BIGSZ   69632
#define WFSZ    8704
#define JSTRIDE (2*BIGSZ + WFSZ) // [W1hi W1lo W2hi W2lo Wfhi Wflo]
__device__ __align__(16) char g_wbuf[NJ * JSTRIDE];

static __device__ __forceinline__ u32 smem_u32(const void* p) {
    u32 a;
    asm("{ .reg .u64 t; cvta.to.shared.u64 t, %1; cvt.u32.u64 %0, t; }" : "=r"(a) : "l"(p));
    return a;
}
static __device__ __forceinline__ u32 packbf(float x0, float x1) {
    u32 r;
    asm("cvt.rn.bf16x2.f32 %0, %1, %2;" : "=r"(r) : "f"(x1), "f"(x0));
    return r;
}
static __device__ __forceinline__ uint4 ldmx4(u32 addr) {
    uint4 r;
    asm volatile("ldmatrix.sync.aligned.m8n8.x4.shared.b16 {%0,%1,%2,%3}, [%4];"
                 : "=r"(r.x), "=r"(r.y), "=r"(r.z), "=r"(r.w) : "r"(addr));
    return r;
}
static __device__ __forceinline__ void mma_bf(float d[4], const uint4& a, u32 b0, u32 b1) {
    asm volatile("mma.sync.aligned.m16n8k16.row.col.f32.bf16.bf16.f32 "
                 "{%0,%1,%2,%3},{%4,%5,%6,%7},{%8,%9},{%0,%1,%2,%3};"
                 : "+f"(d[0]), "+f"(d[1]), "+f"(d[2]), "+f"(d[3])
                 : "r"(a.x), "r"(a.y), "r"(a.z), "r"(a.w), "r"(b0), "r"(b1));
}
static __device__ __forceinline__ void split2(float v0, float v1, u32& hi, u32& lo) {
    hi = packbf(v0, v1);
    float r0 = v0 - __uint_as_float(hi << 16);
    float r1 = v1 - __uint_as_float(hi & 0xffff0000u);
    lo = packbf(r0, r1);
}

// ---- TMA bulk copy + mbarrier machinery ----
#define MBAR_INIT(mb, c)  asm volatile("mbarrier.init.shared.b64 [%0], %1;" :: "r"((u32)(mb)), "r"((u32)(c)) : "memory")
#define MBAR_EXPECT(mb, bytes) \
    asm volatile("mbarrier.arrive.expect_tx.shared.b64 _, [%0], %1;" :: "r"((u32)(mb)), "r"((u32)(bytes)) : "memory")
#define TMA_BULK(dst, src, bytes, mb) \
    asm volatile("cp.async.bulk.shared::cta.global.mbarrier::complete_tx::bytes [%0], [%1], %2, [%3];" \
                 :: "r"((u32)(dst)), "l"(src), "r"((u32)(bytes)), "r"((u32)(mb)) : "memory")
#define FENCE_ASYNC() asm volatile("fence.proxy.async.shared::cta;" ::: "memory")

#define MBAR_WAIT(mb, ph) do { \
    u32 _mb = (u32)(mb); u32 _p = (u32)(ph); u32 _done; \
    asm volatile("{ .reg .pred p; mbarrier.try_wait.parity.acquire.cta.shared::cta.b64 p, [%1], %2; selp.b32 %0, 1, 0, p; }" \
        : "=r"(_done) : "r"(_mb), "r"(_p) : "memory"); \
    if (!_done) { \
        asm volatile("{ .reg .pred P1;\n\t" \
            "WL_%=:\n\t" \
            "mbarrier.try_wait.parity.acquire.cta.shared::cta.b64 P1, [%0], %1, 0x989680;\n\t" \
            "@P1 bra.uni WD_%=;\n\t" \
            "bra.uni WL_%=;\n\t" \
            "WD_%=: }" :: "r"(_mb), "r"(_p) : "memory"); \
    } } while (0)

// ============ weight preconversion kernel (runs once per launch) ============
__global__ void conv_weights_kernel(const float* __restrict__ Wh,
                                    const float* __restrict__ Wf)
{
    const int stride = gridDim.x * blockDim.x;
    const int t0 = blockIdx.x * blockDim.x + threadIdx.x;
    for (int i = t0; i < 14 * 16384; i += stride) {
        int layer = i >> 14;
        int j = layer >> 1, l = layer & 1;
        int r = (i >> 7) & 127, k = i & 127;
        float v = Wh[i];
        __nv_bfloat16 h = __float2bfloat16(v);
        __nv_bfloat16 lo = __float2bfloat16(v - __bfloat162float(h));
        char* base = g_wbuf + j * JSTRIDE + l * BIGSZ;
        ((__nv_bfloat16*)base)[r * 136 + k] = h;
        ((__nv_bfloat16*)(base + BIGLO))[r * 136 + k] = lo;
    }
    for (int i = t0; i < 7 * 1536; i += stride) {
        int j = i / 1536;
        int rem = i - j * 1536;
        int r = rem >> 7, k = rem & 127;
        float v = Wf[i];
        __nv_bfloat16 h = __float2bfloat16(v);
        __nv_bfloat16 lo = __float2bfloat16(v - __bfloat162float(h));
        char* base = g_wbuf + j * JSTRIDE + 2 * BIGSZ;
        ((__nv_bfloat16*)base)[r * 136 + k] = h;
        ((__nv_bfloat16*)(base + WFLO))[r * 136 + k] = lo;
    }
    for (int i = t0; i < 7 * 4 * 136; i += stride) {
        int j = i / 544;
        int rem = i - j * 544;
        int r = 12 + rem / 136, k = rem % 136;
        char* base = g_wbuf + j * JSTRIDE + 2 * BIGSZ;
        ((__nv_bfloat16*)base)[r * 136 + k] = __float2bfloat16(0.f);
        ((__nv_bfloat16*)(base + WFLO))[r * 136 + k] = __float2bfloat16(0.f);
    }
}

// ============ main kernel ============

// hidden layer: A <- relu(A @ W^T + bias); warps 2m x 4n (64 x 128 output)
static __device__ void mma_hidden(u32 smb, char* sm, const float* __restrict__ bias,
                                  int lane, int wid)
{
    const int m_base = (wid >> 2) * 32;
    const int n_base = (wid & 3) * 32;
    float acc[2][4][4];
    #pragma unroll
    for (int mt = 0; mt < 2; ++mt)
        #pragma unroll
        for (int nt = 0; nt < 4; ++nt)
            #pragma unroll
            for (int e = 0; e < 4; ++e) acc[mt][nt][e] = 0.f;

    const int arow = lane & 15, acol = (lane >> 4) << 3;
    const int brow = (lane & 7) + ((lane & 16) >> 1);
    const int bcol = lane & 8;

    #pragma unroll
    for (int k = 0; k < 8; ++k) {
        int k0 = k * 16;
        uint4 ahi[2], alo[2];
        #pragma unroll
        for (int mt = 0; mt < 2; ++mt) {
            u32 a = smb + SM_A_HI + (u32)(m_base + mt * 16 + arow) * RSB + (u32)(k0 + acol) * 2;
            ahi[mt] = ldmx4(a);
            alo[mt] = ldmx4(a + (SM_A_LO - SM_A_HI));
        }
        #pragma unroll
        for (int np = 0; np < 2; ++np) {
            int n0 = n_base + np * 16;
            u32 b = smb + SM_W + (u32)(n0 + brow) * RSB + (u32)(k0 + bcol) * 2;
            uint4 bh = ldmx4(b);
            uint4 bl = ldmx4(b + BIGLO);
            #pragma unroll
            for (int mt = 0; mt < 2; ++mt) {
                mma_bf(acc[mt][np*2+0], ahi[mt], bh.x, bh.y);
                mma_bf(acc[mt][np*2+0], ahi[mt], bl.x, bl.y);
                mma_bf(acc[mt][np*2+0], alo[mt], bh.x, bh.y);
                mma_bf(acc[mt][np*2+1], ahi[mt], bh.z, bh.w);
                mma_bf(acc[mt][np*2+1], ahi[mt], bl.z, bl.w);
                mma_bf(acc[mt][np*2+1], alo[mt], bh.z, bh.w);
            }
        }
    }
    __syncthreads();   // all warps done reading A (and W) before overwrite
    #pragma unroll
    for (int mt = 0; mt < 2; ++mt) {
        #pragma unroll
        for (int nt = 0; nt < 4; ++nt) {
            int r = m_base + mt * 16 + (lane >> 2);
            int c = n_base + nt * 8 + 2 * (lane & 3);
            float b0v = __ldg(&bias[c]), b1v = __ldg(&bias[c + 1]);
            u32 hi, lo;
            float v0 = fmaxf(acc[mt][nt][0] + b0v, 0.f);
            float v1 = fmaxf(acc[mt][nt][1] + b1v, 0.f);
            split2(v0, v1, hi, lo);
            *(u32*)(sm + SM_A_HI + r * RSB + c * 2) = hi;
            *(u32*)(sm + SM_A_LO + r * RSB + c * 2) = lo;
            float v2 = fmaxf(acc[mt][nt][2] + b0v, 0.f);
            float v3 = fmaxf(acc[mt][nt][3] + b1v, 0.f);
            split2(v2, v3, hi, lo);
            *(u32*)(sm + SM_A_HI + (r + 8) * RSB + c * 2) = hi;
            *(u32*)(sm + SM_A_LO + (r + 8) * RSB + c * 2) = lo;
        }
    }
}

// final layer (warps 0-3 only): TOP[64][16] = A @ Wf^T, overlaid on A_LO.
// Each warp touches only its own m16 stripe -> no cross-warp hazard, no sync.
static __device__ void mma_final(u32 smb, char* sm, int lane, int wid)
{
    const int m_base = wid * 16;
    float acc[2][4] = {};
    const int arow = lane & 15, acol = (lane >> 4) << 3;
    const int brow = (lane & 7) + ((lane & 16) >> 1);
    const int bcol = lane & 8;
    #pragma unroll
    for (int k = 0; k < 8; ++k) {
        int k0 = k * 16;
        u32 a = smb + SM_A_HI + (u32)(m_base + arow) * RSB + (u32)(k0 + acol) * 2;
        uint4 ahi = ldmx4(a);
        uint4 alo = ldmx4(a + (SM_A_LO - SM_A_HI));
        u32 b = smb + SM_WF + (u32)brow * RSB + (u32)(k0 + bcol) * 2;
        uint4 bh = ldmx4(b);
        uint4 bl = ldmx4(b + WFLO);
        mma_bf(acc[0], ahi, bh.x, bh.y);
        mma_bf(acc[0], ahi, bl.x, bl.y);
        mma_bf(acc[0], alo, bh.x, bh.y);
        mma_bf(acc[1], ahi, bh.z, bh.w);
        mma_bf(acc[1], ahi, bl.z, bl.w);
        mma_bf(acc[1], alo, bh.z, bh.w);
    }
    #pragma unroll
    for (int nt = 0; nt < 2; ++nt) {
        int r = m_base + (lane >> 2);
        int c = nt * 8 + 2 * (lane & 3);
        *(float2*)(sm + SM_A_LO + r * RSB + TOPOFF + c * 4)       = make_float2(acc[nt][0], acc[nt][1]);
        *(float2*)(sm + SM_A_LO + (r + 8) * RSB + TOPOFF + c * 4) = make_float2(acc[nt][2], acc[nt][3]);
    }
}

__global__ void __launch_bounds__(TPB, 2)
fkine_mma_kernel(const float* __restrict__ q,
                 const float* __restrict__ W0,
                 const float* __restrict__ b0,
                 const float* __restrict__ bh,
                 const float* __restrict__ bf,
                 float* __restrict__ out_y,
                 float* __restrict__ out_t)
{
    extern __shared__ char sm[];
    const u32 smb = smem_u32(sm);
    const int tid = threadIdx.x, lane = tid & 31, wid = tid >> 5;
    const int g0 = blockIdx.x * TILE_M;
    const u32 mbW = smb + SM_MBAR, mbF = smb + SM_MBAR + 8;
    const char* gw = g_wbuf;

    // per-thread cumulative transform (threads 0..63 own sample g0+tid)
    float Tc[16];
    #pragma unroll
    for (int e = 0; e < 16; ++e) Tc[e] = ((e >> 2) == (e & 3)) ? 1.f : 0.f;

    if (tid == 0) {
        MBAR_INIT(mbW, 1); MBAR_INIT(mbF, 1);
        FENCE_ASYNC();
        MBAR_EXPECT(mbW, BIGSZ); TMA_BULK(smb + SM_W, gw, BIGSZ, mbW);
    }
    __syncthreads();

    int phW = 0, phF = 0;

    for (int j = 0; j < NJ; ++j) {
        const char* gj = gw + (size_t)j * JSTRIDE;

        // ---- P0: issue WF(j); layer 0 (K=3, scalar fp32) -> A hi/lo
        if (tid == 0) {
            MBAR_EXPECT(mbF, WFSZ); TMA_BULK(smb + SM_WF, gj + 2 * BIGSZ, WFSZ, mbF);
        }
        {
            int m = tid >> 2, qtr = tid & 3;
            float th = q[(size_t)(g0 + m) * NJ + j];
            float ct = cosf(th), st = sinf(th);
            const float* w0  = W0 + (size_t)j * 384;
            const float* b0j = b0 + (size_t)j * 128;
            int ob = qtr * 32;
            for (int o = ob; o < ob + 32; o += 2) {
                float h0 = fmaxf(fmaf(w0[o*3+0], th, fmaf(w0[o*3+1], ct, fmaf(w0[o*3+2], st, b0j[o]))),   0.f);
                float h1 = fmaxf(fmaf(w0[o*3+3], th, fmaf(w0[o*3+4], ct, fmaf(w0[o*3+5], st, b0j[o+1]))), 0.f);
                u32 hi, lo;
                split2(h0, h1, hi, lo);
                *(u32*)(sm + SM_A_HI + m * RSB + o * 2) = hi;
                *(u32*)(sm + SM_A_LO + m * RSB + o * 2) = lo;
            }
        }
        __syncthreads();

        // ---- P1: hidden layer 1 (uses W = W1(j))
        MBAR_WAIT(mbW, phW); phW ^= 1;
        mma_hidden(smb, sm, bh + (size_t)(j * 2) * 128, lane, wid);
        __syncthreads();           // new A visible; W reads complete

        // ---- P2: refill W with W2(j) (exposed; hidden by co-resident CTA), then layer 2
        if (tid == 0) {
            MBAR_EXPECT(mbW, BIGSZ); TMA_BULK(smb + SM_W, gj + BIGSZ, BIGSZ, mbW);
        }
        MBAR_WAIT(mbW, phW); phW ^= 1;
        mma_hidden(smb, sm, bh + (size_t)(j * 2 + 1) * 128, lane, wid);
        __syncthreads();

        // ---- P3: refill W with W1(j+1); final layer (warps 0-3, uses WF)
        if (tid == 0 && j < NJ - 1) {
            MBAR_EXPECT(mbW, BIGSZ); TMA_BULK(smb + SM_W, gj + JSTRIDE, BIGSZ, mbW);
        }
        MBAR_WAIT(mbF, phF); phF ^= 1;
        if (wid < 4) mma_final(smb, sm, lane, wid);
        __syncthreads();

        // ---- P4: chain epilogue (threads 0..63, Tcum in registers)
        if (tid < TILE_M) {
            int m = tid;
            float Tl[12], Tn[16];
            #pragma unroll
            for (int i = 0; i < 12; ++i)
                Tl[i] = *(float*)(sm + SM_A_LO + m * RSB + TOPOFF + i * 4) + __ldg(&bf[j * 12 + i]);
            #pragma unroll
            for (int i = 0; i < 3; ++i)
                #pragma unroll
                for (int c = 0; c < 4; ++c)
                    Tn[i*4+c] = Tl[i*4+0]*Tc[0+c] + Tl[i*4+1]*Tc[4+c]
                              + Tl[i*4+2]*Tc[8+c] + Tl[i*4+3]*Tc[12+c];
            #pragma unroll
            for (int c = 0; c < 4; ++c) Tn[12+c] = Tc[12+c];

            float4* tp = (float4*)(out_t + (size_t)(g0 + m) * 112 + j * 16);
            tp[0] = make_float4(Tl[0], Tl[1], Tl[2],  Tl[3]);
            tp[1] = make_float4(Tl[4], Tl[5], Tl[6],  Tl[7]);
            tp[2] = make_float4(Tl[8], Tl[9], Tl[10], Tl[11]);
            tp[3] = make_float4(0.f, 0.f, 0.f, 1.f);

            size_t yb = (size_t)(g0 + m) * 21 + j;
            out_y[yb]      = Tn[3];
            out_y[yb + 7]  = Tn[7];
            out_y[yb + 14] = Tn[11];

            #pragma unroll
            for (int i = 0; i < 16; ++i) Tc[i] = Tn[i];
        }
        __syncthreads();
    }
}

extern "C" void kernel_launch(void* const* d_in, const int* in_sizes, int n_in,
                              void* d_out, int out_size)
{
    const float* q  = (const float*)d_in[0];
    const float* W0 = (const float*)d_in[1];
    const float* b0 = (const float*)d_in[2];
    const float* Wh = (const float*)d_in[3];
    const float* bh = (const float*)d_in[4];
    const float* Wf = (const float*)d_in[5];
    const float* bf = (const float*)d_in[6];

    const int N = in_sizes[0] / NJ;           // q is [N, 7]
    float* out_y = (float*)d_out;             // [N, 3, 7]
    float* out_t = out_y + (size_t)N * 21;    // [N, 7, 4, 4]

    conv_weights_kernel<<<128, 256>>>(Wh, Wf);

    cudaFuncSetAttribute(fkine_mma_kernel,
                         cudaFuncAttributeMaxDynamicSharedMemorySize, SM_TOTAL);
    fkine_mma_kernel<<<N / TILE_M, TPB, SM_TOTAL>>>(q, W0, b0, bh, bf, out_y, out_t);
}

// round 9
// speedup vs baseline: 3.3599x; 1.2586x over previous
#include <cuda_runtime.h>
#include <cuda_fp16.h>
#include <cstdint>
#include <math.h>

typedef uint32_t u32;

#define TPB    256
#define NJ     7
#define RSB    272          // bytes per f16 tile row (136 halves)
#define TILE_M 64

// ---- smem byte offsets ----
#define SM_A      0              // activations, fp16 hi only: 64*272 = 17408
#define SM_W      17408          // hidden W hi+lo (hi at +0, lo at +34816): 69632
#define SM_WF     87040          // Wf hi+lo (hi at +0, lo at +4352): 8704
#define SM_MBAR   95744          // 2 mbarriers
#define SM_TOTAL  95760
#define BIGLO     34816
#define WFLO      4352
#define TOPOFF    192            // TOP overlay: SM_A + r*RSB + TOPOFF (16 f32)

// ---- preconverted fp16 weight images in global ----
#define BIGSZ   69632            // one hidden layer hi+lo image
#define WFSZ    8704
#define JSTRIDE (2*BIGSZ + WFSZ) // [W1hi W1lo W2hi W2lo Wfhi Wflo]
__device__ __align__(16) char g_wbuf[NJ * JSTRIDE];

static __device__ __forceinline__ u32 smem_u32(const void* p) {
    u32 a;
    asm("{ .reg .u64 t; cvta.to.shared.u64 t, %1; cvt.u32.u64 %0, t; }" : "=r"(a) : "l"(p));
    return a;
}
// pack two floats -> f16x2 (lo half = x0, hi half = x1)
static __device__ __forceinline__ u32 packh(float x0, float x1) {
    u32 r;
    asm("cvt.rn.f16x2.f32 %0, %1, %2;" : "=r"(r) : "f"(x1), "f"(x0));
    return r;
}
static __device__ __forceinline__ uint4 ldmx4(u32 addr) {
    uint4 r;
    asm volatile("ldmatrix.sync.aligned.m8n8.x4.shared.b16 {%0,%1,%2,%3}, [%4];"
                 : "=r"(r.x), "=r"(r.y), "=r"(r.z), "=r"(r.w) : "r"(addr));
    return r;
}
static __device__ __forceinline__ void mma_h(float d[4], const uint4& a, u32 b0, u32 b1) {
    asm volatile("mma.sync.aligned.m16n8k16.row.col.f32.f16.f16.f32 "
                 "{%0,%1,%2,%3},{%4,%5,%6,%7},{%8,%9},{%0,%1,%2,%3};"
                 : "+f"(d[0]), "+f"(d[1]), "+f"(d[2]), "+f"(d[3])
                 : "r"(a.x), "r"(a.y), "r"(a.z), "r"(a.w), "r"(b0), "r"(b1));
}

// ---- TMA bulk copy + mbarrier machinery ----
#define MBAR_INIT(mb, c)  asm volatile("mbarrier.init.shared.b64 [%0], %1;" :: "r"((u32)(mb)), "r"((u32)(c)) : "memory")
#define MBAR_EXPECT(mb, bytes) \
    asm volatile("mbarrier.arrive.expect_tx.shared.b64 _, [%0], %1;" :: "r"((u32)(mb)), "r"((u32)(bytes)) : "memory")
#define TMA_BULK(dst, src, bytes, mb) \
    asm volatile("cp.async.bulk.shared::cta.global.mbarrier::complete_tx::bytes [%0], [%1], %2, [%3];" \
                 :: "r"((u32)(dst)), "l"(src), "r"((u32)(bytes)), "r"((u32)(mb)) : "memory")
#define FENCE_ASYNC() asm volatile("fence.proxy.async.shared::cta;" ::: "memory")

#define MBAR_WAIT(mb, ph) do { \
    u32 _mb = (u32)(mb); u32 _p = (u32)(ph); u32 _done; \
    asm volatile("{ .reg .pred p; mbarrier.try_wait.parity.acquire.cta.shared::cta.b64 p, [%1], %2; selp.b32 %0, 1, 0, p; }" \
        : "=r"(_done) : "r"(_mb), "r"(_p) : "memory"); \
    if (!_done) { \
        asm volatile("{ .reg .pred P1;\n\t" \
            "WL_%=:\n\t" \
            "mbarrier.try_wait.parity.acquire.cta.shared::cta.b64 P1, [%0], %1, 0x989680;\n\t" \
            "@P1 bra.uni WD_%=;\n\t" \
            "bra.uni WL_%=;\n\t" \
            "WD_%=: }" :: "r"(_mb), "r"(_p) : "memory"); \
    } } while (0)

// ============ weight preconversion kernel (fp16 hi + fp16 residual) ============
__global__ void conv_weights_kernel(const float* __restrict__ Wh,
                                    const float* __restrict__ Wf)
{
    const int stride = gridDim.x * blockDim.x;
    const int t0 = blockIdx.x * blockDim.x + threadIdx.x;
    for (int i = t0; i < 14 * 16384; i += stride) {
        int layer = i >> 14;
        int j = layer >> 1, l = layer & 1;
        int r = (i >> 7) & 127, k = i & 127;
        float v = Wh[i];
        __half h = __float2half_rn(v);
        __half lo = __float2half_rn(v - __half2float(h));
        char* base = g_wbuf + j * JSTRIDE + l * BIGSZ;
        ((__half*)base)[r * 136 + k] = h;
        ((__half*)(base + BIGLO))[r * 136 + k] = lo;
    }
    for (int i = t0; i < 7 * 1536; i += stride) {
        int j = i / 1536;
        int rem = i - j * 1536;
        int r = rem >> 7, k = rem & 127;
        float v = Wf[i];
        __half h = __float2half_rn(v);
        __half lo = __float2half_rn(v - __half2float(h));
        char* base = g_wbuf + j * JSTRIDE + 2 * BIGSZ;
        ((__half*)base)[r * 136 + k] = h;
        ((__half*)(base + WFLO))[r * 136 + k] = lo;
    }
    for (int i = t0; i < 7 * 4 * 136; i += stride) {
        int j = i / 544;
        int rem = i - j * 544;
        int r = 12 + rem / 136, k = rem % 136;
        char* base = g_wbuf + j * JSTRIDE + 2 * BIGSZ;
        ((__half*)base)[r * 136 + k] = __float2half_rn(0.f);
        ((__half*)(base + WFLO))[r * 136 + k] = __float2half_rn(0.f);
    }
}

// ============ main kernel ============

// hidden layer: A <- relu(A @ (Whi+Wlo)^T + bias); warps 2m x 4n (64 x 128 output)
static __device__ void mma_hidden(u32 smb, char* sm, const float* __restrict__ bias,
                                  int lane, int wid)
{
    const int m_base = (wid >> 2) * 32;
    const int n_base = (wid & 3) * 32;
    float acc[2][4][4];
    #pragma unroll
    for (int mt = 0; mt < 2; ++mt)
        #pragma unroll
        for (int nt = 0; nt < 4; ++nt)
            #pragma unroll
            for (int e = 0; e < 4; ++e) acc[mt][nt][e] = 0.f;

    const int arow = lane & 15, acol = (lane >> 4) << 3;
    const int brow = (lane & 7) + ((lane & 16) >> 1);
    const int bcol = lane & 8;

    #pragma unroll
    for (int k = 0; k < 8; ++k) {
        int k0 = k * 16;
        uint4 af[2];
        #pragma unroll
        for (int mt = 0; mt < 2; ++mt) {
            u32 a = smb + SM_A + (u32)(m_base + mt * 16 + arow) * RSB + (u32)(k0 + acol) * 2;
            af[mt] = ldmx4(a);
        }
        #pragma unroll
        for (int np = 0; np < 2; ++np) {
            int n0 = n_base + np * 16;
            u32 b = smb + SM_W + (u32)(n0 + brow) * RSB + (u32)(k0 + bcol) * 2;
            uint4 bh = ldmx4(b);
            uint4 bl = ldmx4(b + BIGLO);
            #pragma unroll
            for (int mt = 0; mt < 2; ++mt) {
                mma_h(acc[mt][np*2+0], af[mt], bh.x, bh.y);
                mma_h(acc[mt][np*2+0], af[mt], bl.x, bl.y);
                mma_h(acc[mt][np*2+1], af[mt], bh.z, bh.w);
                mma_h(acc[mt][np*2+1], af[mt], bl.z, bl.w);
            }
        }
    }
    __syncthreads();   // all warps done reading A (and W) before overwrite
    #pragma unroll
    for (int mt = 0; mt < 2; ++mt) {
        #pragma unroll
        for (int nt = 0; nt < 4; ++nt) {
            int r = m_base + mt * 16 + (lane >> 2);
            int c = n_base + nt * 8 + 2 * (lane & 3);
            float b0v = __ldg(&bias[c]), b1v = __ldg(&bias[c + 1]);
            float v0 = fmaxf(acc[mt][nt][0] + b0v, 0.f);
            float v1 = fmaxf(acc[mt][nt][1] + b1v, 0.f);
            *(u32*)(sm + SM_A + r * RSB + c * 2) = packh(v0, v1);
            float v2 = fmaxf(acc[mt][nt][2] + b0v, 0.f);
            float v3 = fmaxf(acc[mt][nt][3] + b1v, 0.f);
            *(u32*)(sm + SM_A + (r + 8) * RSB + c * 2) = packh(v2, v3);
        }
    }
}

// final layer (warps 0-3 only): TOP[64][16] = A @ (Wfhi+Wflo)^T, overlaid on A rows.
// Each warp touches only its own m16 stripe -> no cross-warp hazard, no sync.
static __device__ void mma_final(u32 smb, char* sm, int lane, int wid)
{
    const int m_base = wid * 16;
    float acc[2][4] = {};
    const int arow = lane & 15, acol = (lane >> 4) << 3;
    const int brow = (lane & 7) + ((lane & 16) >> 1);
    const int bcol = lane & 8;
    #pragma unroll
    for (int k = 0; k < 8; ++k) {
        int k0 = k * 16;
        u32 a = smb + SM_A + (u32)(m_base + arow) * RSB + (u32)(k0 + acol) * 2;
        uint4 af = ldmx4(a);
        u32 b = smb + SM_WF + (u32)brow * RSB + (u32)(k0 + bcol) * 2;
        uint4 bh = ldmx4(b);
        uint4 bl = ldmx4(b + WFLO);
        mma_h(acc[0], af, bh.x, bh.y);
        mma_h(acc[0], af, bl.x, bl.y);
        mma_h(acc[1], af, bh.z, bh.w);
        mma_h(acc[1], af, bl.z, bl.w);
    }
    #pragma unroll
    for (int nt = 0; nt < 2; ++nt) {
        int r = m_base + (lane >> 2);
        int c = nt * 8 + 2 * (lane & 3);
        *(float2*)(sm + SM_A + r * RSB + TOPOFF + c * 4)       = make_float2(acc[nt][0], acc[nt][1]);
        *(float2*)(sm + SM_A + (r + 8) * RSB + TOPOFF + c * 4) = make_float2(acc[nt][2], acc[nt][3]);
    }
}

__global__ void __launch_bounds__(TPB, 2)
fkine_mma_kernel(const float* __restrict__ q,
                 const float* __restrict__ W0,
                 const float* __restrict__ b0,
                 const float* __restrict__ bh,
                 const float* __restrict__ bf,
                 float* __restrict__ out_y,
                 float* __restrict__ out_t)
{
    extern __shared__ char sm[];
    const u32 smb = smem_u32(sm);
    const int tid = threadIdx.x, lane = tid & 31, wid = tid >> 5;
    const int g0 = blockIdx.x * TILE_M;
    const u32 mbW = smb + SM_MBAR, mbF = smb + SM_MBAR + 8;
    const char* gw = g_wbuf;

    // per-thread cumulative transform (threads 0..63 own sample g0+tid)
    float Tc[16];
    #pragma unroll
    for (int e = 0; e < 16; ++e) Tc[e] = ((e >> 2) == (e & 3)) ? 1.f : 0.f;

    if (tid == 0) {
        MBAR_INIT(mbW, 1); MBAR_INIT(mbF, 1);
        FENCE_ASYNC();
        MBAR_EXPECT(mbW, BIGSZ); TMA_BULK(smb + SM_W, gw, BIGSZ, mbW);
    }
    __syncthreads();

    int phW = 0, phF = 0;

    for (int j = 0; j < NJ; ++j) {
        const char* gj = gw + (size_t)j * JSTRIDE;

        // ---- P0: issue WF(j); layer 0 (K=3, scalar fp32) -> A (fp16 hi)
        if (tid == 0) {
            MBAR_EXPECT(mbF, WFSZ); TMA_BULK(smb + SM_WF, gj + 2 * BIGSZ, WFSZ, mbF);
        }
        {
            int m = tid >> 2, qtr = tid & 3;
            float th = q[(size_t)(g0 + m) * NJ + j];
            float ct = cosf(th), st = sinf(th);
            const float* w0  = W0 + (size_t)j * 384;
            const float* b0j = b0 + (size_t)j * 128;
            int ob = qtr * 32;
            for (int o = ob; o < ob + 32; o += 2) {
                float h0 = fmaxf(fmaf(w0[o*3+0], th, fmaf(w0[o*3+1], ct, fmaf(w0[o*3+2], st, b0j[o]))),   0.f);
                float h1 = fmaxf(fmaf(w0[o*3+3], th, fmaf(w0[o*3+4], ct, fmaf(w0[o*3+5], st, b0j[o+1]))), 0.f);
                *(u32*)(sm + SM_A + m * RSB + o * 2) = packh(h0, h1);
            }
        }
        __syncthreads();

        // ---- P1: hidden layer 1 (uses W = W1(j))
        MBAR_WAIT(mbW, phW); phW ^= 1;
        mma_hidden(smb, sm, bh + (size_t)(j * 2) * 128, lane, wid);
        __syncthreads();           // new A visible; W reads complete

        // ---- P2: refill W with W2(j) (hidden by co-resident CTA), then layer 2
        if (tid == 0) {
            MBAR_EXPECT(mbW, BIGSZ); TMA_BULK(smb + SM_W, gj + BIGSZ, BIGSZ, mbW);
        }
        MBAR_WAIT(mbW, phW); phW ^= 1;
        mma_hidden(smb, sm, bh + (size_t)(j * 2 + 1) * 128, lane, wid);
        __syncthreads();

        // ---- P3: refill W with W1(j+1); final layer (warps 0-3, uses WF)
        if (tid == 0 && j < NJ - 1) {
            MBAR_EXPECT(mbW, BIGSZ); TMA_BULK(smb + SM_W, gj + JSTRIDE, BIGSZ, mbW);
        }
        MBAR_WAIT(mbF, phF); phF ^= 1;
        if (wid < 4) mma_final(smb, sm, lane, wid);
        __syncthreads();

        // ---- P4: chain epilogue (threads 0..63, Tcum in registers)
        if (tid < TILE_M) {
            int m = tid;
            float Tl[12], Tn[16];
            #pragma unroll
            for (int i = 0; i < 12; ++i)
                Tl[i] = *(float*)(sm + SM_A + m * RSB + TOPOFF + i * 4) + __ldg(&bf[j * 12 + i]);
            #pragma unroll
            for (int i = 0; i < 3; ++i)
                #pragma unroll
                for (int c = 0; c < 4; ++c)
                    Tn[i*4+c] = Tl[i*4+0]*Tc[0+c] + Tl[i*4+1]*Tc[4+c]
                              + Tl[i*4+2]*Tc[8+c] + Tl[i*4+3]*Tc[12+c];
            #pragma unroll
            for (int c = 0; c < 4; ++c) Tn[12+c] = Tc[12+c];

            float4* tp = (float4*)(out_t + (size_t)(g0 + m) * 112 + j * 16);
            tp[0] = make_float4(Tl[0], Tl[1], Tl[2],  Tl[3]);
            tp[1] = make_float4(Tl[4], Tl[5], Tl[6],  Tl[7]);
            tp[2] = make_float4(Tl[8], Tl[9], Tl[10], Tl[11]);
            tp[3] = make_float4(0.f, 0.f, 0.f, 1.f);

            size_t yb = (size_t)(g0 + m) * 21 + j;
            out_y[yb]      = Tn[3];
            out_y[yb + 7]  = Tn[7];
            out_y[yb + 14] = Tn[11];

            #pragma unroll
            for (int i = 0; i < 16; ++i) Tc[i] = Tn[i];
        }
        __syncthreads();
    }
}

extern "C" void kernel_launch(void* const* d_in, const int* in_sizes, int n_in,
                              void* d_out, int out_size)
{
    const float* q  = (const float*)d_in[0];
    const float* W0 = (const float*)d_in[1];
    const float* b0 = (const float*)d_in[2];
    const float* Wh = (const float*)d_in[3];
    const float* bh = (const float*)d_in[4];
    const float* Wf = (const float*)d_in[5];
    const float* bf = (const float*)d_in[6];

    const int N = in_sizes[0] / NJ;           // q is [N, 7]
    float* out_y = (float*)d_out;             // [N, 3, 7]
    float* out_t = out_y + (size_t)N * 21;    // [N, 7, 4, 4]

    conv_weights_kernel<<<128, 256>>>(Wh, Wf);

    cudaFuncSetAttribute(fkine_mma_kernel,
                         cudaFuncAttributeMaxDynamicSharedMemorySize, SM_TOTAL);
    fkine_mma_kernel<<<N / TILE_M, TPB, SM_TOTAL>>>(q, W0, b0, bh, bf, out_y, out_t);
}

// round 12
// speedup vs baseline: 3.8512x; 1.1463x over previous
#include <cuda_runtime.h>
#include <cuda_fp16.h>
#include <cstdint>
#include <math.h>

typedef uint32_t u32;

#define TPB    128
#define NJ     7
#define RSB    272          // bytes per f16 tile row (136 halves)
#define TILE_M 64

// ---- smem byte offsets ----
#define SM_A      0              // activations, fp16: 64*272 = 17408
#define SM_W      17408          // hidden W hi+lo (hi at +0, lo at +34816): 69632
#define SM_WF     87040          // Wf hi+lo (hi at +0, lo at +4352): 8704
#define SM_MBAR   95744          // 2 mbarriers
#define SM_TOTAL  95760
#define BIGLO     34816
#define WFLO      4352
#define TOPOFF    192            // TOP overlay: SM_A + r*RSB + TOPOFF (16 f32)

// ---- preconverted fp16 weight images in global ----
#define BIGSZ   69632
#define WFSZ    8704
#define JSTRIDE (2*BIGSZ + WFSZ) // [W1hi W1lo W2hi W2lo Wfhi Wflo]
__device__ __align__(16) char g_wbuf[NJ * JSTRIDE];

static __device__ __forceinline__ u32 smem_u32(const void* p) {
    u32 a;
    asm("{ .reg .u64 t; cvta.to.shared.u64 t, %1; cvt.u32.u64 %0, t; }" : "=r"(a) : "l"(p));
    return a;
}
static __device__ __forceinline__ u32 packh(float x0, float x1) {
    u32 r;
    asm("cvt.rn.f16x2.f32 %0, %1, %2;" : "=r"(r) : "f"(x1), "f"(x0));
    return r;
}
static __device__ __forceinline__ uint4 ldmx4(u32 addr) {
    uint4 r;
    asm volatile("ldmatrix.sync.aligned.m8n8.x4.shared.b16 {%0,%1,%2,%3}, [%4];"
                 : "=r"(r.x), "=r"(r.y), "=r"(r.z), "=r"(r.w) : "r"(addr));
    return r;
}
static __device__ __forceinline__ void mma_h(float d[4], const uint4& a, u32 b0, u32 b1) {
    asm volatile("mma.sync.aligned.m16n8k16.row.col.f32.f16.f16.f32 "
                 "{%0,%1,%2,%3},{%4,%5,%6,%7},{%8,%9},{%0,%1,%2,%3};"
                 : "+f"(d[0]), "+f"(d[1]), "+f"(d[2]), "+f"(d[3])
                 : "r"(a.x), "r"(a.y), "r"(a.z), "r"(a.w), "r"(b0), "r"(b1));
}

// ---- TMA bulk copy + mbarrier machinery ----
#define MBAR_INIT(mb, c)  asm volatile("mbarrier.init.shared.b64 [%0], %1;" :: "r"((u32)(mb)), "r"((u32)(c)) : "memory")
#define MBAR_EXPECT(mb, bytes) \
    asm volatile("mbarrier.arrive.expect_tx.shared.b64 _, [%0], %1;" :: "r"((u32)(mb)), "r"((u32)(bytes)) : "memory")
#define TMA_BULK(dst, src, bytes, mb) \
    asm volatile("cp.async.bulk.shared::cta.global.mbarrier::complete_tx::bytes [%0], [%1], %2, [%3];" \
                 :: "r"((u32)(dst)), "l"(src), "r"((u32)(bytes)), "r"((u32)(mb)) : "memory")
#define FENCE_ASYNC() asm volatile("fence.proxy.async.shared::cta;" ::: "memory")

#define MBAR_WAIT(mb, ph) do { \
    u32 _mb = (u32)(mb); u32 _p = (u32)(ph); u32 _done; \
    asm volatile("{ .reg .pred p; mbarrier.try_wait.parity.acquire.cta.shared::cta.b64 p, [%1], %2; selp.b32 %0, 1, 0, p; }" \
        : "=r"(_done) : "r"(_mb), "r"(_p) : "memory"); \
    if (!_done) { \
        asm volatile("{ .reg .pred P1;\n\t" \
            "WL_%=:\n\t" \
            "mbarrier.try_wait.parity.acquire.cta.shared::cta.b64 P1, [%0], %1, 0x989680;\n\t" \
            "@P1 bra.uni WD_%=;\n\t" \
            "bra.uni WL_%=;\n\t" \
            "WD_%=: }" :: "r"(_mb), "r"(_p) : "memory"); \
    } } while (0)

// ============ weight preconversion kernel (fp16 hi + fp16 residual) ============
__global__ void conv_weights_kernel(const float* __restrict__ Wh,
                                    const float* __restrict__ Wf)
{
    const int stride = gridDim.x * blockDim.x;
    const int t0 = blockIdx.x * blockDim.x + threadIdx.x;
    for (int i = t0; i < 14 * 16384; i += stride) {
        int layer = i >> 14;
        int j = layer >> 1, l = layer & 1;
        int r = (i >> 7) & 127, k = i & 127;
        float v = Wh[i];
        __half h = __float2half_rn(v);
        __half lo = __float2half_rn(v - __half2float(h));
        char* base = g_wbuf + j * JSTRIDE + l * BIGSZ;
        ((__half*)base)[r * 136 + k] = h;
        ((__half*)(base + BIGLO))[r * 136 + k] = lo;
    }
    for (int i = t0; i < 7 * 1536; i += stride) {
        int j = i / 1536;
        int rem = i - j * 1536;
        int r = rem >> 7, k = rem & 127;
        float v = Wf[i];
        __half h = __float2half_rn(v);
        __half lo = __float2half_rn(v - __half2float(h));
        char* base = g_wbuf + j * JSTRIDE + 2 * BIGSZ;
        ((__half*)base)[r * 136 + k] = h;
        ((__half*)(base + WFLO))[r * 136 + k] = lo;
    }
    for (int i = t0; i < 7 * 4 * 136; i += stride) {
        int j = i / 544;
        int rem = i - j * 544;
        int r = 12 + rem / 136, k = rem % 136;
        char* base = g_wbuf + j * JSTRIDE + 2 * BIGSZ;
        ((__half*)base)[r * 136 + k] = __float2half_rn(0.f);
        ((__half*)(base + WFLO))[r * 136 + k] = __float2half_rn(0.f);
    }
}

// ============ main kernel ============

// hidden layer: A <- relu(A @ (Whi+Wlo)^T + bias).
// 4 warps, each owns FULL m64 (4 m16 tiles in registers) x its n32 slice:
// B fragments amortized over 4 m-tiles -> minimal total ldmatrix traffic.
static __device__ void mma_hidden(u32 smb, char* sm, const float* __restrict__ bias,
                                  int lane, int wid)
{
    const int n_base = wid * 32;
    float acc[4][4][4];   // [mt][nt over n8][frag]
    #pragma unroll
    for (int mt = 0; mt < 4; ++mt)
        #pragma unroll
        for (int nt = 0; nt < 4; ++nt)
            #pragma unroll
            for (int e = 0; e < 4; ++e) acc[mt][nt][e] = 0.f;

    const int arow = lane & 15, acol = (lane >> 4) << 3;
    const int brow = (lane & 7) + ((lane & 16) >> 1);
    const int bcol = lane & 8;

    #pragma unroll
    for (int k = 0; k < 8; ++k) {
        int k0 = k * 16;
        uint4 af[4];
        #pragma unroll
        for (int mt = 0; mt < 4; ++mt) {
            u32 a = smb + SM_A + (u32)(mt * 16 + arow) * RSB + (u32)(k0 + acol) * 2;
            af[mt] = ldmx4(a);
        }
        #pragma unroll
        for (int np = 0; np < 2; ++np) {
            int n0 = n_base + np * 16;
            u32 b = smb + SM_W + (u32)(n0 + brow) * RSB + (u32)(k0 + bcol) * 2;
            uint4 bh = ldmx4(b);
            uint4 bl = ldmx4(b + BIGLO);
            #pragma unroll
            for (int mt = 0; mt < 4; ++mt) {
                mma_h(acc[mt][np*2+0], af[mt], bh.x, bh.y);
                mma_h(acc[mt][np*2+0], af[mt], bl.x, bl.y);
                mma_h(acc[mt][np*2+1], af[mt], bh.z, bh.w);
                mma_h(acc[mt][np*2+1], af[mt], bl.z, bl.w);
            }
        }
    }
    __syncthreads();   // all warps done reading A (and W) before overwrite
    #pragma unroll
    for (int mt = 0; mt < 4; ++mt) {
        #pragma unroll
        for (int nt = 0; nt < 4; ++nt) {
            int r = mt * 16 + (lane >> 2);
            int c = n_base + nt * 8 + 2 * (lane & 3);
            float b0v = __ldg(&bias[c]), b1v = __ldg(&bias[c + 1]);
            float v0 = fmaxf(acc[mt][nt][0] + b0v, 0.f);
            float v1 = fmaxf(acc[mt][nt][1] + b1v, 0.f);
            *(u32*)(sm + SM_A + r * RSB + c * 2) = packh(v0, v1);
            float v2 = fmaxf(acc[mt][nt][2] + b0v, 0.f);
            float v3 = fmaxf(acc[mt][nt][3] + b1v, 0.f);
            *(u32*)(sm + SM_A + (r + 8) * RSB + c * 2) = packh(v2, v3);
        }
    }
}

// final layer: TOP[64][16] = A @ (Wfhi+Wflo)^T, overlaid on A rows.
// Each of the 4 warps owns its own m16 stripe -> no cross-warp hazard.
static __device__ void mma_final(u32 smb, char* sm, int lane, int wid)
{
    const int m_base = wid * 16;
    float acc[2][4] = {};
    const int arow = lane & 15, acol = (lane >> 4) << 3;
    const int brow = (lane & 7) + ((lane & 16) >> 1);
    const int bcol = lane & 8;
    #pragma unroll
    for (int k = 0; k < 8; ++k) {
        int k0 = k * 16;
        u32 a = smb + SM_A + (u32)(m_base + arow) * RSB + (u32)(k0 + acol) * 2;
        uint4 af = ldmx4(a);
        u32 b = smb + SM_WF + (u32)brow * RSB + (u32)(k0 + bcol) * 2;
        uint4 bh = ldmx4(b);
        uint4 bl = ldmx4(b + WFLO);
        mma_h(acc[0], af, bh.x, bh.y);
        mma_h(acc[0], af, bl.x, bl.y);
        mma_h(acc[1], af, bh.z, bh.w);
        mma_h(acc[1], af, bl.z, bl.w);
    }
    #pragma unroll
    for (int nt = 0; nt < 2; ++nt) {
        int r = m_base + (lane >> 2);
        int c = nt * 8 + 2 * (lane & 3);
        *(float2*)(sm + SM_A + r * RSB + TOPOFF + c * 4)       = make_float2(acc[nt][0], acc[nt][1]);
        *(float2*)(sm + SM_A + (r + 8) * RSB + TOPOFF + c * 4) = make_float2(acc[nt][2], acc[nt][3]);
    }
}

__global__ void __launch_bounds__(TPB, 2)
fkine_mma_kernel(const float* __restrict__ q,
                 const float* __restrict__ W0,
                 const float* __restrict__ b0,
                 const float* __restrict__ bh,
                 const float* __restrict__ bf,
                 float* __restrict__ out_y,
                 float* __restrict__ out_t)
{
    extern __shared__ char sm[];
    const u32 smb = smem_u32(sm);
    const int tid = threadIdx.x, lane = tid & 31, wid = tid >> 5;
    const int g0 = blockIdx.x * TILE_M;
    const u32 mbW = smb + SM_MBAR, mbF = smb + SM_MBAR + 8;
    const char* gw = g_wbuf;

    // per-thread cumulative transform (threads 0..63 own sample g0+tid)
    float Tc[16];
    #pragma unroll
    for (int e = 0; e < 16; ++e) Tc[e] = ((e >> 2) == (e & 3)) ? 1.f : 0.f;

    if (tid == 0) {
        MBAR_INIT(mbW, 1); MBAR_INIT(mbF, 1);
        FENCE_ASYNC();
        MBAR_EXPECT(mbW, BIGSZ); TMA_BULK(smb + SM_W, gw, BIGSZ, mbW);
    }
    __syncthreads();

    int phW = 0, phF = 0;

    for (int j = 0; j < NJ; ++j) {
        const char* gj = gw + (size_t)j * JSTRIDE;

        // ---- P0: issue WF(j); layer 0 (K=3, scalar fp32) -> A (fp16)
        if (tid == 0) {
            MBAR_EXPECT(mbF, WFSZ); TMA_BULK(smb + SM_WF, gj + 2 * BIGSZ, WFSZ, mbF);
        }
        {
            int m = tid >> 1, half = tid & 1;
            float th = q[(size_t)(g0 + m) * NJ + j];
            float ct = cosf(th), st = sinf(th);
            const float* w0  = W0 + (size_t)j * 384;
            const float* b0j = b0 + (size_t)j * 128;
            int ob = half * 64;
            for (int o = ob; o < ob + 64; o += 2) {
                float h0 = fmaxf(fmaf(w0[o*3+0], th, fmaf(w0[o*3+1], ct, fmaf(w0[o*3+2], st, b0j[o]))),   0.f);
                float h1 = fmaxf(fmaf(w0[o*3+3], th, fmaf(w0[o*3+4], ct, fmaf(w0[o*3+5], st, b0j[o+1]))), 0.f);
                *(u32*)(sm + SM_A + m * RSB + o * 2) = packh(h0, h1);
            }
        }
        __syncthreads();

        // ---- P1: hidden layer 1 (uses W = W1(j))
        MBAR_WAIT(mbW, phW); phW ^= 1;
        mma_hidden(smb, sm, bh + (size_t)(j * 2) * 128, lane, wid);
        __syncthreads();           // new A visible; W reads complete

        // ---- P2: refill W with W2(j) (hidden by co-resident CTA), then layer 2
        if (tid == 0) {
            MBAR_EXPECT(mbW, BIGSZ); TMA_BULK(smb + SM_W, gj + BIGSZ, BIGSZ, mbW);
        }
        MBAR_WAIT(mbW, phW); phW ^= 1;
        mma_hidden(smb, sm, bh + (size_t)(j * 2 + 1) * 128, lane, wid);
        __syncthreads();

        // ---- P3: refill W with W1(j+1); final layer (uses WF)
        if (tid == 0 && j < NJ - 1) {
            MBAR_EXPECT(mbW, BIGSZ); TMA_BULK(smb + SM_W, gj + JSTRIDE, BIGSZ, mbW);
        }
        MBAR_WAIT(mbF, phF); phF ^= 1;
        mma_final(smb, sm, lane, wid);
        __syncthreads();

        // ---- P4: chain epilogue (threads 0..63, Tcum in registers)
        if (tid < TILE_M) {
            int m = tid;
            float Tl[12], Tn[16];
            #pragma unroll
            for (int i = 0; i < 12; ++i)
                Tl[i] = *(float*)(sm + SM_A + m * RSB + TOPOFF + i * 4) + __ldg(&bf[j * 12 + i]);
            #pragma unroll
            for (int i = 0; i < 3; ++i)
                #pragma unroll
                for (int c = 0; c < 4; ++c)
                    Tn[i*4+c] = Tl[i*4+0]*Tc[0+c] + Tl[i*4+1]*Tc[4+c]
                              + Tl[i*4+2]*Tc[8+c] + Tl[i*4+3]*Tc[12+c];
            #pragma unroll
            for (int c = 0; c < 4; ++c) Tn[12+c] = Tc[12+c];

            float4* tp = (float4*)(out_t + (size_t)(g0 + m) * 112 + j * 16);
            tp[0] = make_float4(Tl[0], Tl[1], Tl[2],  Tl[3]);
            tp[1] = make_float4(Tl[4], Tl[5], Tl[6],  Tl[7]);
            tp[2] = make_float4(Tl[8], Tl[9], Tl[10], Tl[11]);
            tp[3] = make_float4(0.f, 0.f, 0.f, 1.f);

            size_t yb = (size_t)(g0 + m) * 21 + j;
            out_y[yb]      = Tn[3];
            out_y[yb + 7]  = Tn[7];
            out_y[yb + 14] = Tn[11];

            #pragma unroll
            for (int i = 0; i < 16; ++i) Tc[i] = Tn[i];
        }
        __syncthreads();
    }
}

extern "C" void kernel_launch(void* const* d_in, const int* in_sizes, int n_in,
                              void* d_out, int out_size)
{
    const float* q  = (const float*)d_in[0];
    const float* W0 = (const float*)d_in[1];
    const float* b0 = (const float*)d_in[2];
    const float* Wh = (const float*)d_in[3];
    const float* bh = (const float*)d_in[4];
    const float* Wf = (const float*)d_in[5];
    const float* bf = (const float*)d_in[6];

    const int N = in_sizes[0] / NJ;           // q is [N, 7]
    float* out_y = (float*)d_out;             // [N, 3, 7]
    float* out_t = out_y + (size_t)N * 21;    // [N, 7, 4, 4]

    conv_weights_kernel<<<128, 256>>>(Wh, Wf);

    cudaFuncSetAttribute(fkine_mma_kernel,
                         cudaFuncAttributeMaxDynamicSharedMemorySize, SM_TOTAL);
    fkine_mma_kernel<<<N / TILE_M, TPB, SM_TOTAL>>>(q, W0, b0, bh, bf, out_y, out_t);
}

// round 13
// speedup vs baseline: 4.7559x; 1.2349x over previous
#include <cuda_runtime.h>
#include <cuda_fp16.h>
#include <cstdint>
#include <math.h>

typedef uint32_t u32;

#define TPB    128
#define NJ     7
#define RSB    272          // bytes per f16 tile row (136 halves)
#define TILE_M 64

// ---- smem: A tile only ----
#define SM_A      0              // 64*272 = 17408
#define SM_TOTAL  17408
#define TOPOFF    192            // TOP overlay: SM_A + r*RSB + TOPOFF (16 f32)

// ---- fragment-layout weight images in global ----
// hidden layer image: [kt(8)][ntile(8)][h(2)][lane(32)] x 16B  = 65536 B
// final  layer image: [kt(8)][h(2)][lane(32)] x 16B            = 8192 B
#define HIMG    65536
#define FIMG    8192
#define JSTRIDE (2*HIMG + FIMG)  // [W1frag W2frag Wffrag] per joint
__device__ __align__(16) char g_wbuf[NJ * JSTRIDE];

static __device__ __forceinline__ u32 smem_u32(const void* p) {
    u32 a;
    asm("{ .reg .u64 t; cvta.to.shared.u64 t, %1; cvt.u32.u64 %0, t; }" : "=r"(a) : "l"(p));
    return a;
}
static __device__ __forceinline__ u32 packh(float x0, float x1) {
    u32 r;
    asm("cvt.rn.f16x2.f32 %0, %1, %2;" : "=r"(r) : "f"(x1), "f"(x0));
    return r;
}
static __device__ __forceinline__ uint4 ldmx4(u32 addr) {
    uint4 r;
    asm volatile("ldmatrix.sync.aligned.m8n8.x4.shared.b16 {%0,%1,%2,%3}, [%4];"
                 : "=r"(r.x), "=r"(r.y), "=r"(r.z), "=r"(r.w) : "r"(addr));
    return r;
}
static __device__ __forceinline__ void mma_h(float d[4], const uint4& a, u32 b0, u32 b1) {
    asm volatile("mma.sync.aligned.m16n8k16.row.col.f32.f16.f16.f32 "
                 "{%0,%1,%2,%3},{%4,%5,%6,%7},{%8,%9},{%0,%1,%2,%3};"
                 : "+f"(d[0]), "+f"(d[1]), "+f"(d[2]), "+f"(d[3])
                 : "r"(a.x), "r"(a.y), "r"(a.z), "r"(a.w), "r"(b0), "r"(b1));
}

// ============ weight preconversion: fp32 -> fp16 hi/lo fragment images ============
__global__ void conv_weights_kernel(const float* __restrict__ Wh,
                                    const float* __restrict__ Wf)
{
    const int stride = gridDim.x * blockDim.x;
    const int t0 = blockIdx.x * blockDim.x + threadIdx.x;

    // hidden layers: 14 x 16384 u32 fragment words
    for (int i = t0; i < 14 * 16384; i += stride) {
        int layer = i >> 14;
        int w = i & 16383;
        int e = w & 3, lane = (w >> 2) & 31, h = (w >> 7) & 1;
        int nt = (w >> 8) & 7, kt = (w >> 11) & 7;
        int tg = lane >> 2, tl = lane & 3;
        int n = nt * 16 + tg + ((e >> 1) ? 8 : 0);
        int k = kt * 16 + 2 * tl + ((e & 1) ? 8 : 0);
        const float* Wsrc = Wh + (size_t)layer * 16384;
        float v0 = Wsrc[n * 128 + k], v1 = Wsrc[n * 128 + k + 1];
        u32 out;
        if (h == 0) {
            out = packh(__half2float(__float2half_rn(v0)) * 0.f + __half2float(__float2half_rn(v0)),
                        __half2float(__float2half_rn(v1)));
            out = packh(__half2float(__float2half_rn(v0)), __half2float(__float2half_rn(v1)));
        } else {
            float r0 = v0 - __half2float(__float2half_rn(v0));
            float r1 = v1 - __half2float(__float2half_rn(v1));
            out = packh(r0, r1);
        }
        int j = layer >> 1, l = layer & 1;
        u32* img = (u32*)(g_wbuf + (size_t)j * JSTRIDE + l * HIMG);
        img[w] = out;
    }

    // final layers: 7 x 2048 u32 fragment words (rows 12..15 zero)
    for (int i = t0; i < 7 * 2048; i += stride) {
        int j = i >> 11;
        int w = i & 2047;
        int e = w & 3, lane = (w >> 2) & 31, h = (w >> 7) & 1, kt = (w >> 8) & 7;
        int tg = lane >> 2, tl = lane & 3;
        int n = tg + ((e >> 1) ? 8 : 0);
        int k = kt * 16 + 2 * tl + ((e & 1) ? 8 : 0);
        u32 out = 0;
        if (n < 12) {
            const float* Wsrc = Wf + (size_t)j * 1536;
            float v0 = Wsrc[n * 128 + k], v1 = Wsrc[n * 128 + k + 1];
            if (h == 0) {
                out = packh(__half2float(__float2half_rn(v0)), __half2float(__float2half_rn(v1)));
            } else {
                float r0 = v0 - __half2float(__float2half_rn(v0));
                float r1 = v1 - __half2float(__float2half_rn(v1));
                out = packh(r0, r1);
            }
        }
        u32* img = (u32*)(g_wbuf + (size_t)j * JSTRIDE + 2 * HIMG);
        img[w] = out;
    }
}

// ============ main kernel ============

// hidden layer: A <- relu(A @ (Whi+Wlo)^T + bias).
// 4 warps; each owns full m64 x its n32 slice. B fragments via LDG.128 from L2
// (fragment-layout image), 1-deep register prefetch across the kt loop.
static __device__ void mma_hidden(u32 smb, char* sm, const char* __restrict__ wimg,
                                  const float* __restrict__ bias, int lane, int wid)
{
    const int n_base = wid * 32;
    const uint4* wf = (const uint4*)wimg;
    float acc[4][4][4];
    #pragma unroll
    for (int mt = 0; mt < 4; ++mt)
        #pragma unroll
        for (int nt = 0; nt < 4; ++nt)
            #pragma unroll
            for (int e = 0; e < 4; ++e) acc[mt][nt][e] = 0.f;

    const int arow = lane & 15, acol = (lane >> 4) << 3;
    const int nt0 = 2 * wid;   // first of this warp's two n16 tiles

    uint4 bcur[4], bnxt[4];
    #pragma unroll
    for (int i = 0; i < 4; ++i)
        bcur[i] = __ldg(&wf[(((0 * 8 + nt0 + (i >> 1)) * 2 + (i & 1)) * 32) + lane]);

    #pragma unroll
    for (int kt = 0; kt < 8; ++kt) {
        if (kt < 7) {
            #pragma unroll
            for (int i = 0; i < 4; ++i)
                bnxt[i] = __ldg(&wf[((((kt + 1) * 8 + nt0 + (i >> 1)) * 2 + (i & 1)) * 32) + lane]);
        }
        int k0 = kt * 16;
        uint4 af[4];
        #pragma unroll
        for (int mt = 0; mt < 4; ++mt) {
            u32 a = smb + SM_A + (u32)(mt * 16 + arow) * RSB + (u32)(k0 + acol) * 2;
            af[mt] = ldmx4(a);
        }
        #pragma unroll
        for (int np = 0; np < 2; ++np) {
            uint4 bh = bcur[np * 2 + 0];
            uint4 bl = bcur[np * 2 + 1];
            #pragma unroll
            for (int mt = 0; mt < 4; ++mt) {
                mma_h(acc[mt][np*2+0], af[mt], bh.x, bh.y);
                mma_h(acc[mt][np*2+0], af[mt], bl.x, bl.y);
                mma_h(acc[mt][np*2+1], af[mt], bh.z, bh.w);
                mma_h(acc[mt][np*2+1], af[mt], bl.z, bl.w);
            }
        }
        #pragma unroll
        for (int i = 0; i < 4; ++i) bcur[i] = bnxt[i];
    }
    __syncthreads();   // all warps done reading A before overwrite
    #pragma unroll
    for (int mt = 0; mt < 4; ++mt) {
        #pragma unroll
        for (int nt = 0; nt < 4; ++nt) {
            int r = mt * 16 + (lane >> 2);
            int c = n_base + nt * 8 + 2 * (lane & 3);
            float b0v = __ldg(&bias[c]), b1v = __ldg(&bias[c + 1]);
            float v0 = fmaxf(acc[mt][nt][0] + b0v, 0.f);
            float v1 = fmaxf(acc[mt][nt][1] + b1v, 0.f);
            *(u32*)(sm + SM_A + r * RSB + c * 2) = packh(v0, v1);
            float v2 = fmaxf(acc[mt][nt][2] + b0v, 0.f);
            float v3 = fmaxf(acc[mt][nt][3] + b1v, 0.f);
            *(u32*)(sm + SM_A + (r + 8) * RSB + c * 2) = packh(v2, v3);
        }
    }
}

// final layer: TOP[64][16] = A @ (Wfhi+Wflo)^T, overlaid on A rows.
// Each of the 4 warps owns its m16 stripe -> warp-private, no sync needed.
static __device__ void mma_final(u32 smb, char* sm, const char* __restrict__ fimg,
                                 int lane, int wid)
{
    const int m_base = wid * 16;
    const uint4* wf = (const uint4*)fimg;
    float acc[2][4] = {};
    const int arow = lane & 15, acol = (lane >> 4) << 3;

    uint4 bcur[2], bnxt[2];
    bcur[0] = __ldg(&wf[(0 * 2 + 0) * 32 + lane]);
    bcur[1] = __ldg(&wf[(0 * 2 + 1) * 32 + lane]);

    #pragma unroll
    for (int kt = 0; kt < 8; ++kt) {
        if (kt < 7) {
            bnxt[0] = __ldg(&wf[((kt + 1) * 2 + 0) * 32 + lane]);
            bnxt[1] = __ldg(&wf[((kt + 1) * 2 + 1) * 32 + lane]);
        }
        int k0 = kt * 16;
        u32 a = smb + SM_A + (u32)(m_base + arow) * RSB + (u32)(k0 + acol) * 2;
        uint4 af = ldmx4(a);
        uint4 bh = bcur[0], bl = bcur[1];
        mma_h(acc[0], af, bh.x, bh.y);
        mma_h(acc[0], af, bl.x, bl.y);
        mma_h(acc[1], af, bh.z, bh.w);
        mma_h(acc[1], af, bl.z, bl.w);
        bcur[0] = bnxt[0]; bcur[1] = bnxt[1];
    }
    #pragma unroll
    for (int nt = 0; nt < 2; ++nt) {
        int r = m_base + (lane >> 2);
        int c = nt * 8 + 2 * (lane & 3);
        *(float2*)(sm + SM_A + r * RSB + TOPOFF + c * 4)       = make_float2(acc[nt][0], acc[nt][1]);
        *(float2*)(sm + SM_A + (r + 8) * RSB + TOPOFF + c * 4) = make_float2(acc[nt][2], acc[nt][3]);
    }
}

__global__ void __launch_bounds__(TPB, 4)
fkine_mma_kernel(const float* __restrict__ q,
                 const float* __restrict__ W0,
                 const float* __restrict__ b0,
                 const float* __restrict__ bh,
                 const float* __restrict__ bf,
                 float* __restrict__ out_y,
                 float* __restrict__ out_t)
{
    extern __shared__ char sm[];
    const u32 smb = smem_u32(sm);
    const int tid = threadIdx.x, lane = tid & 31, wid = tid >> 5;
    const int g0 = blockIdx.x * TILE_M;
    const char* gw = g_wbuf;

    // per-thread cumulative transform (threads 0..63 own sample g0+tid)
    float Tc[16];
    #pragma unroll
    for (int e = 0; e < 16; ++e) Tc[e] = ((e >> 2) == (e & 3)) ? 1.f : 0.f;

    for (int j = 0; j < NJ; ++j) {
        const char* gj = gw + (size_t)j * JSTRIDE;

        // ---- P0: layer 0 (K=3, scalar fp32) -> A (fp16)
        {
            int m = tid >> 1, half = tid & 1;
            float th = q[(size_t)(g0 + m) * NJ + j];
            float ct = cosf(th), st = sinf(th);
            const float* w0  = W0 + (size_t)j * 384;
            const float* b0j = b0 + (size_t)j * 128;
            int ob = half * 64;
            for (int o = ob; o < ob + 64; o += 2) {
                float h0 = fmaxf(fmaf(w0[o*3+0], th, fmaf(w0[o*3+1], ct, fmaf(w0[o*3+2], st, b0j[o]))),   0.f);
                float h1 = fmaxf(fmaf(w0[o*3+3], th, fmaf(w0[o*3+4], ct, fmaf(w0[o*3+5], st, b0j[o+1]))), 0.f);
                *(u32*)(sm + SM_A + m * RSB + o * 2) = packh(h0, h1);
            }
        }
        __syncthreads();

        // ---- P1: hidden layer 1
        mma_hidden(smb, sm, gj, bh + (size_t)(j * 2) * 128, lane, wid);
        __syncthreads();

        // ---- P2: hidden layer 2
        mma_hidden(smb, sm, gj + HIMG, bh + (size_t)(j * 2 + 1) * 128, lane, wid);
        __syncthreads();

        // ---- P3: final layer
        mma_final(smb, sm, gj + 2 * HIMG, lane, wid);
        __syncthreads();

        // ---- P4: chain epilogue (threads 0..63, Tcum in registers)
        if (tid < TILE_M) {
            int m = tid;
            float Tl[12], Tn[16];
            #pragma unroll
            for (int i = 0; i < 12; ++i)
                Tl[i] = *(float*)(sm + SM_A + m * RSB + TOPOFF + i * 4) + __ldg(&bf[j * 12 + i]);
            #pragma unroll
            for (int i = 0; i < 3; ++i)
                #pragma unroll
                for (int c = 0; c < 4; ++c)
                    Tn[i*4+c] = Tl[i*4+0]*Tc[0+c] + Tl[i*4+1]*Tc[4+c]
                              + Tl[i*4+2]*Tc[8+c] + Tl[i*4+3]*Tc[12+c];
            #pragma unroll
            for (int c = 0; c < 4; ++c) Tn[12+c] = Tc[12+c];

            float4* tp = (float4*)(out_t + (size_t)(g0 + m) * 112 + j * 16);
            tp[0] = make_float4(Tl[0], Tl[1], Tl[2],  Tl[3]);
            tp[1] = make_float4(Tl[4], Tl[5], Tl[6],  Tl[7]);
            tp[2] = make_float4(Tl[8], Tl[9], Tl[10], Tl[11]);
            tp[3] = make_float4(0.f, 0.f, 0.f, 1.f);

            size_t yb = (size_t)(g0 + m) * 21 + j;
            out_y[yb]      = Tn[3];
            out_y[yb + 7]  = Tn[7];
            out_y[yb + 14] = Tn[11];

            #pragma unroll
            for (int i = 0; i < 16; ++i) Tc[i] = Tn[i];
        }
        __syncthreads();
    }
}

extern "C" void kernel_launch(void* const* d_in, const int* in_sizes, int n_in,
                              void* d_out, int out_size)
{
    const float* q  = (const float*)d_in[0];
    const float* W0 = (const float*)d_in[1];
    const float* b0 = (const float*)d_in[2];
    const float* Wh = (const float*)d_in[3];
    const float* bh = (const float*)d_in[4];
    const float* Wf = (const float*)d_in[5];
    const float* bf = (const float*)d_in[6];

    const int N = in_sizes[0] / NJ;           // q is [N, 7]
    float* out_y = (float*)d_out;             // [N, 3, 7]
    float* out_t = out_y + (size_t)N * 21;    // [N, 7, 4, 4]

    conv_weights_kernel<<<128, 256>>>(Wh, Wf);

    cudaFuncSetAttribute(fkine_mma_kernel,
                         cudaFuncAttributeMaxDynamicSharedMemorySize, SM_TOTAL);
    fkine_mma_kernel<<<N / TILE_M, TPB, SM_TOTAL>>>(q, W0, b0, bh, bf, out_y, out_t);
}

// round 14
// speedup vs baseline: 4.7707x; 1.0031x over previous
#include <cuda_runtime.h>
#include <cuda_fp16.h>
#include <cstdint>
#include <math.h>

typedef uint32_t u32;

#define TPB    128
#define NJ     7
#define RSB    272          // bytes per f16 tile row (136 halves)
#define TILE_M 64

// ---- smem: double-buffered A tiles ----
#define SM_A0     0              // 64*272 = 17408
#define SM_A1     17408
#define SM_TOTAL  34816
#define TOPOFF    192            // TOP overlay: SM_A1 + r*RSB + TOPOFF (12 f32)

// ---- fragment-layout weight images in global ----
// hidden layer image: [kt(8)][ntile(8)][h(2)][lane(32)] x 16B  = 65536 B
// final  layer image: [kt(8)][h(2)][lane(32)] x 16B            = 8192 B
#define HIMG    65536
#define FIMG    8192
#define JSTRIDE (2*HIMG + FIMG)
__device__ __align__(16) char g_wbuf[NJ * JSTRIDE];

static __device__ __forceinline__ u32 smem_u32(const void* p) {
    u32 a;
    asm("{ .reg .u64 t; cvta.to.shared.u64 t, %1; cvt.u32.u64 %0, t; }" : "=r"(a) : "l"(p));
    return a;
}
static __device__ __forceinline__ u32 packh(float x0, float x1) {
    u32 r;
    asm("cvt.rn.f16x2.f32 %0, %1, %2;" : "=r"(r) : "f"(x1), "f"(x0));
    return r;
}
static __device__ __forceinline__ uint4 ldmx4(u32 addr) {
    uint4 r;
    asm volatile("ldmatrix.sync.aligned.m8n8.x4.shared.b16 {%0,%1,%2,%3}, [%4];"
                 : "=r"(r.x), "=r"(r.y), "=r"(r.z), "=r"(r.w) : "r"(addr));
    return r;
}
static __device__ __forceinline__ void stmx4(u32 addr, u32 r0, u32 r1, u32 r2, u32 r3) {
    asm volatile("stmatrix.sync.aligned.m8n8.x4.shared.b16 [%0], {%1,%2,%3,%4};"
                 :: "r"(addr), "r"(r0), "r"(r1), "r"(r2), "r"(r3) : "memory");
}
static __device__ __forceinline__ void mma_h(float d[4], const uint4& a, u32 b0, u32 b1) {
    asm volatile("mma.sync.aligned.m16n8k16.row.col.f32.f16.f16.f32 "
                 "{%0,%1,%2,%3},{%4,%5,%6,%7},{%8,%9},{%0,%1,%2,%3};"
                 : "+f"(d[0]), "+f"(d[1]), "+f"(d[2]), "+f"(d[3])
                 : "r"(a.x), "r"(a.y), "r"(a.z), "r"(a.w), "r"(b0), "r"(b1));
}

// ============ weight preconversion: fp32 -> fp16 hi/lo fragment images ============
__global__ void conv_weights_kernel(const float* __restrict__ Wh,
                                    const float* __restrict__ Wf)
{
    const int stride = gridDim.x * blockDim.x;
    const int t0 = blockIdx.x * blockDim.x + threadIdx.x;

    for (int i = t0; i < 14 * 16384; i += stride) {
        int layer = i >> 14;
        int w = i & 16383;
        int e = w & 3, lane = (w >> 2) & 31, h = (w >> 7) & 1;
        int nt = (w >> 8) & 7, kt = (w >> 11) & 7;
        int tg = lane >> 2, tl = lane & 3;
        int n = nt * 16 + tg + ((e >> 1) ? 8 : 0);
        int k = kt * 16 + 2 * tl + ((e & 1) ? 8 : 0);
        const float* Wsrc = Wh + (size_t)layer * 16384;
        float v0 = Wsrc[n * 128 + k], v1 = Wsrc[n * 128 + k + 1];
        u32 out;
        if (h == 0) {
            out = packh(__half2float(__float2half_rn(v0)), __half2float(__float2half_rn(v1)));
        } else {
            float r0 = v0 - __half2float(__float2half_rn(v0));
            float r1 = v1 - __half2float(__float2half_rn(v1));
            out = packh(r0, r1);
        }
        int j = layer >> 1, l = layer & 1;
        u32* img = (u32*)(g_wbuf + (size_t)j * JSTRIDE + l * HIMG);
        img[w] = out;
    }

    for (int i = t0; i < 7 * 2048; i += stride) {
        int j = i >> 11;
        int w = i & 2047;
        int e = w & 3, lane = (w >> 2) & 31, h = (w >> 7) & 1, kt = (w >> 8) & 7;
        int tg = lane >> 2, tl = lane & 3;
        int n = tg + ((e >> 1) ? 8 : 0);
        int k = kt * 16 + 2 * tl + ((e & 1) ? 8 : 0);
        u32 out = 0;
        if (n < 12) {
            const float* Wsrc = Wf + (size_t)j * 1536;
            float v0 = Wsrc[n * 128 + k], v1 = Wsrc[n * 128 + k + 1];
            if (h == 0) {
                out = packh(__half2float(__float2half_rn(v0)), __half2float(__float2half_rn(v1)));
            } else {
                float r0 = v0 - __half2float(__float2half_rn(v0));
                float r1 = v1 - __half2float(__float2half_rn(v1));
                out = packh(r0, r1);
            }
        }
        u32* img = (u32*)(g_wbuf + (size_t)j * JSTRIDE + 2 * HIMG);
        img[w] = out;
    }
}

// ============ main kernel ============

// hidden layer: dst <- relu(src @ (Whi+Wlo)^T + bias).  No internal sync:
// reads src buffer, stmatrix-writes dst buffer (double-buffered A).
static __device__ void mma_hidden(u32 smb, u32 src, u32 dst, const char* __restrict__ wimg,
                                  const float* __restrict__ bias, int lane, int wid)
{
    const int n_base = wid * 32;
    const uint4* wf = (const uint4*)wimg;
    float acc[4][4][4];
    #pragma unroll
    for (int mt = 0; mt < 4; ++mt)
        #pragma unroll
        for (int nt = 0; nt < 4; ++nt)
            #pragma unroll
            for (int e = 0; e < 4; ++e) acc[mt][nt][e] = 0.f;

    const int arow = lane & 15, acol = (lane >> 4) << 3;
    const int nt0 = 2 * wid;

    uint4 bcur[4], bnxt[4];
    #pragma unroll
    for (int i = 0; i < 4; ++i)
        bcur[i] = __ldg(&wf[(((0 * 8 + nt0 + (i >> 1)) * 2 + (i & 1)) * 32) + lane]);

    #pragma unroll
    for (int kt = 0; kt < 8; ++kt) {
        if (kt < 7) {
            #pragma unroll
            for (int i = 0; i < 4; ++i)
                bnxt[i] = __ldg(&wf[((((kt + 1) * 8 + nt0 + (i >> 1)) * 2 + (i & 1)) * 32) + lane]);
        }
        int k0 = kt * 16;
        uint4 af[4];
        #pragma unroll
        for (int mt = 0; mt < 4; ++mt) {
            u32 a = smb + src + (u32)(mt * 16 + arow) * RSB + (u32)(k0 + acol) * 2;
            af[mt] = ldmx4(a);
        }
        #pragma unroll
        for (int np = 0; np < 2; ++np) {
            uint4 bh = bcur[np * 2 + 0];
            uint4 bl = bcur[np * 2 + 1];
            #pragma unroll
            for (int mt = 0; mt < 4; ++mt) {
                mma_h(acc[mt][np*2+0], af[mt], bh.x, bh.y);
                mma_h(acc[mt][np*2+0], af[mt], bl.x, bl.y);
                mma_h(acc[mt][np*2+1], af[mt], bh.z, bh.w);
                mma_h(acc[mt][np*2+1], af[mt], bl.z, bl.w);
            }
        }
        #pragma unroll
        for (int i = 0; i < 4; ++i) bcur[i] = bnxt[i];
    }

    // bias + relu + pack -> stmatrix into dst (frag-exact mapping)
    const int tl = lane & 3;
    float2 bv[4];
    #pragma unroll
    for (int nt = 0; nt < 4; ++nt)
        bv[nt] = __ldg((const float2*)&bias[n_base + nt * 8 + 2 * tl]);

    #pragma unroll
    for (int mt = 0; mt < 4; ++mt) {
        #pragma unroll
        for (int g = 0; g < 2; ++g) {
            int e0 = 2 * g, e1 = 2 * g + 1;
            u32 r0 = packh(fmaxf(acc[mt][e0][0] + bv[e0].x, 0.f),
                           fmaxf(acc[mt][e0][1] + bv[e0].y, 0.f));
            u32 r1 = packh(fmaxf(acc[mt][e0][2] + bv[e0].x, 0.f),
                           fmaxf(acc[mt][e0][3] + bv[e0].y, 0.f));
            u32 r2 = packh(fmaxf(acc[mt][e1][0] + bv[e1].x, 0.f),
                           fmaxf(acc[mt][e1][1] + bv[e1].y, 0.f));
            u32 r3 = packh(fmaxf(acc[mt][e1][2] + bv[e1].x, 0.f),
                           fmaxf(acc[mt][e1][3] + bv[e1].y, 0.f));
            u32 addr = smb + dst + (u32)(mt * 16 + arow) * RSB
                     + (u32)(n_base + g * 16 + acol) * 2;
            stmx4(addr, r0, r1, r2, r3);
        }
    }
}

// final layer: TOP[64][12] = A(src) @ (Wfhi+Wflo)^T, f32 staged in A1 overlay.
static __device__ void mma_final(u32 smb, char* sm, u32 src, const char* __restrict__ fimg,
                                 int lane, int wid)
{
    const int m_base = wid * 16;
    const uint4* wf = (const uint4*)fimg;
    float acc[2][4] = {};
    const int arow = lane & 15, acol = (lane >> 4) << 3;

    uint4 bcur[2], bnxt[2];
    bcur[0] = __ldg(&wf[(0 * 2 + 0) * 32 + lane]);
    bcur[1] = __ldg(&wf[(0 * 2 + 1) * 32 + lane]);

    #pragma unroll
    for (int kt = 0; kt < 8; ++kt) {
        if (kt < 7) {
            bnxt[0] = __ldg(&wf[((kt + 1) * 2 + 0) * 32 + lane]);
            bnxt[1] = __ldg(&wf[((kt + 1) * 2 + 1) * 32 + lane]);
        }
        int k0 = kt * 16;
        u32 a = smb + src + (u32)(m_base + arow) * RSB + (u32)(k0 + acol) * 2;
        uint4 af = ldmx4(a);
        uint4 bh = bcur[0], bl = bcur[1];
        mma_h(acc[0], af, bh.x, bh.y);
        mma_h(acc[0], af, bl.x, bl.y);
        mma_h(acc[1], af, bh.z, bh.w);
        mma_h(acc[1], af, bl.z, bl.w);
        bcur[0] = bnxt[0]; bcur[1] = bnxt[1];
    }
    #pragma unroll
    for (int nt = 0; nt < 2; ++nt) {
        int r = m_base + (lane >> 2);
        int c = nt * 8 + 2 * (lane & 3);
        if (c < 12) {
            *(float2*)(sm + SM_A1 + r * RSB + TOPOFF + c * 4)       = make_float2(acc[nt][0], acc[nt][1]);
            *(float2*)(sm + SM_A1 + (r + 8) * RSB + TOPOFF + c * 4) = make_float2(acc[nt][2], acc[nt][3]);
        }
    }
}

__global__ void __launch_bounds__(TPB, 4)
fkine_mma_kernel(const float* __restrict__ q,
                 const float* __restrict__ W0,
                 const float* __restrict__ b0,
                 const float* __restrict__ bh,
                 const float* __restrict__ bf,
                 float* __restrict__ out_y,
                 float* __restrict__ out_t)
{
    extern __shared__ char sm[];
    const u32 smb = smem_u32(sm);
    const int tid = threadIdx.x, lane = tid & 31, wid = tid >> 5;
    const int g0 = blockIdx.x * TILE_M;
    const char* gw = g_wbuf;

    // per-thread cumulative transform (threads 0..63 own sample g0+tid)
    float Tc[16];
    #pragma unroll
    for (int e = 0; e < 16; ++e) Tc[e] = ((e >> 2) == (e & 3)) ? 1.f : 0.f;

    // chain epilogue for joint jj: reads TOP (A1 overlay), updates Tc, writes outputs
    auto epilogue = [&](int jj) {
        int m = tid;
        float Tl[12], Tn[16];
        #pragma unroll
        for (int i = 0; i < 12; ++i)
            Tl[i] = *(float*)(sm + SM_A1 + m * RSB + TOPOFF + i * 4) + __ldg(&bf[jj * 12 + i]);
        #pragma unroll
        for (int i = 0; i < 3; ++i)
            #pragma unroll
            for (int c = 0; c < 4; ++c)
                Tn[i*4+c] = Tl[i*4+0]*Tc[0+c] + Tl[i*4+1]*Tc[4+c]
                          + Tl[i*4+2]*Tc[8+c] + Tl[i*4+3]*Tc[12+c];
        #pragma unroll
        for (int c = 0; c < 4; ++c) Tn[12+c] = Tc[12+c];

        float4* tp = (float4*)(out_t + (size_t)(g0 + m) * 112 + jj * 16);
        tp[0] = make_float4(Tl[0], Tl[1], Tl[2],  Tl[3]);
        tp[1] = make_float4(Tl[4], Tl[5], Tl[6],  Tl[7]);
        tp[2] = make_float4(Tl[8], Tl[9], Tl[10], Tl[11]);
        tp[3] = make_float4(0.f, 0.f, 0.f, 1.f);

        size_t yb = (size_t)(g0 + m) * 21 + jj;
        out_y[yb]      = Tn[3];
        out_y[yb + 7]  = Tn[7];
        out_y[yb + 14] = Tn[11];

        #pragma unroll
        for (int i = 0; i < 16; ++i) Tc[i] = Tn[i];
    };

    for (int j = 0; j < NJ; ++j) {
        const char* gj = gw + (size_t)j * JSTRIDE;

        // ---- merged phase: layer0(j) -> A0 (all threads); epilogue(j-1) (threads<64)
        {
            int m = tid >> 1, half = tid & 1;
            float th = q[(size_t)(g0 + m) * NJ + j];
            float ct = cosf(th), st = sinf(th);
            const float* w0  = W0 + (size_t)j * 384;
            const float* b0j = b0 + (size_t)j * 128;
            int ob = half * 64;
            for (int o = ob; o < ob + 64; o += 2) {
                float h0 = fmaxf(fmaf(w0[o*3+0], th, fmaf(w0[o*3+1], ct, fmaf(w0[o*3+2], st, b0j[o]))),   0.f);
                float h1 = fmaxf(fmaf(w0[o*3+3], th, fmaf(w0[o*3+4], ct, fmaf(w0[o*3+5], st, b0j[o+1]))), 0.f);
                *(u32*)(sm + SM_A0 + m * RSB + o * 2) = packh(h0, h1);
            }
        }
        if (j > 0 && tid < TILE_M) epilogue(j - 1);
        __syncthreads();

        // ---- hidden layer 1: A0 -> A1
        mma_hidden(smb, SM_A0, SM_A1, gj, bh + (size_t)(j * 2) * 128, lane, wid);
        __syncthreads();

        // ---- hidden layer 2: A1 -> A0
        mma_hidden(smb, SM_A1, SM_A0, gj + HIMG, bh + (size_t)(j * 2 + 1) * 128, lane, wid);
        __syncthreads();

        // ---- final layer: A0 -> TOP (A1 overlay)
        mma_final(smb, sm, SM_A0, gj + 2 * HIMG, lane, wid);
        __syncthreads();
    }

    if (tid < TILE_M) epilogue(NJ - 1);
}

extern "C" void kernel_launch(void* const* d_in, const int* in_sizes, int n_in,
                              void* d_out, int out_size)
{
    const float* q  = (const float*)d_in[0];
    const float* W0 = (const float*)d_in[1];
    const float* b0 = (const float*)d_in[2];
    const float* Wh = (const float*)d_in[3];
    const float* bh = (const float*)d_in[4];
    const float* Wf = (const float*)d_in[5];
    const float* bf = (const float*)d_in[6];

    const int N = in_sizes[0] / NJ;           // q is [N, 7]
    float* out_y = (float*)d_out;             // [N, 3, 7]
    float* out_t = out_y + (size_t)N * 21;    // [N, 7, 4, 4]

    conv_weights_kernel<<<128, 256>>>(Wh, Wf);

    cudaFuncSetAttribute(fkine_mma_kernel,
                         cudaFuncAttributeMaxDynamicSharedMemorySize, SM_TOTAL);
    fkine_mma_kernel<<<N / TILE_M, TPB, SM_TOTAL>>>(q, W0, b0, bh, bf, out_y, out_t);
}

// round 15
// speedup vs baseline: 5.3062x; 1.1123x over previous
#include <cuda_runtime.h>
#include <cuda_fp16.h>
#include <cstdint>
#include <math.h>

typedef uint32_t u32;

#define TPB    128
#define NJ     7
#define RSB    272          // bytes per f16 tile row (136 halves)
#define TILE_M 64

// ---- smem: double-buffered A tiles ----
#define SM_A0     0              // 64*272 = 17408
#define SM_A1     17408
#define SM_TOTAL  34816
#define TOPOFF    192            // TOP overlay: SM_A1 + r*RSB + TOPOFF (12 f32)

// ---- fragment-layout weight images in global ----
#define HIMG    65536
#define FIMG    8192
#define JSTRIDE (2*HIMG + FIMG)
__device__ __align__(16) char g_wbuf[NJ * JSTRIDE];

static __device__ __forceinline__ u32 smem_u32(const void* p) {
    u32 a;
    asm("{ .reg .u64 t; cvta.to.shared.u64 t, %1; cvt.u32.u64 %0, t; }" : "=r"(a) : "l"(p));
    return a;
}
static __device__ __forceinline__ u32 packh(float x0, float x1) {
    u32 r;
    asm("cvt.rn.f16x2.f32 %0, %1, %2;" : "=r"(r) : "f"(x1), "f"(x0));
    return r;
}
static __device__ __forceinline__ uint4 ldmx4(u32 addr) {
    uint4 r;
    asm volatile("ldmatrix.sync.aligned.m8n8.x4.shared.b16 {%0,%1,%2,%3}, [%4];"
                 : "=r"(r.x), "=r"(r.y), "=r"(r.z), "=r"(r.w) : "r"(addr));
    return r;
}
static __device__ __forceinline__ void stmx4(u32 addr, u32 r0, u32 r1, u32 r2, u32 r3) {
    asm volatile("stmatrix.sync.aligned.m8n8.x4.shared.b16 [%0], {%1,%2,%3,%4};"
                 :: "r"(addr), "r"(r0), "r"(r1), "r"(r2), "r"(r3) : "memory");
}
static __device__ __forceinline__ void mma_h(float d[4], const uint4& a, u32 b0, u32 b1) {
    asm volatile("mma.sync.aligned.m16n8k16.row.col.f32.f16.f16.f32 "
                 "{%0,%1,%2,%3},{%4,%5,%6,%7},{%8,%9},{%0,%1,%2,%3};"
                 : "+f"(d[0]), "+f"(d[1]), "+f"(d[2]), "+f"(d[3])
                 : "r"(a.x), "r"(a.y), "r"(a.z), "r"(a.w), "r"(b0), "r"(b1));
}

// ============ weight preconversion: fp32 -> fp16 hi/lo fragment images ============
__global__ void conv_weights_kernel(const float* __restrict__ Wh,
                                    const float* __restrict__ Wf)
{
    const int stride = gridDim.x * blockDim.x;
    const int t0 = blockIdx.x * blockDim.x + threadIdx.x;

    for (int i = t0; i < 14 * 16384; i += stride) {
        int layer = i >> 14;
        int w = i & 16383;
        int e = w & 3, lane = (w >> 2) & 31, h = (w >> 7) & 1;
        int nt = (w >> 8) & 7, kt = (w >> 11) & 7;
        int tg = lane >> 2, tl = lane & 3;
        int n = nt * 16 + tg + ((e >> 1) ? 8 : 0);
        int k = kt * 16 + 2 * tl + ((e & 1) ? 8 : 0);
        const float* Wsrc = Wh + (size_t)layer * 16384;
        float v0 = Wsrc[n * 128 + k], v1 = Wsrc[n * 128 + k + 1];
        u32 out;
        if (h == 0) {
            out = packh(__half2float(__float2half_rn(v0)), __half2float(__float2half_rn(v1)));
        } else {
            float r0 = v0 - __half2float(__float2half_rn(v0));
            float r1 = v1 - __half2float(__float2half_rn(v1));
            out = packh(r0, r1);
        }
        int j = layer >> 1, l = layer & 1;
        u32* img = (u32*)(g_wbuf + (size_t)j * JSTRIDE + l * HIMG);
        img[w] = out;
    }

    for (int i = t0; i < 7 * 2048; i += stride) {
        int j = i >> 11;
        int w = i & 2047;
        int e = w & 3, lane = (w >> 2) & 31, h = (w >> 7) & 1, kt = (w >> 8) & 7;
        int tg = lane >> 2, tl = lane & 3;
        int n = tg + ((e >> 1) ? 8 : 0);
        int k = kt * 16 + 2 * tl + ((e & 1) ? 8 : 0);
        u32 out = 0;
        if (n < 12) {
            const float* Wsrc = Wf + (size_t)j * 1536;
            float v0 = Wsrc[n * 128 + k], v1 = Wsrc[n * 128 + k + 1];
            if (h == 0) {
                out = packh(__half2float(__float2half_rn(v0)), __half2float(__float2half_rn(v1)));
            } else {
                float r0 = v0 - __half2float(__float2half_rn(v0));
                float r1 = v1 - __half2float(__float2half_rn(v1));
                out = packh(r0, r1);
            }
        }
        u32* img = (u32*)(g_wbuf + (size_t)j * JSTRIDE + 2 * HIMG);
        img[w] = out;
    }
}

// ============ MLP kernel (per-joint, fully parallel) ============

static __device__ void mma_hidden(u32 smb, u32 src, u32 dst, const char* __restrict__ wimg,
                                  const float* __restrict__ bias, int lane, int wid)
{
    const int n_base = wid * 32;
    const uint4* wf = (const uint4*)wimg;
    float acc[4][4][4];
    #pragma unroll
    for (int mt = 0; mt < 4; ++mt)
        #pragma unroll
        for (int nt = 0; nt < 4; ++nt)
            #pragma unroll
            for (int e = 0; e < 4; ++e) acc[mt][nt][e] = 0.f;

    const int arow = lane & 15, acol = (lane >> 4) << 3;
    const int nt0 = 2 * wid;

    uint4 bcur[4], bnxt[4];
    #pragma unroll
    for (int i = 0; i < 4; ++i)
        bcur[i] = __ldg(&wf[(((0 * 8 + nt0 + (i >> 1)) * 2 + (i & 1)) * 32) + lane]);

    #pragma unroll
    for (int kt = 0; kt < 8; ++kt) {
        if (kt < 7) {
            #pragma unroll
            for (int i = 0; i < 4; ++i)
                bnxt[i] = __ldg(&wf[((((kt + 1) * 8 + nt0 + (i >> 1)) * 2 + (i & 1)) * 32) + lane]);
        }
        int k0 = kt * 16;
        uint4 af[4];
        #pragma unroll
        for (int mt = 0; mt < 4; ++mt) {
            u32 a = smb + src + (u32)(mt * 16 + arow) * RSB + (u32)(k0 + acol) * 2;
            af[mt] = ldmx4(a);
        }
        #pragma unroll
        for (int np = 0; np < 2; ++np) {
            uint4 bh = bcur[np * 2 + 0];
            uint4 bl = bcur[np * 2 + 1];
            #pragma unroll
            for (int mt = 0; mt < 4; ++mt) {
                mma_h(acc[mt][np*2+0], af[mt], bh.x, bh.y);
                mma_h(acc[mt][np*2+0], af[mt], bl.x, bl.y);
                mma_h(acc[mt][np*2+1], af[mt], bh.z, bh.w);
                mma_h(acc[mt][np*2+1], af[mt], bl.z, bl.w);
            }
        }
        #pragma unroll
        for (int i = 0; i < 4; ++i) bcur[i] = bnxt[i];
    }

    const int tl = lane & 3;
    float2 bv[4];
    #pragma unroll
    for (int nt = 0; nt < 4; ++nt)
        bv[nt] = __ldg((const float2*)&bias[n_base + nt * 8 + 2 * tl]);

    #pragma unroll
    for (int mt = 0; mt < 4; ++mt) {
        #pragma unroll
        for (int g = 0; g < 2; ++g) {
            int e0 = 2 * g, e1 = 2 * g + 1;
            u32 r0 = packh(fmaxf(acc[mt][e0][0] + bv[e0].x, 0.f),
                           fmaxf(acc[mt][e0][1] + bv[e0].y, 0.f));
            u32 r1 = packh(fmaxf(acc[mt][e0][2] + bv[e0].x, 0.f),
                           fmaxf(acc[mt][e0][3] + bv[e0].y, 0.f));
            u32 r2 = packh(fmaxf(acc[mt][e1][0] + bv[e1].x, 0.f),
                           fmaxf(acc[mt][e1][1] + bv[e1].y, 0.f));
            u32 r3 = packh(fmaxf(acc[mt][e1][2] + bv[e1].x, 0.f),
                           fmaxf(acc[mt][e1][3] + bv[e1].y, 0.f));
            u32 addr = smb + dst + (u32)(mt * 16 + arow) * RSB
                     + (u32)(n_base + g * 16 + acol) * 2;
            stmx4(addr, r0, r1, r2, r3);
        }
    }
}

static __device__ void mma_final(u32 smb, char* sm, u32 src, const char* __restrict__ fimg,
                                 int lane, int wid)
{
    const int m_base = wid * 16;
    const uint4* wf = (const uint4*)fimg;
    float acc[2][4] = {};
    const int arow = lane & 15, acol = (lane >> 4) << 3;

    uint4 bcur[2], bnxt[2];
    bcur[0] = __ldg(&wf[(0 * 2 + 0) * 32 + lane]);
    bcur[1] = __ldg(&wf[(0 * 2 + 1) * 32 + lane]);

    #pragma unroll
    for (int kt = 0; kt < 8; ++kt) {
        if (kt < 7) {
            bnxt[0] = __ldg(&wf[((kt + 1) * 2 + 0) * 32 + lane]);
            bnxt[1] = __ldg(&wf[((kt + 1) * 2 + 1) * 32 + lane]);
        }
        int k0 = kt * 16;
        u32 a = smb + src + (u32)(m_base + arow) * RSB + (u32)(k0 + acol) * 2;
        uint4 af = ldmx4(a);
        uint4 bh = bcur[0], bl = bcur[1];
        mma_h(acc[0], af, bh.x, bh.y);
        mma_h(acc[0], af, bl.x, bl.y);
        mma_h(acc[1], af, bh.z, bh.w);
        mma_h(acc[1], af, bl.z, bl.w);
        bcur[0] = bnxt[0]; bcur[1] = bnxt[1];
    }
    #pragma unroll
    for (int nt = 0; nt < 2; ++nt) {
        int r = m_base + (lane >> 2);
        int c = nt * 8 + 2 * (lane & 3);
        if (c < 12) {
            *(float2*)(sm + SM_A1 + r * RSB + TOPOFF + c * 4)       = make_float2(acc[nt][0], acc[nt][1]);
            *(float2*)(sm + SM_A1 + (r + 8) * RSB + TOPOFF + c * 4) = make_float2(acc[nt][2], acc[nt][3]);
        }
    }
}

// grid = (N/64, 7); blockIdx.x fastest -> a wave of CTAs shares one joint's weights
__global__ void __launch_bounds__(TPB, 4)
fkine_mlp_kernel(const float* __restrict__ q,
                 const float* __restrict__ W0,
                 const float* __restrict__ b0,
                 const float* __restrict__ bh,
                 const float* __restrict__ bf,
                 float* __restrict__ out_t)
{
    extern __shared__ char sm[];
    const u32 smb = smem_u32(sm);
    const int tid = threadIdx.x, lane = tid & 31, wid = tid >> 5;
    const int g0 = blockIdx.x * TILE_M;
    const int j  = blockIdx.y;
    const char* gj = g_wbuf + (size_t)j * JSTRIDE;

    // ---- layer 0 (K=3, scalar fp32) -> A0 (fp16)
    {
        int m = tid >> 1, half = tid & 1;
        float th = q[(size_t)(g0 + m) * NJ + j];
        float ct = cosf(th), st = sinf(th);
        const float* w0  = W0 + (size_t)j * 384;
        const float* b0j = b0 + (size_t)j * 128;
        int ob = half * 64;
        for (int o = ob; o < ob + 64; o += 2) {
            float h0 = fmaxf(fmaf(w0[o*3+0], th, fmaf(w0[o*3+1], ct, fmaf(w0[o*3+2], st, b0j[o]))),   0.f);
            float h1 = fmaxf(fmaf(w0[o*3+3], th, fmaf(w0[o*3+4], ct, fmaf(w0[o*3+5], st, b0j[o+1]))), 0.f);
            *(u32*)(sm + SM_A0 + m * RSB + o * 2) = packh(h0, h1);
        }
    }
    __syncthreads();

    // ---- hidden layer 1: A0 -> A1
    mma_hidden(smb, SM_A0, SM_A1, gj, bh + (size_t)(j * 2) * 128, lane, wid);
    __syncthreads();

    // ---- hidden layer 2: A1 -> A0
    mma_hidden(smb, SM_A1, SM_A0, gj + HIMG, bh + (size_t)(j * 2 + 1) * 128, lane, wid);
    __syncthreads();

    // ---- final layer: A0 -> TOP (A1 overlay)
    mma_final(smb, sm, SM_A0, gj + 2 * HIMG, lane, wid);
    __syncthreads();

    // ---- write local transform t[m][j] (with bias + bottom row)
    if (tid < TILE_M) {
        int m = tid;
        float Tl[12];
        #pragma unroll
        for (int i = 0; i < 12; ++i)
            Tl[i] = *(float*)(sm + SM_A1 + m * RSB + TOPOFF + i * 4) + __ldg(&bf[j * 12 + i]);
        float4* tp = (float4*)(out_t + (size_t)(g0 + m) * 112 + j * 16);
        tp[0] = make_float4(Tl[0], Tl[1], Tl[2],  Tl[3]);
        tp[1] = make_float4(Tl[4], Tl[5], Tl[6],  Tl[7]);
        tp[2] = make_float4(Tl[8], Tl[9], Tl[10], Tl[11]);
        tp[3] = make_float4(0.f, 0.f, 0.f, 1.f);
    }
}

// ============ chain kernel: cumulative 4x4 products -> y ============
#define CTPB 256
__global__ void __launch_bounds__(CTPB)
fkine_chain_kernel(const float* __restrict__ t, float* __restrict__ out_y)
{
    __shared__ float ysm[CTPB * 21];
    const int tid = threadIdx.x;
    const int m0 = blockIdx.x * CTPB;
    const int m = m0 + tid;

    float Tc[16];
    #pragma unroll
    for (int e = 0; e < 16; ++e) Tc[e] = ((e >> 2) == (e & 3)) ? 1.f : 0.f;

    const float4* tp = (const float4*)(t + (size_t)m * 112);
    #pragma unroll
    for (int j = 0; j < NJ; ++j) {
        float4 r0 = tp[j * 4 + 0];
        float4 r1 = tp[j * 4 + 1];
        float4 r2 = tp[j * 4 + 2];
        float Tl[12] = {r0.x, r0.y, r0.z, r0.w,
                        r1.x, r1.y, r1.z, r1.w,
                        r2.x, r2.y, r2.z, r2.w};
        float Tn[16];
        #pragma unroll
        for (int i = 0; i < 3; ++i)
            #pragma unroll
            for (int c = 0; c < 4; ++c)
                Tn[i*4+c] = Tl[i*4+0]*Tc[0+c] + Tl[i*4+1]*Tc[4+c]
                          + Tl[i*4+2]*Tc[8+c] + Tl[i*4+3]*Tc[12+c];
        #pragma unroll
        for (int c = 0; c < 4; ++c) Tn[12+c] = Tc[12+c];

        ysm[tid * 21 + j]      = Tn[3];
        ysm[tid * 21 + 7 + j]  = Tn[7];
        ysm[tid * 21 + 14 + j] = Tn[11];

        #pragma unroll
        for (int i = 0; i < 16; ++i) Tc[i] = Tn[i];
    }
    __syncthreads();
    for (int idx = tid; idx < CTPB * 21; idx += CTPB)
        out_y[(size_t)m0 * 21 + idx] = ysm[idx];
}

extern "C" void kernel_launch(void* const* d_in, const int* in_sizes, int n_in,
                              void* d_out, int out_size)
{
    const float* q  = (const float*)d_in[0];
    const float* W0 = (const float*)d_in[1];
    const float* b0 = (const float*)d_in[2];
    const float* Wh = (const float*)d_in[3];
    const float* bh = (const float*)d_in[4];
    const float* Wf = (const float*)d_in[5];
    const float* bf = (const float*)d_in[6];

    const int N = in_sizes[0] / NJ;           // q is [N, 7]
    float* out_y = (float*)d_out;             // [N, 3, 7]
    float* out_t = out_y + (size_t)N * 21;    // [N, 7, 4, 4]

    conv_weights_kernel<<<128, 256>>>(Wh, Wf);

    cudaFuncSetAttribute(fkine_mlp_kernel,
                         cudaFuncAttributeMaxDynamicSharedMemorySize, SM_TOTAL);
    dim3 grid(N / TILE_M, NJ);
    fkine_mlp_kernel<<<grid, TPB, SM_TOTAL>>>(q, W0, b0, bh, bf, out_t);

    fkine_chain_kernel<<<N / CTPB, CTPB>>>(out_t, out_y);
}

// round 16
// speedup vs baseline: 5.6800x; 1.0704x over previous
#include <cuda_runtime.h>
#include <cuda_fp16.h>
#include <cstdint>
#include <math.h>

typedef uint32_t u32;

#define TPB    128
#define NJ     7
#define RSB    272          // bytes per f16 tile row (136 halves)
#define TILE_M 64

// ---- smem: double-buffered A tiles ----
#define SM_A0     0              // 64*272 = 17408
#define SM_A1     17408
#define SM_TOTAL  34816
#define TOPOFF    192            // TOP overlay: SM_A1 + r*RSB + TOPOFF (12 f32)

// ---- fragment-layout weight images in global ----
#define HIMG    65536
#define FIMG    8192
#define JSTRIDE (2*HIMG + FIMG)
__device__ __align__(16) char g_wbuf[NJ * JSTRIDE];

static __device__ __forceinline__ u32 smem_u32(const void* p) {
    u32 a;
    asm("{ .reg .u64 t; cvta.to.shared.u64 t, %1; cvt.u32.u64 %0, t; }" : "=r"(a) : "l"(p));
    return a;
}
static __device__ __forceinline__ u32 packh(float x0, float x1) {
    u32 r;
    asm("cvt.rn.f16x2.f32 %0, %1, %2;" : "=r"(r) : "f"(x1), "f"(x0));
    return r;
}
static __device__ __forceinline__ uint4 ldmx4(u32 addr) {
    uint4 r;
    asm volatile("ldmatrix.sync.aligned.m8n8.x4.shared.b16 {%0,%1,%2,%3}, [%4];"
                 : "=r"(r.x), "=r"(r.y), "=r"(r.z), "=r"(r.w) : "r"(addr));
    return r;
}
static __device__ __forceinline__ void stmx4(u32 addr, u32 r0, u32 r1, u32 r2, u32 r3) {
    asm volatile("stmatrix.sync.aligned.m8n8.x4.shared.b16 [%0], {%1,%2,%3,%4};"
                 :: "r"(addr), "r"(r0), "r"(r1), "r"(r2), "r"(r3) : "memory");
}
static __device__ __forceinline__ void mma_h(float d[4], const uint4& a, u32 b0, u32 b1) {
    asm volatile("mma.sync.aligned.m16n8k16.row.col.f32.f16.f16.f32 "
                 "{%0,%1,%2,%3},{%4,%5,%6,%7},{%8,%9},{%0,%1,%2,%3};"
                 : "+f"(d[0]), "+f"(d[1]), "+f"(d[2]), "+f"(d[3])
                 : "r"(a.x), "r"(a.y), "r"(a.z), "r"(a.w), "r"(b0), "r"(b1));
}

// ============ weight preconversion: fp32 -> fp16 hi/lo fragment images ============
__global__ void conv_weights_kernel(const float* __restrict__ Wh,
                                    const float* __restrict__ Wf)
{
    const int stride = gridDim.x * blockDim.x;
    const int t0 = blockIdx.x * blockDim.x + threadIdx.x;

    for (int i = t0; i < 14 * 16384; i += stride) {
        int layer = i >> 14;
        int w = i & 16383;
        int e = w & 3, lane = (w >> 2) & 31, h = (w >> 7) & 1;
        int nt = (w >> 8) & 7, kt = (w >> 11) & 7;
        int tg = lane >> 2, tl = lane & 3;
        int n = nt * 16 + tg + ((e >> 1) ? 8 : 0);
        int k = kt * 16 + 2 * tl + ((e & 1) ? 8 : 0);
        const float* Wsrc = Wh + (size_t)layer * 16384;
        float v0 = Wsrc[n * 128 + k], v1 = Wsrc[n * 128 + k + 1];
        u32 out;
        if (h == 0) {
            out = packh(__half2float(__float2half_rn(v0)), __half2float(__float2half_rn(v1)));
        } else {
            float r0 = v0 - __half2float(__float2half_rn(v0));
            float r1 = v1 - __half2float(__float2half_rn(v1));
            out = packh(r0, r1);
        }
        int j = layer >> 1, l = layer & 1;
        u32* img = (u32*)(g_wbuf + (size_t)j * JSTRIDE + l * HIMG);
        img[w] = out;
    }

    for (int i = t0; i < 7 * 2048; i += stride) {
        int j = i >> 11;
        int w = i & 2047;
        int e = w & 3, lane = (w >> 2) & 31, h = (w >> 7) & 1, kt = (w >> 8) & 7;
        int tg = lane >> 2, tl = lane & 3;
        int n = tg + ((e >> 1) ? 8 : 0);
        int k = kt * 16 + 2 * tl + ((e & 1) ? 8 : 0);
        u32 out = 0;
        if (n < 12) {
            const float* Wsrc = Wf + (size_t)j * 1536;
            float v0 = Wsrc[n * 128 + k], v1 = Wsrc[n * 128 + k + 1];
            if (h == 0) {
                out = packh(__half2float(__float2half_rn(v0)), __half2float(__float2half_rn(v1)));
            } else {
                float r0 = v0 - __half2float(__float2half_rn(v0));
                float r1 = v1 - __half2float(__float2half_rn(v1));
                out = packh(r0, r1);
            }
        }
        u32* img = (u32*)(g_wbuf + (size_t)j * JSTRIDE + 2 * HIMG);
        img[w] = out;
    }
}

// ============ MLP kernel (per-joint, fully parallel) ============

static __device__ void mma_hidden(u32 smb, u32 src, u32 dst, const char* __restrict__ wimg,
                                  const float* __restrict__ bias, int lane, int wid)
{
    const int n_base = wid * 32;
    const uint4* wf = (const uint4*)wimg;
    float acc[4][4][4];
    #pragma unroll
    for (int mt = 0; mt < 4; ++mt)
        #pragma unroll
        for (int nt = 0; nt < 4; ++nt)
            #pragma unroll
            for (int e = 0; e < 4; ++e) acc[mt][nt][e] = 0.f;

    const int arow = lane & 15, acol = (lane >> 4) << 3;
    const int nt0 = 2 * wid;

    uint4 bcur[4], bnxt[4];
    #pragma unroll
    for (int i = 0; i < 4; ++i)
        bcur[i] = __ldg(&wf[(((0 * 8 + nt0 + (i >> 1)) * 2 + (i & 1)) * 32) + lane]);

    #pragma unroll
    for (int kt = 0; kt < 8; ++kt) {
        if (kt < 7) {
            #pragma unroll
            for (int i = 0; i < 4; ++i)
                bnxt[i] = __ldg(&wf[((((kt + 1) * 8 + nt0 + (i >> 1)) * 2 + (i & 1)) * 32) + lane]);
        }
        int k0 = kt * 16;
        uint4 af[4];
        #pragma unroll
        for (int mt = 0; mt < 4; ++mt) {
            u32 a = smb + src + (u32)(mt * 16 + arow) * RSB + (u32)(k0 + acol) * 2;
            af[mt] = ldmx4(a);
        }
        #pragma unroll
        for (int np = 0; np < 2; ++np) {
            uint4 bh = bcur[np * 2 + 0];
            uint4 bl = bcur[np * 2 + 1];
            #pragma unroll
            for (int mt = 0; mt < 4; ++mt) {
                mma_h(acc[mt][np*2+0], af[mt], bh.x, bh.y);
                mma_h(acc[mt][np*2+0], af[mt], bl.x, bl.y);
                mma_h(acc[mt][np*2+1], af[mt], bh.z, bh.w);
                mma_h(acc[mt][np*2+1], af[mt], bl.z, bl.w);
            }
        }
        #pragma unroll
        for (int i = 0; i < 4; ++i) bcur[i] = bnxt[i];
    }

    const int tl = lane & 3;
    float2 bv[4];
    #pragma unroll
    for (int nt = 0; nt < 4; ++nt)
        bv[nt] = __ldg((const float2*)&bias[n_base + nt * 8 + 2 * tl]);

    #pragma unroll
    for (int mt = 0; mt < 4; ++mt) {
        #pragma unroll
        for (int g = 0; g < 2; ++g) {
            int e0 = 2 * g, e1 = 2 * g + 1;
            u32 r0 = packh(fmaxf(acc[mt][e0][0] + bv[e0].x, 0.f),
                           fmaxf(acc[mt][e0][1] + bv[e0].y, 0.f));
            u32 r1 = packh(fmaxf(acc[mt][e0][2] + bv[e0].x, 0.f),
                           fmaxf(acc[mt][e0][3] + bv[e0].y, 0.f));
            u32 r2 = packh(fmaxf(acc[mt][e1][0] + bv[e1].x, 0.f),
                           fmaxf(acc[mt][e1][1] + bv[e1].y, 0.f));
            u32 r3 = packh(fmaxf(acc[mt][e1][2] + bv[e1].x, 0.f),
                           fmaxf(acc[mt][e1][3] + bv[e1].y, 0.f));
            u32 addr = smb + dst + (u32)(mt * 16 + arow) * RSB
                     + (u32)(n_base + g * 16 + acol) * 2;
            stmx4(addr, r0, r1, r2, r3);
        }
    }
}

static __device__ void mma_final(u32 smb, char* sm, u32 src, const char* __restrict__ fimg,
                                 int lane, int wid)
{
    const int m_base = wid * 16;
    const uint4* wf = (const uint4*)fimg;
    float acc[2][4] = {};
    const int arow = lane & 15, acol = (lane >> 4) << 3;

    uint4 bcur[2], bnxt[2];
    bcur[0] = __ldg(&wf[(0 * 2 + 0) * 32 + lane]);
    bcur[1] = __ldg(&wf[(0 * 2 + 1) * 32 + lane]);

    #pragma unroll
    for (int kt = 0; kt < 8; ++kt) {
        if (kt < 7) {
            bnxt[0] = __ldg(&wf[((kt + 1) * 2 + 0) * 32 + lane]);
            bnxt[1] = __ldg(&wf[((kt + 1) * 2 + 1) * 32 + lane]);
        }
        int k0 = kt * 16;
        u32 a = smb + src + (u32)(m_base + arow) * RSB + (u32)(k0 + acol) * 2;
        uint4 af = ldmx4(a);
        uint4 bh = bcur[0], bl = bcur[1];
        mma_h(acc[0], af, bh.x, bh.y);
        mma_h(acc[0], af, bl.x, bl.y);
        mma_h(acc[1], af, bh.z, bh.w);
        mma_h(acc[1], af, bl.z, bl.w);
        bcur[0] = bnxt[0]; bcur[1] = bnxt[1];
    }
    #pragma unroll
    for (int nt = 0; nt < 2; ++nt) {
        int r = m_base + (lane >> 2);
        int c = nt * 8 + 2 * (lane & 3);
        if (c < 12) {
            *(float2*)(sm + SM_A1 + r * RSB + TOPOFF + c * 4)       = make_float2(acc[nt][0], acc[nt][1]);
            *(float2*)(sm + SM_A1 + (r + 8) * RSB + TOPOFF + c * 4) = make_float2(acc[nt][2], acc[nt][3]);
        }
    }
}

// grid = (N/64, 7); blockIdx.x fastest -> a wave of CTAs shares one joint's weights
__global__ void __launch_bounds__(TPB, 4)
fkine_mlp_kernel(const float* __restrict__ q,
                 const float* __restrict__ W0,
                 const float* __restrict__ b0,
                 const float* __restrict__ bh,
                 const float* __restrict__ bf,
                 float* __restrict__ out_t)
{
    extern __shared__ char sm[];
    const u32 smb = smem_u32(sm);
    const int tid = threadIdx.x, lane = tid & 31, wid = tid >> 5;
    const int g0 = blockIdx.x * TILE_M;
    const int j  = blockIdx.y;
    const char* gj = g_wbuf + (size_t)j * JSTRIDE;

    // ---- layer 0 (K=3): lane = sample, uniform weight loads, STS.128 out
    {
        int m = (wid & 1) * 32 + lane;          // sample row within tile
        float th = q[(size_t)(g0 + m) * NJ + j];
        float ct = cosf(th), st = sinf(th);
        const float* w0  = W0 + (size_t)j * 384;
        const float* b0j = b0 + (size_t)j * 128;
        int ob = (wid >> 1) * 64;
        for (int o8 = ob; o8 < ob + 64; o8 += 8) {
            float4 bA = __ldg((const float4*)&b0j[o8]);
            float4 bB = __ldg((const float4*)&b0j[o8 + 4]);
            float bb[8] = {bA.x, bA.y, bA.z, bA.w, bB.x, bB.y, bB.z, bB.w};
            u32 pk[4];
            #pragma unroll
            for (int p = 0; p < 4; ++p) {
                int o = o8 + 2 * p;
                float2 f0 = __ldg((const float2*)&w0[o * 3]);      // w0[o][0], w0[o][1]
                float2 f1 = __ldg((const float2*)&w0[o * 3 + 2]);  // w0[o][2], w0[o+1][0]
                float2 f2 = __ldg((const float2*)&w0[o * 3 + 4]);  // w0[o+1][1], w0[o+1][2]
                float h0 = fmaxf(fmaf(f0.x, th, fmaf(f0.y, ct, fmaf(f1.x, st, bb[2*p]))),   0.f);
                float h1 = fmaxf(fmaf(f1.y, th, fmaf(f2.x, ct, fmaf(f2.y, st, bb[2*p+1]))), 0.f);
                pk[p] = packh(h0, h1);
            }
            *(uint4*)(sm + SM_A0 + m * RSB + o8 * 2) = make_uint4(pk[0], pk[1], pk[2], pk[3]);
        }
    }
    __syncthreads();

    // ---- hidden layer 1: A0 -> A1
    mma_hidden(smb, SM_A0, SM_A1, gj, bh + (size_t)(j * 2) * 128, lane, wid);
    __syncthreads();

    // ---- hidden layer 2: A1 -> A0
    mma_hidden(smb, SM_A1, SM_A0, gj + HIMG, bh + (size_t)(j * 2 + 1) * 128, lane, wid);
    __syncthreads();

    // ---- final layer: A0 -> TOP (A1 overlay)
    mma_final(smb, sm, SM_A0, gj + 2 * HIMG, lane, wid);
    __syncthreads();

    // ---- write local transform t[m][j] (with bias + bottom row)
    if (tid < TILE_M) {
        int m = tid;
        float Tl[12];
        #pragma unroll
        for (int i = 0; i < 12; ++i)
            Tl[i] = *(float*)(sm + SM_A1 + m * RSB + TOPOFF + i * 4) + __ldg(&bf[j * 12 + i]);
        float4* tp = (float4*)(out_t + (size_t)(g0 + m) * 112 + j * 16);
        tp[0] = make_float4(Tl[0], Tl[1], Tl[2],  Tl[3]);
        tp[1] = make_float4(Tl[4], Tl[5], Tl[6],  Tl[7]);
        tp[2] = make_float4(Tl[8], Tl[9], Tl[10], Tl[11]);
        tp[3] = make_float4(0.f, 0.f, 0.f, 1.f);
    }
}

// ============ chain kernel: smem-staged coalesced t reads -> cumulative products -> y ============
#define CTPB 128
#define CH_TS   (CTPB * 112)               // floats
#define CH_SMEM ((CH_TS + CTPB * 21) * 4)  // bytes
__global__ void __launch_bounds__(CTPB)
fkine_chain_kernel(const float* __restrict__ t, float* __restrict__ out_y)
{
    extern __shared__ float chs[];
    float* tsm = chs;             // CTPB x 112
    float* ysm = chs + CH_TS;     // CTPB x 21
    const int tid = threadIdx.x;
    const size_t m0 = (size_t)blockIdx.x * CTPB;

    // coalesced stage of this block's t slab (CTPB * 448 B contiguous)
    const float4* src = (const float4*)(t + m0 * 112);
    float4* dst = (float4*)tsm;
    #pragma unroll 4
    for (int i = tid; i < CTPB * 28; i += CTPB) dst[i] = src[i];
    __syncthreads();

    float Tc[16];
    #pragma unroll
    for (int e = 0; e < 16; ++e) Tc[e] = ((e >> 2) == (e & 3)) ? 1.f : 0.f;

    const float* tp = tsm + tid * 112;
    #pragma unroll
    for (int j = 0; j < NJ; ++j) {
        float Tl[12];
        #pragma unroll
        for (int i = 0; i < 12; ++i) Tl[i] = tp[j * 16 + i];
        float Tn[16];
        #pragma unroll
        for (int i = 0; i < 3; ++i)
            #pragma unroll
            for (int c = 0; c < 4; ++c)
                Tn[i*4+c] = Tl[i*4+0]*Tc[0+c] + Tl[i*4+1]*Tc[4+c]
                          + Tl[i*4+2]*Tc[8+c] + Tl[i*4+3]*Tc[12+c];
        #pragma unroll
        for (int c = 0; c < 4; ++c) Tn[12+c] = Tc[12+c];

        ysm[tid * 21 + j]      = Tn[3];
        ysm[tid * 21 + 7 + j]  = Tn[7];
        ysm[tid * 21 + 14 + j] = Tn[11];

        #pragma unroll
        for (int i = 0; i < 16; ++i) Tc[i] = Tn[i];
    }
    __syncthreads();
    for (int idx = tid; idx < CTPB * 21; idx += CTPB)
        out_y[m0 * 21 + idx] = ysm[idx];
}

extern "C" void kernel_launch(void* const* d_in, const int* in_sizes, int n_in,
                              void* d_out, int out_size)
{
    const float* q  = (const float*)d_in[0];
    const float* W0 = (const float*)d_in[1];
    const float* b0 = (const float*)d_in[2];
    const float* Wh = (const float*)d_in[3];
    const float* bh = (const float*)d_in[4];
    const float* Wf = (const float*)d_in[5];
    const float* bf = (const float*)d_in[6];

    const int N = in_sizes[0] / NJ;           // q is [N, 7]
    float* out_y = (float*)d_out;             // [N, 3, 7]
    float* out_t = out_y + (size_t)N * 21;    // [N, 7, 4, 4]

    conv_weights_kernel<<<1024, 256>>>(Wh, Wf);

    cudaFuncSetAttribute(fkine_mlp_kernel,
                         cudaFuncAttributeMaxDynamicSharedMemorySize, SM_TOTAL);
    dim3 grid(N / TILE_M, NJ);
    fkine_mlp_kernel<<<grid, TPB, SM_TOTAL>>>(q, W0, b0, bh, bf, out_t);

    cudaFuncSetAttribute(fkine_chain_kernel,
                         cudaFuncAttributeMaxDynamicSharedMemorySize, CH_SMEM);
    fkine_chain_kernel<<<N / CTPB, CTPB, CH_SMEM>>>(out_t, out_y);
}

// round 17
// speedup vs baseline: 7.5423x; 1.3279x over previous
#include <cuda_runtime.h>
#include <cuda_fp16.h>
#include <cstdint>
#include <math.h>

typedef uint32_t u32;

#define TPB    128
#define NJ     7
#define RSB    272          // bytes per f16 tile row (136 halves)
#define TILE_M 64

// ---- smem: double-buffered A tiles ----
#define SM_A0     0              // 64*272 = 17408
#define SM_A1     17408
#define SM_TOTAL  34816
#define TOPOFF    192            // TOP overlay: SM_A1 + r*RSB + TOPOFF (12 f32)

// ---- fragment-layout weight images in global ----
// hidden layer image (hi only): [kt(8)][ntile(8)][lane(32)] x 16B = 32768 B
// final  layer image (hi+lo)  : [kt(8)][h(2)][lane(32)] x 16B    = 8192 B
#define HIMG    32768
#define FIMG    8192
#define JSTRIDE (2*HIMG + FIMG)
__device__ __align__(16) char g_wbuf[NJ * JSTRIDE];

static __device__ __forceinline__ u32 smem_u32(const void* p) {
    u32 a;
    asm("{ .reg .u64 t; cvta.to.shared.u64 t, %1; cvt.u32.u64 %0, t; }" : "=r"(a) : "l"(p));
    return a;
}
static __device__ __forceinline__ u32 packh(float x0, float x1) {
    u32 r;
    asm("cvt.rn.f16x2.f32 %0, %1, %2;" : "=r"(r) : "f"(x1), "f"(x0));
    return r;
}
static __device__ __forceinline__ uint4 ldmx4(u32 addr) {
    uint4 r;
    asm volatile("ldmatrix.sync.aligned.m8n8.x4.shared.b16 {%0,%1,%2,%3}, [%4];"
                 : "=r"(r.x), "=r"(r.y), "=r"(r.z), "=r"(r.w) : "r"(addr));
    return r;
}
static __device__ __forceinline__ void stmx4(u32 addr, u32 r0, u32 r1, u32 r2, u32 r3) {
    asm volatile("stmatrix.sync.aligned.m8n8.x4.shared.b16 [%0], {%1,%2,%3,%4};"
                 :: "r"(addr), "r"(r0), "r"(r1), "r"(r2), "r"(r3) : "memory");
}
static __device__ __forceinline__ void mma_h(float d[4], const uint4& a, u32 b0, u32 b1) {
    asm volatile("mma.sync.aligned.m16n8k16.row.col.f32.f16.f16.f32 "
                 "{%0,%1,%2,%3},{%4,%5,%6,%7},{%8,%9},{%0,%1,%2,%3};"
                 : "+f"(d[0]), "+f"(d[1]), "+f"(d[2]), "+f"(d[3])
                 : "r"(a.x), "r"(a.y), "r"(a.z), "r"(a.w), "r"(b0), "r"(b1));
}

// ============ weight preconversion ============
// hidden: fp16 hi only, fragment layout; final: fp16 hi + residual lo
__global__ void conv_weights_kernel(const float* __restrict__ Wh,
                                    const float* __restrict__ Wf)
{
    const int stride = gridDim.x * blockDim.x;
    const int t0 = blockIdx.x * blockDim.x + threadIdx.x;

    // hidden layers: 14 x 8192 u32 fragment words (hi only)
    for (int i = t0; i < 14 * 8192; i += stride) {
        int layer = i >> 13;
        int w = i & 8191;
        int e = w & 3, lane = (w >> 2) & 31;
        int nt = (w >> 7) & 7, kt = (w >> 10) & 7;
        int tg = lane >> 2, tl = lane & 3;
        int n = nt * 16 + tg + ((e >> 1) ? 8 : 0);
        int k = kt * 16 + 2 * tl + ((e & 1) ? 8 : 0);
        const float* Wsrc = Wh + (size_t)layer * 16384;
        float v0 = Wsrc[n * 128 + k], v1 = Wsrc[n * 128 + k + 1];
        u32 out = packh(__half2float(__float2half_rn(v0)), __half2float(__float2half_rn(v1)));
        int j = layer >> 1, l = layer & 1;
        u32* img = (u32*)(g_wbuf + (size_t)j * JSTRIDE + l * HIMG);
        img[w] = out;
    }

    // final layers: 7 x 2048 u32 words (hi + lo; rows 12..15 zero)
    for (int i = t0; i < 7 * 2048; i += stride) {
        int j = i >> 11;
        int w = i & 2047;
        int e = w & 3, lane = (w >> 2) & 31, h = (w >> 7) & 1, kt = (w >> 8) & 7;
        int tg = lane >> 2, tl = lane & 3;
        int n = tg + ((e >> 1) ? 8 : 0);
        int k = kt * 16 + 2 * tl + ((e & 1) ? 8 : 0);
        u32 out = 0;
        if (n < 12) {
            const float* Wsrc = Wf + (size_t)j * 1536;
            float v0 = Wsrc[n * 128 + k], v1 = Wsrc[n * 128 + k + 1];
            if (h == 0) {
                out = packh(__half2float(__float2half_rn(v0)), __half2float(__float2half_rn(v1)));
            } else {
                float r0 = v0 - __half2float(__float2half_rn(v0));
                float r1 = v1 - __half2float(__float2half_rn(v1));
                out = packh(r0, r1);
            }
        }
        u32* img = (u32*)(g_wbuf + (size_t)j * JSTRIDE + 2 * HIMG);
        img[w] = out;
    }
}

// ============ MLP kernel (per-joint, fully parallel) ============

// hidden layer: dst <- relu(src @ Whi^T + bias); single fp16 weight term
static __device__ void mma_hidden(u32 smb, u32 src, u32 dst, const char* __restrict__ wimg,
                                  const float* __restrict__ bias, int lane, int wid)
{
    const int n_base = wid * 32;
    const uint4* wf = (const uint4*)wimg;
    float acc[4][4][4];
    #pragma unroll
    for (int mt = 0; mt < 4; ++mt)
        #pragma unroll
        for (int nt = 0; nt < 4; ++nt)
            #pragma unroll
            for (int e = 0; e < 4; ++e) acc[mt][nt][e] = 0.f;

    const int arow = lane & 15, acol = (lane >> 4) << 3;
    const int nt0 = 2 * wid;

    uint4 bcur[2], bnxt[2];
    #pragma unroll
    for (int i = 0; i < 2; ++i)
        bcur[i] = __ldg(&wf[((0 * 8 + nt0 + i) * 32) + lane]);

    #pragma unroll
    for (int kt = 0; kt < 8; ++kt) {
        if (kt < 7) {
            #pragma unroll
            for (int i = 0; i < 2; ++i)
                bnxt[i] = __ldg(&wf[(((kt + 1) * 8 + nt0 + i) * 32) + lane]);
        }
        int k0 = kt * 16;
        uint4 af[4];
        #pragma unroll
        for (int mt = 0; mt < 4; ++mt) {
            u32 a = smb + src + (u32)(mt * 16 + arow) * RSB + (u32)(k0 + acol) * 2;
            af[mt] = ldmx4(a);
        }
        #pragma unroll
        for (int np = 0; np < 2; ++np) {
            uint4 bh = bcur[np];
            #pragma unroll
            for (int mt = 0; mt < 4; ++mt) {
                mma_h(acc[mt][np*2+0], af[mt], bh.x, bh.y);
                mma_h(acc[mt][np*2+1], af[mt], bh.z, bh.w);
            }
        }
        bcur[0] = bnxt[0]; bcur[1] = bnxt[1];
    }

    const int tl = lane & 3;
    float2 bv[4];
    #pragma unroll
    for (int nt = 0; nt < 4; ++nt)
        bv[nt] = __ldg((const float2*)&bias[n_base + nt * 8 + 2 * tl]);

    #pragma unroll
    for (int mt = 0; mt < 4; ++mt) {
        #pragma unroll
        for (int g = 0; g < 2; ++g) {
            int e0 = 2 * g, e1 = 2 * g + 1;
            u32 r0 = packh(fmaxf(acc[mt][e0][0] + bv[e0].x, 0.f),
                           fmaxf(acc[mt][e0][1] + bv[e0].y, 0.f));
            u32 r1 = packh(fmaxf(acc[mt][e0][2] + bv[e0].x, 0.f),
                           fmaxf(acc[mt][e0][3] + bv[e0].y, 0.f));
            u32 r2 = packh(fmaxf(acc[mt][e1][0] + bv[e1].x, 0.f),
                           fmaxf(acc[mt][e1][1] + bv[e1].y, 0.f));
            u32 r3 = packh(fmaxf(acc[mt][e1][2] + bv[e1].x, 0.f),
                           fmaxf(acc[mt][e1][3] + bv[e1].y, 0.f));
            u32 addr = smb + dst + (u32)(mt * 16 + arow) * RSB
                     + (u32)(n_base + g * 16 + acol) * 2;
            stmx4(addr, r0, r1, r2, r3);
        }
    }
}

// final layer (2-term weights): TOP[64][12] = A @ (Wfhi+Wflo)^T -> A1 overlay
static __device__ void mma_final(u32 smb, char* sm, u32 src, const char* __restrict__ fimg,
                                 int lane, int wid)
{
    const int m_base = wid * 16;
    const uint4* wf = (const uint4*)fimg;
    float acc[2][4] = {};
    const int arow = lane & 15, acol = (lane >> 4) << 3;

    uint4 bcur[2], bnxt[2];
    bcur[0] = __ldg(&wf[(0 * 2 + 0) * 32 + lane]);
    bcur[1] = __ldg(&wf[(0 * 2 + 1) * 32 + lane]);

    #pragma unroll
    for (int kt = 0; kt < 8; ++kt) {
        if (kt < 7) {
            bnxt[0] = __ldg(&wf[((kt + 1) * 2 + 0) * 32 + lane]);
            bnxt[1] = __ldg(&wf[((kt + 1) * 2 + 1) * 32 + lane]);
        }
        int k0 = kt * 16;
        u32 a = smb + src + (u32)(m_base + arow) * RSB + (u32)(k0 + acol) * 2;
        uint4 af = ldmx4(a);
        uint4 bh = bcur[0], bl = bcur[1];
        mma_h(acc[0], af, bh.x, bh.y);
        mma_h(acc[0], af, bl.x, bl.y);
        mma_h(acc[1], af, bh.z, bh.w);
        mma_h(acc[1], af, bl.z, bl.w);
        bcur[0] = bnxt[0]; bcur[1] = bnxt[1];
    }
    #pragma unroll
    for (int nt = 0; nt < 2; ++nt) {
        int r = m_base + (lane >> 2);
        int c = nt * 8 + 2 * (lane & 3);
        if (c < 12) {
            *(float2*)(sm + SM_A1 + r * RSB + TOPOFF + c * 4)       = make_float2(acc[nt][0], acc[nt][1]);
            *(float2*)(sm + SM_A1 + (r + 8) * RSB + TOPOFF + c * 4) = make_float2(acc[nt][2], acc[nt][3]);
        }
    }
}

// grid = (N/64, 7); blockIdx.x fastest -> a wave of CTAs shares one joint's weights
__global__ void __launch_bounds__(TPB, 4)
fkine_mlp_kernel(const float* __restrict__ q,
                 const float* __restrict__ W0,
                 const float* __restrict__ b0,
                 const float* __restrict__ bh,
                 const float* __restrict__ bf,
                 float* __restrict__ out_t)
{
    extern __shared__ char sm[];
    const u32 smb = smem_u32(sm);
    const int tid = threadIdx.x, lane = tid & 31, wid = tid >> 5;
    const int g0 = blockIdx.x * TILE_M;
    const int j  = blockIdx.y;
    const char* gj = g_wbuf + (size_t)j * JSTRIDE;

    // ---- layer 0 (K=3): lane = sample, uniform weight loads, STS.128 out
    {
        int m = (wid & 1) * 32 + lane;
        float th = q[(size_t)(g0 + m) * NJ + j];
        float ct = cosf(th), st = sinf(th);
        const float* w0  = W0 + (size_t)j * 384;
        const float* b0j = b0 + (size_t)j * 128;
        int ob = (wid >> 1) * 64;
        for (int o8 = ob; o8 < ob + 64; o8 += 8) {
            float4 bA = __ldg((const float4*)&b0j[o8]);
            float4 bB = __ldg((const float4*)&b0j[o8 + 4]);
            float bb[8] = {bA.x, bA.y, bA.z, bA.w, bB.x, bB.y, bB.z, bB.w};
            u32 pk[4];
            #pragma unroll
            for (int p = 0; p < 4; ++p) {
                int o = o8 + 2 * p;
                float2 f0 = __ldg((const float2*)&w0[o * 3]);
                float2 f1 = __ldg((const float2*)&w0[o * 3 + 2]);
                float2 f2 = __ldg((const float2*)&w0[o * 3 + 4]);
                float h0 = fmaxf(fmaf(f0.x, th, fmaf(f0.y, ct, fmaf(f1.x, st, bb[2*p]))),   0.f);
                float h1 = fmaxf(fmaf(f1.y, th, fmaf(f2.x, ct, fmaf(f2.y, st, bb[2*p+1]))), 0.f);
                pk[p] = packh(h0, h1);
            }
            *(uint4*)(sm + SM_A0 + m * RSB + o8 * 2) = make_uint4(pk[0], pk[1], pk[2], pk[3]);
        }
    }
    __syncthreads();

    // ---- hidden layer 1: A0 -> A1
    mma_hidden(smb, SM_A0, SM_A1, gj, bh + (size_t)(j * 2) * 128, lane, wid);
    __syncthreads();

    // ---- hidden layer 2: A1 -> A0
    mma_hidden(smb, SM_A1, SM_A0, gj + HIMG, bh + (size_t)(j * 2 + 1) * 128, lane, wid);
    __syncthreads();

    // ---- final layer: A0 -> TOP (A1 overlay)
    mma_final(smb, sm, SM_A0, gj + 2 * HIMG, lane, wid);
    __syncthreads();

    // ---- write local transform t[m][j] (with bias + bottom row)
    if (tid < TILE_M) {
        int m = tid;
        float Tl[12];
        #pragma unroll
        for (int i = 0; i < 12; ++i)
            Tl[i] = *(float*)(sm + SM_A1 + m * RSB + TOPOFF + i * 4) + __ldg(&bf[j * 12 + i]);
        float4* tp = (float4*)(out_t + (size_t)(g0 + m) * 112 + j * 16);
        tp[0] = make_float4(Tl[0], Tl[1], Tl[2],  Tl[3]);
        tp[1] = make_float4(Tl[4], Tl[5], Tl[6],  Tl[7]);
        tp[2] = make_float4(Tl[8], Tl[9], Tl[10], Tl[11]);
        tp[3] = make_float4(0.f, 0.f, 0.f, 1.f);
    }
}

// ============ chain kernel: smem-staged coalesced t reads -> cumulative products -> y ============
#define CTPB 128
#define CH_TS   (CTPB * 112)
#define CH_SMEM ((CH_TS + CTPB * 21) * 4)
__global__ void __launch_bounds__(CTPB)
fkine_chain_kernel(const float* __restrict__ t, float* __restrict__ out_y)
{
    extern __shared__ float chs[];
    float* tsm = chs;
    float* ysm = chs + CH_TS;
    const int tid = threadIdx.x;
    const size_t m0 = (size_t)blockIdx.x * CTPB;

    const float4* src = (const float4*)(t + m0 * 112);
    float4* dst = (float4*)tsm;
    #pragma unroll 4
    for (int i = tid; i < CTPB * 28; i += CTPB) dst[i] = src[i];
    __syncthreads();

    float Tc[16];
    #pragma unroll
    for (int e = 0; e < 16; ++e) Tc[e] = ((e >> 2) == (e & 3)) ? 1.f : 0.f;

    const float* tp = tsm + tid * 112;
    #pragma unroll
    for (int j = 0; j < NJ; ++j) {
        float Tl[12];
        #pragma unroll
        for (int i = 0; i < 12; ++i) Tl[i] = tp[j * 16 + i];
        float Tn[16];
        #pragma unroll
        for (int i = 0; i < 3; ++i)
            #pragma unroll
            for (int c = 0; c < 4; ++c)
                Tn[i*4+c] = Tl[i*4+0]*Tc[0+c] + Tl[i*4+1]*Tc[4+c]
                          + Tl[i*4+2]*Tc[8+c] + Tl[i*4+3]*Tc[12+c];
        #pragma unroll
        for (int c = 0; c < 4; ++c) Tn[12+c] = Tc[12+c];

        ysm[tid * 21 + j]      = Tn[3];
        ysm[tid * 21 + 7 + j]  = Tn[7];
        ysm[tid * 21 + 14 + j] = Tn[11];

        #pragma unroll
        for (int i = 0; i < 16; ++i) Tc[i] = Tn[i];
    }
    __syncthreads();
    for (int idx = tid; idx < CTPB * 21; idx += CTPB)
        out_y[m0 * 21 + idx] = ysm[idx];
}

extern "C" void kernel_launch(void* const* d_in, const int* in_sizes, int n_in,
                              void* d_out, int out_size)
{
    const float* q  = (const float*)d_in[0];
    const float* W0 = (const float*)d_in[1];
    const float* b0 = (const float*)d_in[2];
    const float* Wh = (const float*)d_in[3];
    const float* bh = (const float*)d_in[4];
    const float* Wf = (const float*)d_in[5];
    const float* bf = (const float*)d_in[6];

    const int N = in_sizes[0] / NJ;           // q is [N, 7]
    float* out_y = (float*)d_out;             // [N, 3, 7]
    float* out_t = out_y + (size_t)N * 21;    // [N, 7, 4, 4]

    conv_weights_kernel<<<1024, 256>>>(Wh, Wf);

    cudaFuncSetAttribute(fkine_mlp_kernel,
                         cudaFuncAttributeMaxDynamicSharedMemorySize, SM_TOTAL);
    dim3 grid(N / TILE_M, NJ);
    fkine_mlp_kernel<<<grid, TPB, SM_TOTAL>>>(q, W0, b0, bh, bf, out_t);

    cudaFuncSetAttribute(fkine_chain_kernel,
                         cudaFuncAttributeMaxDynamicSharedMemorySize, CH_SMEM);
    fkine_chain_kernel<<<N / CTPB, CTPB, CH_SMEM>>>(out_t, out_y);
}